// round 1
// baseline (speedup 1.0000x reference)
#include <cuda_runtime.h>
#include <cuda_bf16.h>
#include <math.h>

// Problem constants
constexpr int B  = 4;
constexpr int S  = 2048;
constexpr int D  = 2048;
constexpr int H  = 16;
constexpr int DH = 128;
constexpr int M  = B * S;          // 8192 rows

// Scratch buffers (allocation-free rule: device globals)
__device__ float g_q[(size_t)M * D];
__device__ float g_k[(size_t)M * D];
__device__ float g_v[(size_t)M * D];
__device__ float g_ctx[(size_t)M * D];

// ---------------------------------------------------------------------------
// Dense GEMM: C[M][N] = A[M][K] @ W[K][N] + bias[N]
// 128x128 CTA tile, BK=16, 256 threads, 8x8 per-thread micro-tile.
// ---------------------------------------------------------------------------
constexpr int BM = 128, BN = 128, BK = 16;

__device__ __forceinline__ void gemm_body(const float* __restrict__ A,
                                          const float* __restrict__ W,
                                          const float* __restrict__ bias,
                                          float* __restrict__ C,
                                          int Mm, int Nn, int Kk)
{
    __shared__ float As[BK][BM + 4];   // transposed A tile, padded
    __shared__ float Ws[BK][BN];

    const int t  = threadIdx.x;
    const int tx = t & 15;
    const int ty = t >> 4;
    const int m0 = blockIdx.y * BM;
    const int n0 = blockIdx.x * BN;

    const int arow = t >> 1;           // 0..127
    const int acol = (t & 1) * 8;      // 0 or 8
    const int wrow = t >> 4;           // 0..15
    const int wcol = (t & 15) * 8;     // 0..120

    float acc[8][8];
    #pragma unroll
    for (int i = 0; i < 8; i++)
        #pragma unroll
        for (int j = 0; j < 8; j++) acc[i][j] = 0.f;

    const float* Abase = A + (size_t)(m0 + arow) * Kk;

    for (int k0 = 0; k0 < Kk; k0 += BK) {
        // Load A tile (128 x 16) transposed into As
        float4 a0 = *(const float4*)(Abase + k0 + acol);
        float4 a1 = *(const float4*)(Abase + k0 + acol + 4);
        As[acol + 0][arow] = a0.x; As[acol + 1][arow] = a0.y;
        As[acol + 2][arow] = a0.z; As[acol + 3][arow] = a0.w;
        As[acol + 4][arow] = a1.x; As[acol + 5][arow] = a1.y;
        As[acol + 6][arow] = a1.z; As[acol + 7][arow] = a1.w;
        // Load W tile (16 x 128)
        const float* Wr = W + (size_t)(k0 + wrow) * Nn + n0 + wcol;
        float4 w0 = *(const float4*)(Wr);
        float4 w1 = *(const float4*)(Wr + 4);
        *(float4*)&Ws[wrow][wcol]     = w0;
        *(float4*)&Ws[wrow][wcol + 4] = w1;
        __syncthreads();

        #pragma unroll
        for (int k = 0; k < BK; k++) {
            float a[8], b[8];
            *(float4*)&a[0] = *(float4*)&As[k][ty * 8];
            *(float4*)&a[4] = *(float4*)&As[k][ty * 8 + 4];
            *(float4*)&b[0] = *(float4*)&Ws[k][tx * 8];
            *(float4*)&b[4] = *(float4*)&Ws[k][tx * 8 + 4];
            #pragma unroll
            for (int i = 0; i < 8; i++)
                #pragma unroll
                for (int j = 0; j < 8; j++)
                    acc[i][j] += a[i] * b[j];
        }
        __syncthreads();
    }

    // Epilogue: bias + store
    const int n = n0 + tx * 8;
    float4 b0 = *(const float4*)(bias + n);
    float4 b1 = *(const float4*)(bias + n + 4);
    #pragma unroll
    for (int i = 0; i < 8; i++) {
        int m = m0 + ty * 8 + i;
        float4 o0, o1;
        o0.x = acc[i][0] + b0.x; o0.y = acc[i][1] + b0.y;
        o0.z = acc[i][2] + b0.z; o0.w = acc[i][3] + b0.w;
        o1.x = acc[i][4] + b1.x; o1.y = acc[i][5] + b1.y;
        o1.z = acc[i][6] + b1.z; o1.w = acc[i][7] + b1.w;
        *(float4*)(C + (size_t)m * Nn + n)     = o0;
        *(float4*)(C + (size_t)m * Nn + n + 4) = o1;
    }
}

__global__ __launch_bounds__(256)
void qkv_gemm_kernel(const float* __restrict__ X,
                     const float* __restrict__ Wq, const float* __restrict__ bq,
                     const float* __restrict__ Wk, const float* __restrict__ bk,
                     const float* __restrict__ Wv, const float* __restrict__ bv)
{
    int z = blockIdx.z;
    const float* W = (z == 0) ? Wq : (z == 1) ? Wk : Wv;
    const float* b = (z == 0) ? bq : (z == 1) ? bk : bv;
    float*       C = (z == 0) ? g_q : (z == 1) ? g_k : g_v;
    gemm_body(X, W, b, C, M, D, D);
}

__global__ __launch_bounds__(256)
void out_gemm_kernel(const float* __restrict__ Wo, const float* __restrict__ bo,
                     float* __restrict__ out)
{
    gemm_body(g_ctx, Wo, bo, out, M, D, D);
}

// ---------------------------------------------------------------------------
// Flash attention (fp32, causal). Br=Bc=64, 256 threads, online softmax.
// grid: (S/64, B*H)
// ---------------------------------------------------------------------------
constexpr int BR = 64, BC = 64;
constexpr int QKV_STRIDE = DH + 4;             // 132, float4-aligned pad
constexpr int SS_STRIDE  = BC + 1;             // 65
constexpr int ATTN_SMEM_FLOATS =
    3 * BR * QKV_STRIDE + BR * SS_STRIDE + 3 * BR;
constexpr int ATTN_SMEM_BYTES = ATTN_SMEM_FLOATS * 4;   // 118,784 B

__device__ __forceinline__ void load_tile64(const float* __restrict__ g,
                                            float* __restrict__ smem, float mul)
{
    const int t = threadIdx.x;
    const int r  = t >> 2;           // 0..63
    const int c4 = t & 3;
    #pragma unroll
    for (int it = 0; it < 8; it++) {
        int chunk = it * 4 + c4;     // 0..31
        float4 v = *(const float4*)(g + (size_t)r * D + chunk * 4);
        v.x *= mul; v.y *= mul; v.z *= mul; v.w *= mul;
        *(float4*)&smem[r * QKV_STRIDE + chunk * 4] = v;
    }
}

__global__ __launch_bounds__(256)
void attn_kernel()
{
    extern __shared__ float sm[];
    float* Qs  = sm;                               // [64][132]
    float* Ks  = Qs + BR * QKV_STRIDE;
    float* Vs  = Ks + BC * QKV_STRIDE;
    float* Ss  = Vs + BC * QKV_STRIDE;             // [64][65]
    float* m_s = Ss + BR * SS_STRIDE;              // [64]
    float* l_s = m_s + BR;
    float* sc_s = l_s + BR;

    const int t  = threadIdx.x;
    const int tx = t & 15;
    const int ty = t >> 4;
    const int iq = blockIdx.x;           // query block
    const int bh = blockIdx.y;
    const int b  = bh >> 4;
    const int h  = bh & 15;
    const int q0 = iq * BR;

    const float qscale = 0.0883883476483184f;   // 1/sqrt(128)

    const float* Qg = g_q + ((size_t)(b * S + q0)) * D + h * DH;
    load_tile64(Qg, Qs, qscale);
    if (t < BR) { m_s[t] = -1e30f; l_s[t] = 0.f; }

    float o_acc[4][8];
    #pragma unroll
    for (int i = 0; i < 4; i++)
        #pragma unroll
        for (int j = 0; j < 8; j++) o_acc[i][j] = 0.f;

    for (int jb = 0; jb <= iq; jb++) {
        __syncthreads();   // prev PV done (and Q load on first iter)
        const int k0 = jb * BC;
        const float* Kg = g_k + ((size_t)(b * S + k0)) * D + h * DH;
        const float* Vg = g_v + ((size_t)(b * S + k0)) * D + h * DH;
        load_tile64(Kg, Ks, 1.f);
        load_tile64(Vg, Vs, 1.f);
        __syncthreads();

        // S = Q K^T  (scale pre-folded into Q)
        float sacc[4][4];
        #pragma unroll
        for (int i = 0; i < 4; i++)
            #pragma unroll
            for (int j = 0; j < 4; j++) sacc[i][j] = 0.f;

        #pragma unroll 4
        for (int k = 0; k < DH; k += 4) {
            float4 qa[4], kb[4];
            #pragma unroll
            for (int i = 0; i < 4; i++)
                qa[i] = *(float4*)&Qs[(ty * 4 + i) * QKV_STRIDE + k];
            #pragma unroll
            for (int j = 0; j < 4; j++)
                kb[j] = *(float4*)&Ks[(tx * 4 + j) * QKV_STRIDE + k];
            #pragma unroll
            for (int i = 0; i < 4; i++)
                #pragma unroll
                for (int j = 0; j < 4; j++)
                    sacc[i][j] += qa[i].x * kb[j].x + qa[i].y * kb[j].y +
                                  qa[i].z * kb[j].z + qa[i].w * kb[j].w;
        }
        const bool diag = (jb == iq);
        #pragma unroll
        for (int i = 0; i < 4; i++) {
            int rr = ty * 4 + i;
            #pragma unroll
            for (int j = 0; j < 4; j++) {
                int cc = tx * 4 + j;
                float v = sacc[i][j];
                if (diag && cc > rr) v = -1e30f;
                Ss[rr * SS_STRIDE + cc] = v;
            }
        }
        __syncthreads();

        // Online softmax stats: 4 threads per row
        {
            const int r = t >> 2;
            const int q = t & 3;
            float mloc = -1e30f;
            #pragma unroll
            for (int kk = 0; kk < 16; kk++)
                mloc = fmaxf(mloc, Ss[r * SS_STRIDE + q * 16 + kk]);
            mloc = fmaxf(mloc, __shfl_xor_sync(0xffffffffu, mloc, 1));
            mloc = fmaxf(mloc, __shfl_xor_sync(0xffffffffu, mloc, 2));
            float mold = m_s[r];
            float mnew = fmaxf(mold, mloc);
            float ssum = 0.f;
            #pragma unroll
            for (int kk = 0; kk < 16; kk++) {
                float p = __expf(Ss[r * SS_STRIDE + q * 16 + kk] - mnew);
                Ss[r * SS_STRIDE + q * 16 + kk] = p;
                ssum += p;
            }
            ssum += __shfl_xor_sync(0xffffffffu, ssum, 1);
            ssum += __shfl_xor_sync(0xffffffffu, ssum, 2);
            if (q == 0) {
                float sc = __expf(mold - mnew);
                m_s[r]  = mnew;
                l_s[r]  = l_s[r] * sc + ssum;
                sc_s[r] = sc;
            }
        }
        __syncthreads();

        // O = O*scale + P V   (thread tile: 4 rows x 8 cols)
        #pragma unroll
        for (int i = 0; i < 4; i++) {
            float sc = sc_s[ty * 4 + i];
            #pragma unroll
            for (int j = 0; j < 8; j++) o_acc[i][j] *= sc;
        }
        #pragma unroll 2
        for (int k = 0; k < BC; k++) {
            float a[4];
            #pragma unroll
            for (int i = 0; i < 4; i++)
                a[i] = Ss[(ty * 4 + i) * SS_STRIDE + k];
            float4 v0 = *(float4*)&Vs[k * QKV_STRIDE + tx * 8];
            float4 v1 = *(float4*)&Vs[k * QKV_STRIDE + tx * 8 + 4];
            #pragma unroll
            for (int i = 0; i < 4; i++) {
                o_acc[i][0] += a[i] * v0.x; o_acc[i][1] += a[i] * v0.y;
                o_acc[i][2] += a[i] * v0.z; o_acc[i][3] += a[i] * v0.w;
                o_acc[i][4] += a[i] * v1.x; o_acc[i][5] += a[i] * v1.y;
                o_acc[i][6] += a[i] * v1.z; o_acc[i][7] += a[i] * v1.w;
            }
        }
    }

    // Finalize: divide by l, write ctx in [B, S, H*DH] layout
    #pragma unroll
    for (int i = 0; i < 4; i++) {
        int r = ty * 4 + i;
        float inv = 1.f / l_s[r];
        float4 o0, o1;
        o0.x = o_acc[i][0] * inv; o0.y = o_acc[i][1] * inv;
        o0.z = o_acc[i][2] * inv; o0.w = o_acc[i][3] * inv;
        o1.x = o_acc[i][4] * inv; o1.y = o_acc[i][5] * inv;
        o1.z = o_acc[i][6] * inv; o1.w = o_acc[i][7] * inv;
        float* dst = g_ctx + ((size_t)(b * S + q0 + r)) * D + h * DH + tx * 8;
        *(float4*)(dst)     = o0;
        *(float4*)(dst + 4) = o1;
    }
}

// ---------------------------------------------------------------------------
extern "C" void kernel_launch(void* const* d_in, const int* in_sizes, int n_in,
                              void* d_out, int out_size)
{
    const float* X  = (const float*)d_in[0];
    const float* Wq = (const float*)d_in[1];
    const float* bq = (const float*)d_in[2];
    const float* Wk = (const float*)d_in[3];
    const float* bk = (const float*)d_in[4];
    const float* Wv = (const float*)d_in[5];
    const float* bv = (const float*)d_in[6];
    const float* Wo = (const float*)d_in[7];
    const float* bo = (const float*)d_in[8];
    float* out = (float*)d_out;

    cudaFuncSetAttribute(attn_kernel,
                         cudaFuncAttributeMaxDynamicSharedMemorySize,
                         ATTN_SMEM_BYTES);

    dim3 gemm_grid(D / BN, M / BM, 3);
    qkv_gemm_kernel<<<gemm_grid, 256>>>(X, Wq, bq, Wk, bk, Wv, bv);

    dim3 attn_grid(S / BR, B * H);
    attn_kernel<<<attn_grid, 256, ATTN_SMEM_BYTES>>>();

    dim3 out_grid(D / BN, M / BM);
    out_gemm_kernel<<<out_grid, 256>>>(Wo, bo, out);
}

// round 3
// speedup vs baseline: 1.6031x; 1.6031x over previous
#include <cuda_runtime.h>
#include <cuda_bf16.h>
#include <math.h>
#include <cstdint>

// Problem constants
constexpr int B  = 4;
constexpr int S  = 2048;
constexpr int D  = 2048;
constexpr int H  = 16;
constexpr int DH = 128;
constexpr int M  = B * S;          // 8192 rows

// ---------------------------------------------------------------------------
// Scratch (allocation-free rule: device globals)
// ---------------------------------------------------------------------------
__device__ float g_q[(size_t)M * D];
__device__ float g_k[(size_t)M * D];
__device__ float g_v[(size_t)M * D];
__device__ float g_ctx[(size_t)M * D];
__device__ __nv_bfloat16 g_x_h[(size_t)M * D];
__device__ __nv_bfloat16 g_x_l[(size_t)M * D];
__device__ __nv_bfloat16 g_c_h[(size_t)M * D];
__device__ __nv_bfloat16 g_c_l[(size_t)M * D];
__device__ __nv_bfloat16 g_wT_h[(size_t)4 * D * D];   // [w][N][K] transposed weights
__device__ __nv_bfloat16 g_wT_l[(size_t)4 * D * D];

// ---------------------------------------------------------------------------
// PTX helpers (sm_103 baseline: mma.sync + ldmatrix + cp.async only)
// ---------------------------------------------------------------------------
__device__ __forceinline__ uint32_t smem_u32(const void* p) {
    uint32_t a;
    asm("{ .reg .u64 t; cvta.to.shared.u64 t, %1; cvt.u32.u64 %0, t; }" : "=r"(a) : "l"(p));
    return a;
}

__device__ __forceinline__ void cp_async16(uint32_t dst, const void* src) {
    asm volatile("cp.async.cg.shared.global [%0], [%1], 16;" :: "r"(dst), "l"(src));
}
#define CP_COMMIT() asm volatile("cp.async.commit_group;" ::: "memory")
#define CP_WAIT0()  asm volatile("cp.async.wait_group 0;" ::: "memory")
#define CP_WAIT1()  asm volatile("cp.async.wait_group 1;" ::: "memory")

__device__ __forceinline__ void ldsm_x4(uint32_t* r, uint32_t addr) {
    asm volatile("ldmatrix.sync.aligned.m8n8.x4.shared.b16 {%0,%1,%2,%3}, [%4];"
        : "=r"(r[0]), "=r"(r[1]), "=r"(r[2]), "=r"(r[3]) : "r"(addr));
}

__device__ __forceinline__ void mma16816(float* c, const uint32_t* a, const uint32_t* b) {
    asm volatile("mma.sync.aligned.m16n8k16.row.col.f32.bf16.bf16.f32 "
        "{%0,%1,%2,%3}, {%4,%5,%6,%7}, {%8,%9}, {%0,%1,%2,%3};"
        : "+f"(c[0]), "+f"(c[1]), "+f"(c[2]), "+f"(c[3])
        : "r"(a[0]), "r"(a[1]), "r"(a[2]), "r"(a[3]), "r"(b[0]), "r"(b[1]));
}

// ---------------------------------------------------------------------------
// Split / transpose conversion kernels
// ---------------------------------------------------------------------------
__device__ __forceinline__ void split_store4(float4 v, __nv_bfloat16* hi, __nv_bfloat16* lo, size_t i) {
    __nv_bfloat16 h[4], l[4];
    float f[4] = {v.x, v.y, v.z, v.w};
    #pragma unroll
    for (int j = 0; j < 4; j++) {
        h[j] = __float2bfloat16(f[j]);
        l[j] = __float2bfloat16(f[j] - __bfloat162float(h[j]));
    }
    *(uint2*)(hi + i) = *(const uint2*)h;
    *(uint2*)(lo + i) = *(const uint2*)l;
}

__global__ __launch_bounds__(256) void split_x_kernel(const float4* __restrict__ in) {
    size_t i = (size_t)blockIdx.x * blockDim.x + threadIdx.x;
    split_store4(in[i], g_x_h, g_x_l, i * 4);
}

__global__ __launch_bounds__(256) void split_ctx_kernel() {
    size_t i = (size_t)blockIdx.x * blockDim.x + threadIdx.x;
    split_store4(((const float4*)g_ctx)[i], g_c_h, g_c_l, i * 4);
}

// Weights: W [K][N] fp32 -> transposed split bf16 [N][K]
__global__ __launch_bounds__(256) void wsplit_kernel(const float* __restrict__ Wq,
                                                     const float* __restrict__ Wk,
                                                     const float* __restrict__ Wv,
                                                     const float* __restrict__ Wo) {
    __shared__ float tile[32][33];
    int z = blockIdx.z;
    const float* W = (z == 0) ? Wq : (z == 1) ? Wk : (z == 2) ? Wv : Wo;
    __nv_bfloat16* oh = g_wT_h + (size_t)z * D * D;
    __nv_bfloat16* ol = g_wT_l + (size_t)z * D * D;
    int n0 = blockIdx.x * 32, k0 = blockIdx.y * 32;
    int tx = threadIdx.x & 31, ty = threadIdx.x >> 5;     // 32 x 8
    #pragma unroll
    for (int i = 0; i < 4; i++) {
        int k = ty + i * 8;
        tile[k][tx] = W[(size_t)(k0 + k) * D + n0 + tx];
    }
    __syncthreads();
    #pragma unroll
    for (int i = 0; i < 4; i++) {
        int n = ty + i * 8;
        float v = tile[tx][n];
        __nv_bfloat16 h = __float2bfloat16(v);
        __nv_bfloat16 l = __float2bfloat16(v - __bfloat162float(h));
        oh[(size_t)(n0 + n) * D + k0 + tx] = h;
        ol[(size_t)(n0 + n) * D + k0 + tx] = l;
    }
}

// ---------------------------------------------------------------------------
// mma.sync split-bf16 GEMM: C[128x128 tile] = A(hi+lo) @ B(hi+lo)^T + bias
// A: [M,K] bf16 row-major (K contiguous). B: [N,K] bf16 (K contiguous) = col operand.
// 3 passes: Ah*Bh + Ah*Bl + Al*Bh, fp32 accumulators in registers.
// 8 warps in 2x4 grid, warp tile 64x32, BK=32, double-buffered cp.async.
// ---------------------------------------------------------------------------
constexpr int BKG      = 32;
constexpr int LDT      = 40;                  // bf16 stride per tile row (32 data + 8 pad)
constexpr int TILE_BY  = 128 * LDT * 2;       // 10240 B per tile
constexpr int STAGE_BY = 4 * TILE_BY;         // Ah, Al, Bh, Bl = 40960 B
constexpr int GEMM_SMEM = 2 * STAGE_BY;       // 81920 B
constexpr int NITER    = D / BKG;             // 64

__device__ __forceinline__ void load_stage(uint32_t sbase,
                                           const __nv_bfloat16* Ah,
                                           const __nv_bfloat16* Al,
                                           const __nv_bfloat16* Bh,
                                           const __nv_bfloat16* Bl,
                                           int k0, int t) {
    const __nv_bfloat16* bases[4] = {Ah, Al, Bh, Bl};
    #pragma unroll
    for (int i = 0; i < 8; i++) {
        const int tile = i >> 1;                 // compile-time per unrolled i
        int rem  = t + 256 * (i & 1);            // 0..511
        int row  = rem >> 2;                     // 0..127
        int chnk = rem & 3;                      // 16B chunk (8 bf16)
        const __nv_bfloat16* src = bases[tile] + (size_t)row * D + k0 + chnk * 8;
        uint32_t dst = sbase + tile * TILE_BY + row * (LDT * 2) + chnk * 16;
        cp_async16(dst, src);
    }
    CP_COMMIT();
}

__device__ __forceinline__ void tc_gemm_body(const __nv_bfloat16* __restrict__ Ahp,
                                             const __nv_bfloat16* __restrict__ Alp,
                                             const __nv_bfloat16* __restrict__ Bhp,
                                             const __nv_bfloat16* __restrict__ Blp,
                                             const float* __restrict__ bias,
                                             float* __restrict__ C) {
    extern __shared__ char smem[];
    const uint32_t sb = smem_u32(smem);
    const int t    = threadIdx.x;
    const int lane = t & 31;
    const int w    = t >> 5;
    const int wm   = (w & 1) * 64;
    const int wn   = (w >> 1) * 32;
    const int m0   = blockIdx.y * 128;
    const int n0   = blockIdx.x * 128;

    const __nv_bfloat16* Arow  = Ahp + (size_t)m0 * D;
    const __nv_bfloat16* AlRow = Alp + (size_t)m0 * D;
    const __nv_bfloat16* Brow  = Bhp + (size_t)n0 * D;
    const __nv_bfloat16* BlRow = Blp + (size_t)n0 * D;

    float acc[4][4][4];
    #pragma unroll
    for (int i = 0; i < 4; i++)
        #pragma unroll
        for (int j = 0; j < 4; j++)
            #pragma unroll
            for (int r = 0; r < 4; r++) acc[i][j][r] = 0.f;

    // lane-derived ldmatrix offsets
    const int arow  = lane & 15;                 // A row within 16-row frag
    const int akoff = (lane >> 4) * 16;          // bytes: k+8 half
    const int bn    = (lane & 7) + ((lane >> 4) << 3);   // B n-row
    const int bkoff = ((lane >> 3) & 1) * 16;    // bytes: k+8 half

    load_stage(sb, Arow, AlRow, Brow, BlRow, 0, t);

    for (int c = 0; c < NITER; c++) {
        if (c + 1 < NITER) {
            load_stage(sb + ((c + 1) & 1) * STAGE_BY, Arow, AlRow, Brow, BlRow,
                       (c + 1) * BKG, t);
            CP_WAIT1();
        } else {
            CP_WAIT0();
        }
        __syncthreads();

        const uint32_t sbase = sb + (c & 1) * STAGE_BY;
        #pragma unroll
        for (int kk = 0; kk < 2; kk++) {         // two k16 steps
            const uint32_t kbyte = kk * 32;      // 16 bf16 = 32 B
            uint32_t ah[4][4], al[4][4];
            #pragma unroll
            for (int mf = 0; mf < 4; mf++) {
                uint32_t ad = sbase + (wm + mf * 16 + arow) * (LDT * 2) + kbyte + akoff;
                ldsm_x4(ah[mf], ad);
                ldsm_x4(al[mf], ad + TILE_BY);
            }
            uint32_t bh[8], bl[8];
            #pragma unroll
            for (int bp = 0; bp < 2; bp++) {     // 16 n-rows per x4
                uint32_t bd = sbase + 2 * TILE_BY + (wn + bp * 16 + bn) * (LDT * 2) + kbyte + bkoff;
                ldsm_x4(&bh[bp * 4], bd);
                ldsm_x4(&bl[bp * 4], bd + TILE_BY);
            }
            #pragma unroll
            for (int mf = 0; mf < 4; mf++)
                #pragma unroll
                for (int nf = 0; nf < 4; nf++) {
                    const uint32_t* bhp = &bh[(nf >> 1) * 4 + (nf & 1) * 2];
                    const uint32_t* blp = &bl[(nf >> 1) * 4 + (nf & 1) * 2];
                    mma16816(acc[mf][nf], ah[mf], bhp);
                    mma16816(acc[mf][nf], ah[mf], blp);
                    mma16816(acc[mf][nf], al[mf], bhp);
                }
        }
        __syncthreads();
    }

    // Epilogue: bias + fp32 store
    const int rbase = m0 + wm + (lane >> 2);
    const int cbase = n0 + wn + (lane & 3) * 2;
    #pragma unroll
    for (int mf = 0; mf < 4; mf++) {
        #pragma unroll
        for (int nf = 0; nf < 4; nf++) {
            int col = cbase + nf * 8;
            float2 bv = *(const float2*)(bias + col);
            int r0 = rbase + mf * 16;
            float2 o0, o1;
            o0.x = acc[mf][nf][0] + bv.x; o0.y = acc[mf][nf][1] + bv.y;
            o1.x = acc[mf][nf][2] + bv.x; o1.y = acc[mf][nf][3] + bv.y;
            *(float2*)(C + (size_t)r0 * D + col)       = o0;
            *(float2*)(C + (size_t)(r0 + 8) * D + col) = o1;
        }
    }
}

__global__ __launch_bounds__(256) void qkv_tc_gemm(const float* __restrict__ bq,
                                                   const float* __restrict__ bk,
                                                   const float* __restrict__ bv) {
    const int z = blockIdx.z;
    const __nv_bfloat16* Bh = g_wT_h + (size_t)z * D * D;
    const __nv_bfloat16* Bl = g_wT_l + (size_t)z * D * D;
    const float* bias = (z == 0) ? bq : (z == 1) ? bk : bv;
    float* C = (z == 0) ? g_q : (z == 1) ? g_k : g_v;
    tc_gemm_body(g_x_h, g_x_l, Bh, Bl, bias, C);
}

__global__ __launch_bounds__(256) void out_tc_gemm(const float* __restrict__ bo,
                                                   float* __restrict__ out) {
    tc_gemm_body(g_c_h, g_c_l, g_wT_h + (size_t)3 * D * D, g_wT_l + (size_t)3 * D * D, bo, out);
}

// ---------------------------------------------------------------------------
// Flash attention (fp32, causal). Br=Bc=64, 256 threads, online softmax.
// ---------------------------------------------------------------------------
constexpr int BR = 64, BC = 64;
constexpr int QKV_STRIDE = DH + 4;
constexpr int SS_STRIDE  = BC + 1;
constexpr int ATTN_SMEM_FLOATS = 3 * BR * QKV_STRIDE + BR * SS_STRIDE + 3 * BR;
constexpr int ATTN_SMEM_BYTES  = ATTN_SMEM_FLOATS * 4;

__device__ __forceinline__ void load_tile64(const float* __restrict__ g,
                                            float* __restrict__ smemp, float mul) {
    const int t  = threadIdx.x;
    const int r  = t >> 2;
    const int c4 = t & 3;
    #pragma unroll
    for (int it = 0; it < 8; it++) {
        int chunk = it * 4 + c4;
        float4 v = *(const float4*)(g + (size_t)r * D + chunk * 4);
        v.x *= mul; v.y *= mul; v.z *= mul; v.w *= mul;
        *(float4*)&smemp[r * QKV_STRIDE + chunk * 4] = v;
    }
}

__global__ __launch_bounds__(256) void attn_kernel() {
    extern __shared__ float sm[];
    float* Qs   = sm;
    float* Ks   = Qs + BR * QKV_STRIDE;
    float* Vs   = Ks + BC * QKV_STRIDE;
    float* Ss   = Vs + BC * QKV_STRIDE;
    float* m_s  = Ss + BR * SS_STRIDE;
    float* l_s  = m_s + BR;
    float* sc_s = l_s + BR;

    const int t  = threadIdx.x;
    const int tx = t & 15;
    const int ty = t >> 4;
    const int iq = blockIdx.x;
    const int bh = blockIdx.y;
    const int b  = bh >> 4;
    const int h  = bh & 15;
    const int q0 = iq * BR;

    const float qscale = 0.0883883476483184f;   // 1/sqrt(128)

    const float* Qg = g_q + ((size_t)(b * S + q0)) * D + h * DH;
    load_tile64(Qg, Qs, qscale);
    if (t < BR) { m_s[t] = -1e30f; l_s[t] = 0.f; }

    float o_acc[4][8];
    #pragma unroll
    for (int i = 0; i < 4; i++)
        #pragma unroll
        for (int j = 0; j < 8; j++) o_acc[i][j] = 0.f;

    for (int jb = 0; jb <= iq; jb++) {
        __syncthreads();
        const int k0 = jb * BC;
        const float* Kg = g_k + ((size_t)(b * S + k0)) * D + h * DH;
        const float* Vg = g_v + ((size_t)(b * S + k0)) * D + h * DH;
        load_tile64(Kg, Ks, 1.f);
        load_tile64(Vg, Vs, 1.f);
        __syncthreads();

        float sacc[4][4];
        #pragma unroll
        for (int i = 0; i < 4; i++)
            #pragma unroll
            for (int j = 0; j < 4; j++) sacc[i][j] = 0.f;

        #pragma unroll 4
        for (int k = 0; k < DH; k += 4) {
            float4 qa[4], kb[4];
            #pragma unroll
            for (int i = 0; i < 4; i++)
                qa[i] = *(float4*)&Qs[(ty * 4 + i) * QKV_STRIDE + k];
            #pragma unroll
            for (int j = 0; j < 4; j++)
                kb[j] = *(float4*)&Ks[(tx * 4 + j) * QKV_STRIDE + k];
            #pragma unroll
            for (int i = 0; i < 4; i++)
                #pragma unroll
                for (int j = 0; j < 4; j++)
                    sacc[i][j] += qa[i].x * kb[j].x + qa[i].y * kb[j].y +
                                  qa[i].z * kb[j].z + qa[i].w * kb[j].w;
        }
        const bool diag = (jb == iq);
        #pragma unroll
        for (int i = 0; i < 4; i++) {
            int rr = ty * 4 + i;
            #pragma unroll
            for (int j = 0; j < 4; j++) {
                int cc = tx * 4 + j;
                float v = sacc[i][j];
                if (diag && cc > rr) v = -1e30f;
                Ss[rr * SS_STRIDE + cc] = v;
            }
        }
        __syncthreads();

        {
            const int r = t >> 2;
            const int q = t & 3;
            float mloc = -1e30f;
            #pragma unroll
            for (int kk = 0; kk < 16; kk++)
                mloc = fmaxf(mloc, Ss[r * SS_STRIDE + q * 16 + kk]);
            mloc = fmaxf(mloc, __shfl_xor_sync(0xffffffffu, mloc, 1));
            mloc = fmaxf(mloc, __shfl_xor_sync(0xffffffffu, mloc, 2));
            float mold = m_s[r];
            float mnew = fmaxf(mold, mloc);
            float ssum = 0.f;
            #pragma unroll
            for (int kk = 0; kk < 16; kk++) {
                float p = __expf(Ss[r * SS_STRIDE + q * 16 + kk] - mnew);
                Ss[r * SS_STRIDE + q * 16 + kk] = p;
                ssum += p;
            }
            ssum += __shfl_xor_sync(0xffffffffu, ssum, 1);
            ssum += __shfl_xor_sync(0xffffffffu, ssum, 2);
            if (q == 0) {
                float sc = __expf(mold - mnew);
                m_s[r]  = mnew;
                l_s[r]  = l_s[r] * sc + ssum;
                sc_s[r] = sc;
            }
        }
        __syncthreads();

        #pragma unroll
        for (int i = 0; i < 4; i++) {
            float sc = sc_s[ty * 4 + i];
            #pragma unroll
            for (int j = 0; j < 8; j++) o_acc[i][j] *= sc;
        }
        #pragma unroll 2
        for (int k = 0; k < BC; k++) {
            float a[4];
            #pragma unroll
            for (int i = 0; i < 4; i++)
                a[i] = Ss[(ty * 4 + i) * SS_STRIDE + k];
            float4 v0 = *(float4*)&Vs[k * QKV_STRIDE + tx * 8];
            float4 v1 = *(float4*)&Vs[k * QKV_STRIDE + tx * 8 + 4];
            #pragma unroll
            for (int i = 0; i < 4; i++) {
                o_acc[i][0] += a[i] * v0.x; o_acc[i][1] += a[i] * v0.y;
                o_acc[i][2] += a[i] * v0.z; o_acc[i][3] += a[i] * v0.w;
                o_acc[i][4] += a[i] * v1.x; o_acc[i][5] += a[i] * v1.y;
                o_acc[i][6] += a[i] * v1.z; o_acc[i][7] += a[i] * v1.w;
            }
        }
    }

    #pragma unroll
    for (int i = 0; i < 4; i++) {
        int r = ty * 4 + i;
        float inv = 1.f / l_s[r];
        float4 o0, o1;
        o0.x = o_acc[i][0] * inv; o0.y = o_acc[i][1] * inv;
        o0.z = o_acc[i][2] * inv; o0.w = o_acc[i][3] * inv;
        o1.x = o_acc[i][4] * inv; o1.y = o_acc[i][5] * inv;
        o1.z = o_acc[i][6] * inv; o1.w = o_acc[i][7] * inv;
        float* dst = g_ctx + ((size_t)(b * S + q0 + r)) * D + h * DH + tx * 8;
        *(float4*)(dst)     = o0;
        *(float4*)(dst + 4) = o1;
    }
}

// ---------------------------------------------------------------------------
extern "C" void kernel_launch(void* const* d_in, const int* in_sizes, int n_in,
                              void* d_out, int out_size)
{
    const float* X  = (const float*)d_in[0];
    const float* Wq = (const float*)d_in[1];
    const float* bq = (const float*)d_in[2];
    const float* Wk = (const float*)d_in[3];
    const float* bk = (const float*)d_in[4];
    const float* Wv = (const float*)d_in[5];
    const float* bv = (const float*)d_in[6];
    const float* Wo = (const float*)d_in[7];
    const float* bo = (const float*)d_in[8];
    float* out = (float*)d_out;

    cudaFuncSetAttribute(attn_kernel, cudaFuncAttributeMaxDynamicSharedMemorySize, ATTN_SMEM_BYTES);
    cudaFuncSetAttribute(qkv_tc_gemm, cudaFuncAttributeMaxDynamicSharedMemorySize, GEMM_SMEM);
    cudaFuncSetAttribute(out_tc_gemm, cudaFuncAttributeMaxDynamicSharedMemorySize, GEMM_SMEM);

    // 1. split X into bf16 hi/lo
    split_x_kernel<<<(M * D / 4) / 256, 256>>>((const float4*)X);
    // 2. transpose+split the 4 weight matrices
    wsplit_kernel<<<dim3(D / 32, D / 32, 4), 256>>>(Wq, Wk, Wv, Wo);
    // 3. QKV projections on tensor cores (mma.sync)
    qkv_tc_gemm<<<dim3(D / 128, M / 128, 3), 256, GEMM_SMEM>>>(bq, bk, bv);
    // 4. attention
    attn_kernel<<<dim3(S / BR, B * H), 256, ATTN_SMEM_BYTES>>>();
    // 5. split ctx
    split_ctx_kernel<<<(M * D / 4) / 256, 256>>>();
    // 6. output projection on tensor cores
    out_tc_gemm<<<dim3(D / 128, M / 128), 256, GEMM_SMEM>>>(bo, out);
}

// round 4
// speedup vs baseline: 3.4866x; 2.1749x over previous
#include <cuda_runtime.h>
#include <cuda_bf16.h>
#include <math.h>
#include <cstdint>

// Problem constants
constexpr int B  = 4;
constexpr int S  = 2048;
constexpr int D  = 2048;
constexpr int H  = 16;
constexpr int DH = 128;
constexpr int M  = B * S;          // 8192 rows

// ---------------------------------------------------------------------------
// Scratch (allocation-free rule: device globals). All bf16 hi/lo split pairs.
// ---------------------------------------------------------------------------
__device__ __nv_bfloat16 g_x_h[(size_t)M * D];
__device__ __nv_bfloat16 g_x_l[(size_t)M * D];
__device__ __nv_bfloat16 g_qh[(size_t)M * D];
__device__ __nv_bfloat16 g_ql[(size_t)M * D];
__device__ __nv_bfloat16 g_kh[(size_t)M * D];
__device__ __nv_bfloat16 g_kl[(size_t)M * D];
__device__ __nv_bfloat16 g_vh[(size_t)M * D];
__device__ __nv_bfloat16 g_vl[(size_t)M * D];
__device__ __nv_bfloat16 g_c_h[(size_t)M * D];
__device__ __nv_bfloat16 g_c_l[(size_t)M * D];
__device__ __nv_bfloat16 g_wT_h[(size_t)4 * D * D];   // [w][N][K]
__device__ __nv_bfloat16 g_wT_l[(size_t)4 * D * D];

// ---------------------------------------------------------------------------
// PTX helpers (sm_103 baseline: mma.sync + ldmatrix + cp.async only)
// ---------------------------------------------------------------------------
__device__ __forceinline__ uint32_t smem_u32(const void* p) {
    uint32_t a;
    asm("{ .reg .u64 t; cvta.to.shared.u64 t, %1; cvt.u32.u64 %0, t; }" : "=r"(a) : "l"(p));
    return a;
}

__device__ __forceinline__ void cp_async16(uint32_t dst, const void* src) {
    asm volatile("cp.async.cg.shared.global [%0], [%1], 16;" :: "r"(dst), "l"(src));
}
#define CP_COMMIT() asm volatile("cp.async.commit_group;" ::: "memory")
#define CP_WAIT0()  asm volatile("cp.async.wait_group 0;" ::: "memory")
#define CP_WAIT1()  asm volatile("cp.async.wait_group 1;" ::: "memory")

__device__ __forceinline__ void ldsm_x4(uint32_t* r, uint32_t addr) {
    asm volatile("ldmatrix.sync.aligned.m8n8.x4.shared.b16 {%0,%1,%2,%3}, [%4];"
        : "=r"(r[0]), "=r"(r[1]), "=r"(r[2]), "=r"(r[3]) : "r"(addr));
}
__device__ __forceinline__ void ldsm_x4_t(uint32_t* r, uint32_t addr) {
    asm volatile("ldmatrix.sync.aligned.m8n8.x4.trans.shared.b16 {%0,%1,%2,%3}, [%4];"
        : "=r"(r[0]), "=r"(r[1]), "=r"(r[2]), "=r"(r[3]) : "r"(addr));
}

__device__ __forceinline__ void mma16816(float* c, const uint32_t* a, const uint32_t* b) {
    asm volatile("mma.sync.aligned.m16n8k16.row.col.f32.bf16.bf16.f32 "
        "{%0,%1,%2,%3}, {%4,%5,%6,%7}, {%8,%9}, {%0,%1,%2,%3};"
        : "+f"(c[0]), "+f"(c[1]), "+f"(c[2]), "+f"(c[3])
        : "r"(a[0]), "r"(a[1]), "r"(a[2]), "r"(a[3]), "r"(b[0]), "r"(b[1]));
}

// pack(lo, hi): lo -> bits[15:0], hi -> bits[31:16]
__device__ __forceinline__ uint32_t pack_bf16(float lo, float hi) {
    uint32_t d;
    asm("cvt.rn.bf16x2.f32 %0, %1, %2;" : "=r"(d) : "f"(hi), "f"(lo));
    return d;
}

// fast 2^z for z <= 0 (quartic Taylor after rint reduction, err ~4e-5)
__device__ __forceinline__ float exp2_fast(float z) {
    z = fmaxf(z, -126.f);
    float fi = rintf(z);
    float f  = z - fi;
    float p  = 0.00961813f;
    p = fmaf(p, f, 0.0555041f);
    p = fmaf(p, f, 0.2402265f);
    p = fmaf(p, f, 0.6931472f);
    p = fmaf(p, f, 1.0f);
    int e = (int)fi;
    return p * __int_as_float((uint32_t)(e + 127) << 23);
}

// ---------------------------------------------------------------------------
// Split / transpose conversion kernels
// ---------------------------------------------------------------------------
__global__ __launch_bounds__(256) void split_x_kernel(const float4* __restrict__ in) {
    size_t i = (size_t)blockIdx.x * blockDim.x + threadIdx.x;
    float4 v = in[i];
    float f[4] = {v.x, v.y, v.z, v.w};
    __nv_bfloat16 h[4], l[4];
    #pragma unroll
    for (int j = 0; j < 4; j++) {
        h[j] = __float2bfloat16(f[j]);
        l[j] = __float2bfloat16(f[j] - __bfloat162float(h[j]));
    }
    *(uint2*)(g_x_h + i * 4) = *(const uint2*)h;
    *(uint2*)(g_x_l + i * 4) = *(const uint2*)l;
}

// Weights: W [K][N] fp32 -> transposed split bf16 [N][K]
__global__ __launch_bounds__(256) void wsplit_kernel(const float* __restrict__ Wq,
                                                     const float* __restrict__ Wk,
                                                     const float* __restrict__ Wv,
                                                     const float* __restrict__ Wo) {
    __shared__ float tile[32][33];
    int z = blockIdx.z;
    const float* W = (z == 0) ? Wq : (z == 1) ? Wk : (z == 2) ? Wv : Wo;
    __nv_bfloat16* oh = g_wT_h + (size_t)z * D * D;
    __nv_bfloat16* ol = g_wT_l + (size_t)z * D * D;
    int n0 = blockIdx.x * 32, k0 = blockIdx.y * 32;
    int tx = threadIdx.x & 31, ty = threadIdx.x >> 5;
    #pragma unroll
    for (int i = 0; i < 4; i++) {
        int k = ty + i * 8;
        tile[k][tx] = W[(size_t)(k0 + k) * D + n0 + tx];
    }
    __syncthreads();
    #pragma unroll
    for (int i = 0; i < 4; i++) {
        int n = ty + i * 8;
        float v = tile[tx][n];
        __nv_bfloat16 h = __float2bfloat16(v);
        __nv_bfloat16 l = __float2bfloat16(v - __bfloat162float(h));
        oh[(size_t)(n0 + n) * D + k0 + tx] = h;
        ol[(size_t)(n0 + n) * D + k0 + tx] = l;
    }
}

// ---------------------------------------------------------------------------
// mma.sync split-bf16 GEMM (as R3, with selectable epilogue)
// ---------------------------------------------------------------------------
constexpr int BKG      = 32;
constexpr int LDT      = 40;
constexpr int TILE_BY  = 128 * LDT * 2;
constexpr int STAGE_BY = 4 * TILE_BY;
constexpr int GEMM_SMEM = 2 * STAGE_BY;
constexpr int NITER    = D / BKG;

__device__ __forceinline__ void load_stage(uint32_t sbase,
                                           const __nv_bfloat16* Ah,
                                           const __nv_bfloat16* Al,
                                           const __nv_bfloat16* Bh,
                                           const __nv_bfloat16* Bl,
                                           int k0, int t) {
    const __nv_bfloat16* bases[4] = {Ah, Al, Bh, Bl};
    #pragma unroll
    for (int i = 0; i < 8; i++) {
        const int tile = i >> 1;
        int rem  = t + 256 * (i & 1);
        int row  = rem >> 2;
        int chnk = rem & 3;
        const __nv_bfloat16* src = bases[tile] + (size_t)row * D + k0 + chnk * 8;
        uint32_t dst = sbase + tile * TILE_BY + row * (LDT * 2) + chnk * 16;
        cp_async16(dst, src);
    }
    CP_COMMIT();
}

template <int SPLIT_OUT>
__device__ __forceinline__ void tc_gemm_body(const __nv_bfloat16* __restrict__ Ahp,
                                             const __nv_bfloat16* __restrict__ Alp,
                                             const __nv_bfloat16* __restrict__ Bhp,
                                             const __nv_bfloat16* __restrict__ Blp,
                                             const float* __restrict__ bias,
                                             float* __restrict__ C,
                                             __nv_bfloat16* __restrict__ Ch,
                                             __nv_bfloat16* __restrict__ Cl) {
    extern __shared__ char smem[];
    const uint32_t sb = smem_u32(smem);
    const int t    = threadIdx.x;
    const int lane = t & 31;
    const int w    = t >> 5;
    const int wm   = (w & 1) * 64;
    const int wn   = (w >> 1) * 32;
    const int m0   = blockIdx.y * 128;
    const int n0   = blockIdx.x * 128;

    const __nv_bfloat16* Arow  = Ahp + (size_t)m0 * D;
    const __nv_bfloat16* AlRow = Alp + (size_t)m0 * D;
    const __nv_bfloat16* Brow  = Bhp + (size_t)n0 * D;
    const __nv_bfloat16* BlRow = Blp + (size_t)n0 * D;

    float acc[4][4][4];
    #pragma unroll
    for (int i = 0; i < 4; i++)
        #pragma unroll
        for (int j = 0; j < 4; j++)
            #pragma unroll
            for (int r = 0; r < 4; r++) acc[i][j][r] = 0.f;

    const int arow  = lane & 15;
    const int akoff = (lane >> 4) * 16;
    const int bn    = (lane & 7) + ((lane >> 4) << 3);
    const int bkoff = ((lane >> 3) & 1) * 16;

    load_stage(sb, Arow, AlRow, Brow, BlRow, 0, t);

    for (int c = 0; c < NITER; c++) {
        if (c + 1 < NITER) {
            load_stage(sb + ((c + 1) & 1) * STAGE_BY, Arow, AlRow, Brow, BlRow,
                       (c + 1) * BKG, t);
            CP_WAIT1();
        } else {
            CP_WAIT0();
        }
        __syncthreads();

        const uint32_t sbase = sb + (c & 1) * STAGE_BY;
        #pragma unroll
        for (int kk = 0; kk < 2; kk++) {
            const uint32_t kbyte = kk * 32;
            uint32_t ah[4][4], al[4][4];
            #pragma unroll
            for (int mf = 0; mf < 4; mf++) {
                uint32_t ad = sbase + (wm + mf * 16 + arow) * (LDT * 2) + kbyte + akoff;
                ldsm_x4(ah[mf], ad);
                ldsm_x4(al[mf], ad + TILE_BY);
            }
            uint32_t bh[8], bl[8];
            #pragma unroll
            for (int bp = 0; bp < 2; bp++) {
                uint32_t bd = sbase + 2 * TILE_BY + (wn + bp * 16 + bn) * (LDT * 2) + kbyte + bkoff;
                ldsm_x4(&bh[bp * 4], bd);
                ldsm_x4(&bl[bp * 4], bd + TILE_BY);
            }
            #pragma unroll
            for (int mf = 0; mf < 4; mf++)
                #pragma unroll
                for (int nf = 0; nf < 4; nf++) {
                    const uint32_t* bhp = &bh[(nf >> 1) * 4 + (nf & 1) * 2];
                    const uint32_t* blp = &bl[(nf >> 1) * 4 + (nf & 1) * 2];
                    mma16816(acc[mf][nf], ah[mf], bhp);
                    mma16816(acc[mf][nf], ah[mf], blp);
                    mma16816(acc[mf][nf], al[mf], bhp);
                }
        }
        __syncthreads();
    }

    // Epilogue
    const int rbase = m0 + wm + (lane >> 2);
    const int cbase = n0 + wn + (lane & 3) * 2;
    #pragma unroll
    for (int mf = 0; mf < 4; mf++) {
        #pragma unroll
        for (int nf = 0; nf < 4; nf++) {
            int col = cbase + nf * 8;
            float2 bv = *(const float2*)(bias + col);
            int r0 = rbase + mf * 16;
            float v0 = acc[mf][nf][0] + bv.x, v1 = acc[mf][nf][1] + bv.y;
            float v2 = acc[mf][nf][2] + bv.x, v3 = acc[mf][nf][3] + bv.y;
            if (SPLIT_OUT) {
                uint32_t h01 = pack_bf16(v0, v1);
                float h0 = __uint_as_float(h01 << 16);
                float h1 = __uint_as_float(h01 & 0xffff0000u);
                uint32_t l01 = pack_bf16(v0 - h0, v1 - h1);
                uint32_t h23 = pack_bf16(v2, v3);
                float h2 = __uint_as_float(h23 << 16);
                float h3 = __uint_as_float(h23 & 0xffff0000u);
                uint32_t l23 = pack_bf16(v2 - h2, v3 - h3);
                *(uint32_t*)(Ch + (size_t)r0 * D + col)       = h01;
                *(uint32_t*)(Cl + (size_t)r0 * D + col)       = l01;
                *(uint32_t*)(Ch + (size_t)(r0 + 8) * D + col) = h23;
                *(uint32_t*)(Cl + (size_t)(r0 + 8) * D + col) = l23;
            } else {
                float2 o0 = {v0, v1}, o1 = {v2, v3};
                *(float2*)(C + (size_t)r0 * D + col)       = o0;
                *(float2*)(C + (size_t)(r0 + 8) * D + col) = o1;
            }
        }
    }
}

__global__ __launch_bounds__(256) void qkv_tc_gemm(const float* __restrict__ bq,
                                                   const float* __restrict__ bk,
                                                   const float* __restrict__ bv) {
    const int z = blockIdx.z;
    const __nv_bfloat16* Bh = g_wT_h + (size_t)z * D * D;
    const __nv_bfloat16* Bl = g_wT_l + (size_t)z * D * D;
    const float* bias = (z == 0) ? bq : (z == 1) ? bk : bv;
    __nv_bfloat16* Ch = (z == 0) ? g_qh : (z == 1) ? g_kh : g_vh;
    __nv_bfloat16* Cl = (z == 0) ? g_ql : (z == 1) ? g_kl : g_vl;
    tc_gemm_body<1>(g_x_h, g_x_l, Bh, Bl, bias, nullptr, Ch, Cl);
}

__global__ __launch_bounds__(256) void out_tc_gemm(const float* __restrict__ bo,
                                                   float* __restrict__ out) {
    tc_gemm_body<0>(g_c_h, g_c_l, g_wT_h + (size_t)3 * D * D, g_wT_l + (size_t)3 * D * D,
                    bo, out, nullptr, nullptr);
}

// ---------------------------------------------------------------------------
// Tensor-core flash attention (split-bf16, causal). Br=Bc=64, 128 threads.
// Warp w owns q rows [w*16, w*16+16). grid: (S/64, B*H), q blocks reversed.
// ---------------------------------------------------------------------------
constexpr int AT_LDB   = 272;                    // bytes per tile row (136 bf16)
constexpr int AT_TILE  = 64 * AT_LDB;            // 17408 B
constexpr int ATTN_SMEM = 6 * AT_TILE;           // 104448 B
constexpr float SCALE_LOG2E = 0.12751650f;       // (1/sqrt(128)) * log2(e)

__global__ __launch_bounds__(128) void attn_tc_kernel() {
    extern __shared__ char sm8[];
    const uint32_t sb = smem_u32(sm8);
    const uint32_t Qh = sb,               Ql = sb + AT_TILE;
    const uint32_t Kh = sb + 2 * AT_TILE, Kl = sb + 3 * AT_TILE;
    const uint32_t Vh = sb + 4 * AT_TILE, Vl = sb + 5 * AT_TILE;

    const int t    = threadIdx.x;
    const int lane = t & 31;
    const int w    = t >> 5;
    const int iq   = (gridDim.x - 1) - blockIdx.x;      // big blocks first
    const int bh   = blockIdx.y;
    const int b    = bh >> 4;
    const int h    = bh & 15;
    const int q0   = iq * 64;
    const int wq   = w * 16;

    // Load Q tile (hi/lo): 64 rows x 128 dh
    {
        #pragma unroll
        for (int i = 0; i < 8; i++) {
            int idx  = t + 128 * i;            // 0..1023
            int row  = idx >> 4;
            int chnk = idx & 15;
            size_t g = (size_t)(b * S + q0 + row) * D + h * DH + chnk * 8;
            uint32_t so = row * AT_LDB + chnk * 16;
            cp_async16(Qh + so, g_qh + g);
            cp_async16(Ql + so, g_ql + g);
        }
        CP_COMMIT();
    }

    // ldmatrix lane offsets
    const int arow  = lane & 15;
    const int akoff = (lane >> 4) * 16;
    const int bn    = (lane & 7) + ((lane >> 4) << 3);
    const int bkoff = ((lane >> 3) & 1) * 16;
    const int vrow  = lane & 15;                 // k row for trans load
    const int vcol  = (lane >> 4) << 3;          // n col group

    float o[16][4];
    #pragma unroll
    for (int i = 0; i < 16; i++)
        #pragma unroll
        for (int r = 0; r < 4; r++) o[i][r] = 0.f;
    float m0 = -1e30f, m1 = -1e30f, l0 = 0.f, l1 = 0.f;

    const int r0g = q0 + wq + (lane >> 2);       // global q row (upper)
    const int r1g = r0g + 8;

    for (int jb = 0; jb <= iq; jb++) {
        const int k0 = jb * 64;
        if (jb > 0) __syncthreads();             // done reading prev K/V
        // Load K/V tiles (hi/lo)
        #pragma unroll
        for (int i = 0; i < 8; i++) {
            int idx  = t + 128 * i;
            int row  = idx >> 4;
            int chnk = idx & 15;
            size_t g = (size_t)(b * S + k0 + row) * D + h * DH + chnk * 8;
            uint32_t so = row * AT_LDB + chnk * 16;
            cp_async16(Kh + so, g_kh + g);
            cp_async16(Kl + so, g_kl + g);
            cp_async16(Vh + so, g_vh + g);
            cp_async16(Vl + so, g_vl + g);
        }
        CP_COMMIT();
        CP_WAIT0();
        __syncthreads();

        // ---- S = Q K^T (3-pass split) ----
        float c[8][4];
        #pragma unroll
        for (int j = 0; j < 8; j++)
            #pragma unroll
            for (int r = 0; r < 4; r++) c[j][r] = 0.f;

        #pragma unroll
        for (int kt = 0; kt < 8; kt++) {
            uint32_t qa[4], ql4[4];
            uint32_t ad = Qh + (wq + arow) * AT_LDB + kt * 32 + akoff;
            ldsm_x4(qa, ad);
            ldsm_x4(ql4, ad + AT_TILE);
            #pragma unroll
            for (int nb = 0; nb < 4; nb++) {
                uint32_t kh4[4], kl4[4];
                uint32_t bd = Kh + (nb * 16 + bn) * AT_LDB + kt * 32 + bkoff;
                ldsm_x4(kh4, bd);
                ldsm_x4(kl4, bd + AT_TILE);
                #pragma unroll
                for (int half = 0; half < 2; half++) {
                    int nf = nb * 2 + half;
                    mma16816(c[nf], qa,  &kh4[half * 2]);
                    mma16816(c[nf], qa,  &kl4[half * 2]);
                    mma16816(c[nf], ql4, &kh4[half * 2]);
                }
            }
        }

        // ---- scale + causal mask ----
        const bool diag = (jb == iq);
        #pragma unroll
        for (int j = 0; j < 8; j++) {
            int cc = k0 + j * 8 + (lane & 3) * 2;
            #pragma unroll
            for (int r = 0; r < 4; r++) {
                float v = c[j][r] * SCALE_LOG2E;
                if (diag) {
                    int col = cc + (r & 1);
                    int row = (r < 2) ? r0g : r1g;
                    if (col > row) v = -1e30f;
                }
                c[j][r] = v;
            }
        }

        // ---- online softmax (log2 domain) ----
        float mx0 = -1e30f, mx1 = -1e30f;
        #pragma unroll
        for (int j = 0; j < 8; j++) {
            mx0 = fmaxf(mx0, fmaxf(c[j][0], c[j][1]));
            mx1 = fmaxf(mx1, fmaxf(c[j][2], c[j][3]));
        }
        mx0 = fmaxf(mx0, __shfl_xor_sync(0xffffffffu, mx0, 1));
        mx0 = fmaxf(mx0, __shfl_xor_sync(0xffffffffu, mx0, 2));
        mx1 = fmaxf(mx1, __shfl_xor_sync(0xffffffffu, mx1, 1));
        mx1 = fmaxf(mx1, __shfl_xor_sync(0xffffffffu, mx1, 2));
        float mn0 = fmaxf(m0, mx0), mn1 = fmaxf(m1, mx1);
        float sc0 = exp2_fast(m0 - mn0), sc1 = exp2_fast(m1 - mn1);
        m0 = mn0; m1 = mn1;

        float ls0 = 0.f, ls1 = 0.f;
        #pragma unroll
        for (int j = 0; j < 8; j++) {
            c[j][0] = exp2_fast(c[j][0] - mn0);
            c[j][1] = exp2_fast(c[j][1] - mn0);
            c[j][2] = exp2_fast(c[j][2] - mn1);
            c[j][3] = exp2_fast(c[j][3] - mn1);
            ls0 += c[j][0] + c[j][1];
            ls1 += c[j][2] + c[j][3];
        }
        ls0 += __shfl_xor_sync(0xffffffffu, ls0, 1);
        ls0 += __shfl_xor_sync(0xffffffffu, ls0, 2);
        ls1 += __shfl_xor_sync(0xffffffffu, ls1, 1);
        ls1 += __shfl_xor_sync(0xffffffffu, ls1, 2);
        l0 = l0 * sc0 + ls0;
        l1 = l1 * sc1 + ls1;

        // rescale O
        #pragma unroll
        for (int nf = 0; nf < 16; nf++) {
            o[nf][0] *= sc0; o[nf][1] *= sc0;
            o[nf][2] *= sc1; o[nf][3] *= sc1;
        }

        // ---- pack P to hi/lo A-fragments ----
        uint32_t pah[4][4], pal[4][4];
        #pragma unroll
        for (int g = 0; g < 4; g++) {
            #pragma unroll
            for (int q = 0; q < 4; q++) {
                int j = 2 * g + (q >> 1);
                int e = (q & 1) * 2;
                float p0v = c[j][e], p1v = c[j][e + 1];
                uint32_t hp = pack_bf16(p0v, p1v);
                float h0 = __uint_as_float(hp << 16);
                float h1 = __uint_as_float(hp & 0xffff0000u);
                pah[g][q] = hp;
                pal[g][q] = pack_bf16(p0v - h0, p1v - h1);
            }
        }

        // ---- O += P V (3-pass split), V via ldmatrix.trans ----
        #pragma unroll
        for (int g = 0; g < 4; g++) {
            #pragma unroll
            for (int vb = 0; vb < 8; vb++) {
                uint32_t vh4[4], vl4[4];
                uint32_t vd = Vh + (g * 16 + vrow) * AT_LDB + (vb * 16 + vcol) * 2;
                ldsm_x4_t(vh4, vd);
                ldsm_x4_t(vl4, vd + AT_TILE);
                #pragma unroll
                for (int half = 0; half < 2; half++) {
                    int nf = vb * 2 + half;
                    mma16816(o[nf], pah[g], &vh4[half * 2]);
                    mma16816(o[nf], pah[g], &vl4[half * 2]);
                    mma16816(o[nf], pal[g], &vh4[half * 2]);
                }
            }
        }
    }

    // ---- finalize: O/l, write ctx as bf16 hi/lo ----
    const float inv0 = 1.f / l0, inv1 = 1.f / l1;
    const int colb = h * DH + (lane & 3) * 2;
    #pragma unroll
    for (int nf = 0; nf < 16; nf++) {
        int col = colb + nf * 8;
        float v0 = o[nf][0] * inv0, v1 = o[nf][1] * inv0;
        float v2 = o[nf][2] * inv1, v3 = o[nf][3] * inv1;
        uint32_t h01 = pack_bf16(v0, v1);
        float h0 = __uint_as_float(h01 << 16);
        float h1 = __uint_as_float(h01 & 0xffff0000u);
        uint32_t l01 = pack_bf16(v0 - h0, v1 - h1);
        uint32_t h23 = pack_bf16(v2, v3);
        float h2 = __uint_as_float(h23 << 16);
        float h3 = __uint_as_float(h23 & 0xffff0000u);
        uint32_t l23 = pack_bf16(v2 - h2, v3 - h3);
        size_t g0 = (size_t)(b * S + r0g) * D + col;
        size_t g1 = (size_t)(b * S + r1g) * D + col;
        *(uint32_t*)(g_c_h + g0) = h01;
        *(uint32_t*)(g_c_l + g0) = l01;
        *(uint32_t*)(g_c_h + g1) = h23;
        *(uint32_t*)(g_c_l + g1) = l23;
    }
}

// ---------------------------------------------------------------------------
extern "C" void kernel_launch(void* const* d_in, const int* in_sizes, int n_in,
                              void* d_out, int out_size)
{
    const float* X  = (const float*)d_in[0];
    const float* Wq = (const float*)d_in[1];
    const float* bq = (const float*)d_in[2];
    const float* Wk = (const float*)d_in[3];
    const float* bk = (const float*)d_in[4];
    const float* Wv = (const float*)d_in[5];
    const float* bv = (const float*)d_in[6];
    const float* Wo = (const float*)d_in[7];
    const float* bo = (const float*)d_in[8];
    float* out = (float*)d_out;

    cudaFuncSetAttribute(attn_tc_kernel, cudaFuncAttributeMaxDynamicSharedMemorySize, ATTN_SMEM);
    cudaFuncSetAttribute(qkv_tc_gemm, cudaFuncAttributeMaxDynamicSharedMemorySize, GEMM_SMEM);
    cudaFuncSetAttribute(out_tc_gemm, cudaFuncAttributeMaxDynamicSharedMemorySize, GEMM_SMEM);

    split_x_kernel<<<(M * D / 4) / 256, 256>>>((const float4*)X);
    wsplit_kernel<<<dim3(D / 32, D / 32, 4), 256>>>(Wq, Wk, Wv, Wo);
    qkv_tc_gemm<<<dim3(D / 128, M / 128, 3), 256, GEMM_SMEM>>>(bq, bk, bv);
    attn_tc_kernel<<<dim3(S / 64, B * H), 128, ATTN_SMEM>>>();
    out_tc_gemm<<<dim3(D / 128, M / 128), 256, GEMM_SMEM>>>(bo, out);
}

// round 5
// speedup vs baseline: 3.5915x; 1.0301x over previous
#include <cuda_runtime.h>
#include <cuda_bf16.h>
#include <math.h>
#include <cstdint>

// Problem constants
constexpr int B  = 4;
constexpr int S  = 2048;
constexpr int D  = 2048;
constexpr int H  = 16;
constexpr int DH = 128;
constexpr int M  = B * S;          // 8192 rows

// ---------------------------------------------------------------------------
// Scratch (allocation-free rule: device globals). All bf16 hi/lo split pairs.
// ---------------------------------------------------------------------------
__device__ __nv_bfloat16 g_x_h[(size_t)M * D];
__device__ __nv_bfloat16 g_x_l[(size_t)M * D];
__device__ __nv_bfloat16 g_qh[(size_t)M * D];
__device__ __nv_bfloat16 g_ql[(size_t)M * D];
__device__ __nv_bfloat16 g_kh[(size_t)M * D];
__device__ __nv_bfloat16 g_kl[(size_t)M * D];
__device__ __nv_bfloat16 g_vh[(size_t)M * D];
__device__ __nv_bfloat16 g_vl[(size_t)M * D];
__device__ __nv_bfloat16 g_c_h[(size_t)M * D];
__device__ __nv_bfloat16 g_c_l[(size_t)M * D];
__device__ __nv_bfloat16 g_wT_h[(size_t)4 * D * D];   // [w][N][K]
__device__ __nv_bfloat16 g_wT_l[(size_t)4 * D * D];

// ---------------------------------------------------------------------------
// PTX helpers (sm_103 baseline: mma.sync + ldmatrix + cp.async only)
// ---------------------------------------------------------------------------
__device__ __forceinline__ uint32_t smem_u32(const void* p) {
    uint32_t a;
    asm("{ .reg .u64 t; cvta.to.shared.u64 t, %1; cvt.u32.u64 %0, t; }" : "=r"(a) : "l"(p));
    return a;
}

__device__ __forceinline__ void cp_async16(uint32_t dst, const void* src) {
    asm volatile("cp.async.cg.shared.global [%0], [%1], 16;" :: "r"(dst), "l"(src));
}
#define CP_COMMIT() asm volatile("cp.async.commit_group;" ::: "memory")
#define CP_WAIT0()  asm volatile("cp.async.wait_group 0;" ::: "memory")
#define CP_WAIT1()  asm volatile("cp.async.wait_group 1;" ::: "memory")

__device__ __forceinline__ void ldsm_x4(uint32_t* r, uint32_t addr) {
    asm volatile("ldmatrix.sync.aligned.m8n8.x4.shared.b16 {%0,%1,%2,%3}, [%4];"
        : "=r"(r[0]), "=r"(r[1]), "=r"(r[2]), "=r"(r[3]) : "r"(addr));
}
__device__ __forceinline__ void ldsm_x4_t(uint32_t* r, uint32_t addr) {
    asm volatile("ldmatrix.sync.aligned.m8n8.x4.trans.shared.b16 {%0,%1,%2,%3}, [%4];"
        : "=r"(r[0]), "=r"(r[1]), "=r"(r[2]), "=r"(r[3]) : "r"(addr));
}

__device__ __forceinline__ void mma16816(float* c, const uint32_t* a, const uint32_t* b) {
    asm volatile("mma.sync.aligned.m16n8k16.row.col.f32.bf16.bf16.f32 "
        "{%0,%1,%2,%3}, {%4,%5,%6,%7}, {%8,%9}, {%0,%1,%2,%3};"
        : "+f"(c[0]), "+f"(c[1]), "+f"(c[2]), "+f"(c[3])
        : "r"(a[0]), "r"(a[1]), "r"(a[2]), "r"(a[3]), "r"(b[0]), "r"(b[1]));
}

// pack(lo, hi): lo -> bits[15:0], hi -> bits[31:16]
__device__ __forceinline__ uint32_t pack_bf16(float lo, float hi) {
    uint32_t d;
    asm("cvt.rn.bf16x2.f32 %0, %1, %2;" : "=r"(d) : "f"(hi), "f"(lo));
    return d;
}

// fast 2^z for z <= 0 (quartic Taylor after rint reduction, err ~4e-5)
__device__ __forceinline__ float exp2_fast(float z) {
    z = fmaxf(z, -126.f);
    float fi = rintf(z);
    float f  = z - fi;
    float p  = 0.00961813f;
    p = fmaf(p, f, 0.0555041f);
    p = fmaf(p, f, 0.2402265f);
    p = fmaf(p, f, 0.6931472f);
    p = fmaf(p, f, 1.0f);
    int e = (int)fi;
    return p * __int_as_float((uint32_t)(e + 127) << 23);
}

// ---------------------------------------------------------------------------
// Split / transpose conversion kernels
// ---------------------------------------------------------------------------
__global__ __launch_bounds__(256) void split_x_kernel(const float4* __restrict__ in) {
    size_t i = (size_t)blockIdx.x * blockDim.x + threadIdx.x;
    float4 v = in[i];
    float f[4] = {v.x, v.y, v.z, v.w};
    __nv_bfloat16 h[4], l[4];
    #pragma unroll
    for (int j = 0; j < 4; j++) {
        h[j] = __float2bfloat16(f[j]);
        l[j] = __float2bfloat16(f[j] - __bfloat162float(h[j]));
    }
    *(uint2*)(g_x_h + i * 4) = *(const uint2*)h;
    *(uint2*)(g_x_l + i * 4) = *(const uint2*)l;
}

// Weights: W [K][N] fp32 -> transposed split bf16 [N][K]
__global__ __launch_bounds__(256) void wsplit_kernel(const float* __restrict__ Wq,
                                                     const float* __restrict__ Wk,
                                                     const float* __restrict__ Wv,
                                                     const float* __restrict__ Wo) {
    __shared__ float tile[32][33];
    int z = blockIdx.z;
    const float* W = (z == 0) ? Wq : (z == 1) ? Wk : (z == 2) ? Wv : Wo;
    __nv_bfloat16* oh = g_wT_h + (size_t)z * D * D;
    __nv_bfloat16* ol = g_wT_l + (size_t)z * D * D;
    int n0 = blockIdx.x * 32, k0 = blockIdx.y * 32;
    int tx = threadIdx.x & 31, ty = threadIdx.x >> 5;
    #pragma unroll
    for (int i = 0; i < 4; i++) {
        int k = ty + i * 8;
        tile[k][tx] = W[(size_t)(k0 + k) * D + n0 + tx];
    }
    __syncthreads();
    #pragma unroll
    for (int i = 0; i < 4; i++) {
        int n = ty + i * 8;
        float v = tile[tx][n];
        __nv_bfloat16 h = __float2bfloat16(v);
        __nv_bfloat16 l = __float2bfloat16(v - __bfloat162float(h));
        oh[(size_t)(n0 + n) * D + k0 + tx] = h;
        ol[(size_t)(n0 + n) * D + k0 + tx] = l;
    }
}

// ---------------------------------------------------------------------------
// mma.sync split-bf16 GEMM: C[128x128 tile] = A(hi+lo) @ B(hi+lo)^T + bias
// 4 warps (2x2), warp tile 64x64, BK=32, double-buffered cp.async, 128 thr.
// ---------------------------------------------------------------------------
constexpr int BKG      = 32;
constexpr int LDT      = 40;                 // bf16 stride per tile row (80 B)
constexpr int TILE_BY  = 128 * LDT * 2;      // 10240 B per tile
constexpr int STAGE_BY = 4 * TILE_BY;        // Ah, Al, Bh, Bl = 40960 B
constexpr int GEMM_SMEM = 2 * STAGE_BY;      // 81920 B
constexpr int NITER    = D / BKG;            // 64

__device__ __forceinline__ void load_stage(uint32_t sbase,
                                           const __nv_bfloat16* Ah,
                                           const __nv_bfloat16* Al,
                                           const __nv_bfloat16* Bh,
                                           const __nv_bfloat16* Bl,
                                           int k0, int t) {
    const __nv_bfloat16* bases[4] = {Ah, Al, Bh, Bl};
    #pragma unroll
    for (int i = 0; i < 16; i++) {
        const int tile = i >> 2;              // 4 slots per tile per thread
        int idx  = t + 128 * (i & 3);         // 0..511
        int row  = idx >> 2;                  // 0..127
        int chnk = idx & 3;                   // 16B chunk
        const __nv_bfloat16* src = bases[tile] + (size_t)row * D + k0 + chnk * 8;
        uint32_t dst = sbase + tile * TILE_BY + row * (LDT * 2) + chnk * 16;
        cp_async16(dst, src);
    }
    CP_COMMIT();
}

template <int SPLIT_OUT>
__device__ __forceinline__ void tc_gemm_body(const __nv_bfloat16* __restrict__ Ahp,
                                             const __nv_bfloat16* __restrict__ Alp,
                                             const __nv_bfloat16* __restrict__ Bhp,
                                             const __nv_bfloat16* __restrict__ Blp,
                                             const float* __restrict__ bias,
                                             float* __restrict__ C,
                                             __nv_bfloat16* __restrict__ Ch,
                                             __nv_bfloat16* __restrict__ Cl) {
    extern __shared__ char smem[];
    const uint32_t sb = smem_u32(smem);
    const int t    = threadIdx.x;
    const int lane = t & 31;
    const int w    = t >> 5;
    const int wm   = (w & 1) * 64;
    const int wn   = (w >> 1) * 64;
    const int m0   = blockIdx.y * 128;
    const int n0   = blockIdx.x * 128;

    const __nv_bfloat16* Arow  = Ahp + (size_t)m0 * D;
    const __nv_bfloat16* AlRow = Alp + (size_t)m0 * D;
    const __nv_bfloat16* Brow  = Bhp + (size_t)n0 * D;
    const __nv_bfloat16* BlRow = Blp + (size_t)n0 * D;

    float acc[4][8][4];
    #pragma unroll
    for (int i = 0; i < 4; i++)
        #pragma unroll
        for (int j = 0; j < 8; j++)
            #pragma unroll
            for (int r = 0; r < 4; r++) acc[i][j][r] = 0.f;

    const int arow  = lane & 15;
    const int akoff = (lane >> 4) * 16;
    const int bn    = (lane & 7) + ((lane >> 4) << 3);
    const int bkoff = ((lane >> 3) & 1) * 16;

    load_stage(sb, Arow, AlRow, Brow, BlRow, 0, t);

    for (int c = 0; c < NITER; c++) {
        if (c + 1 < NITER) {
            load_stage(sb + ((c + 1) & 1) * STAGE_BY, Arow, AlRow, Brow, BlRow,
                       (c + 1) * BKG, t);
            CP_WAIT1();
        } else {
            CP_WAIT0();
        }
        __syncthreads();                       // stage c visible to all

        const uint32_t sbase = sb + (c & 1) * STAGE_BY;
        #pragma unroll
        for (int kk = 0; kk < 2; kk++) {
            const uint32_t kbyte = kk * 32;
            uint32_t ah[4][4], al[4][4];
            #pragma unroll
            for (int mf = 0; mf < 4; mf++) {
                uint32_t ad = sbase + (wm + mf * 16 + arow) * (LDT * 2) + kbyte + akoff;
                ldsm_x4(ah[mf], ad);
                ldsm_x4(al[mf], ad + TILE_BY);
            }
            #pragma unroll
            for (int nb = 0; nb < 4; nb++) {
                uint32_t bh4[4], bl4[4];
                uint32_t bd = sbase + 2 * TILE_BY + (wn + nb * 16 + bn) * (LDT * 2) + kbyte + bkoff;
                ldsm_x4(bh4, bd);
                ldsm_x4(bl4, bd + TILE_BY);
                #pragma unroll
                for (int mf = 0; mf < 4; mf++)
                    #pragma unroll
                    for (int half = 0; half < 2; half++) {
                        int nf = nb * 2 + half;
                        mma16816(acc[mf][nf], ah[mf], &bh4[half * 2]);
                        mma16816(acc[mf][nf], ah[mf], &bl4[half * 2]);
                        mma16816(acc[mf][nf], al[mf], &bh4[half * 2]);
                    }
            }
        }
        __syncthreads();                       // done reading stage c
    }

    // Epilogue
    const int rbase = m0 + wm + (lane >> 2);
    const int cbase = n0 + wn + (lane & 3) * 2;
    #pragma unroll
    for (int mf = 0; mf < 4; mf++) {
        #pragma unroll
        for (int nf = 0; nf < 8; nf++) {
            int col = cbase + nf * 8;
            float2 bv = *(const float2*)(bias + col);
            int r0 = rbase + mf * 16;
            float v0 = acc[mf][nf][0] + bv.x, v1 = acc[mf][nf][1] + bv.y;
            float v2 = acc[mf][nf][2] + bv.x, v3 = acc[mf][nf][3] + bv.y;
            if (SPLIT_OUT) {
                uint32_t h01 = pack_bf16(v0, v1);
                float h0 = __uint_as_float(h01 << 16);
                float h1 = __uint_as_float(h01 & 0xffff0000u);
                uint32_t l01 = pack_bf16(v0 - h0, v1 - h1);
                uint32_t h23 = pack_bf16(v2, v3);
                float h2 = __uint_as_float(h23 << 16);
                float h3 = __uint_as_float(h23 & 0xffff0000u);
                uint32_t l23 = pack_bf16(v2 - h2, v3 - h3);
                *(uint32_t*)(Ch + (size_t)r0 * D + col)       = h01;
                *(uint32_t*)(Cl + (size_t)r0 * D + col)       = l01;
                *(uint32_t*)(Ch + (size_t)(r0 + 8) * D + col) = h23;
                *(uint32_t*)(Cl + (size_t)(r0 + 8) * D + col) = l23;
            } else {
                float2 o0 = {v0, v1}, o1 = {v2, v3};
                *(float2*)(C + (size_t)r0 * D + col)       = o0;
                *(float2*)(C + (size_t)(r0 + 8) * D + col) = o1;
            }
        }
    }
}

__global__ __launch_bounds__(128) void qkv_tc_gemm(const float* __restrict__ bq,
                                                   const float* __restrict__ bk,
                                                   const float* __restrict__ bv) {
    const int z = blockIdx.z;
    const __nv_bfloat16* Bh = g_wT_h + (size_t)z * D * D;
    const __nv_bfloat16* Bl = g_wT_l + (size_t)z * D * D;
    const float* bias = (z == 0) ? bq : (z == 1) ? bk : bv;
    __nv_bfloat16* Ch = (z == 0) ? g_qh : (z == 1) ? g_kh : g_vh;
    __nv_bfloat16* Cl = (z == 0) ? g_ql : (z == 1) ? g_kl : g_vl;
    tc_gemm_body<1>(g_x_h, g_x_l, Bh, Bl, bias, nullptr, Ch, Cl);
}

__global__ __launch_bounds__(128) void out_tc_gemm(const float* __restrict__ bo,
                                                   float* __restrict__ out) {
    tc_gemm_body<0>(g_c_h, g_c_l, g_wT_h + (size_t)3 * D * D, g_wT_l + (size_t)3 * D * D,
                    bo, out, nullptr, nullptr);
}

// ---------------------------------------------------------------------------
// Tensor-core flash attention (split-bf16, causal). Br=Bc=64, 128 threads.
// Q held in registers; warp w owns q rows [w*16, w*16+16).
// ---------------------------------------------------------------------------
constexpr int AT_LDB   = 272;                    // bytes per tile row (136 bf16)
constexpr int AT_TILE  = 64 * AT_LDB;            // 17408 B
constexpr int ATTN_SMEM = 6 * AT_TILE;           // 104448 B
constexpr float SCALE_LOG2E = 0.12751650f;       // (1/sqrt(128)) * log2(e)

__global__ __launch_bounds__(128) void attn_tc_kernel() {
    extern __shared__ char sm8[];
    const uint32_t sb = smem_u32(sm8);
    const uint32_t Qh = sb,               Ql = sb + AT_TILE;
    const uint32_t Kh = sb + 2 * AT_TILE, Kl = sb + 3 * AT_TILE;
    const uint32_t Vh = sb + 4 * AT_TILE, Vl = sb + 5 * AT_TILE;

    const int t    = threadIdx.x;
    const int lane = t & 31;
    const int w    = t >> 5;
    const int iq   = (gridDim.x - 1) - blockIdx.x;      // big blocks first
    const int bh   = blockIdx.y;
    const int b    = bh >> 4;
    const int h    = bh & 15;
    const int q0   = iq * 64;
    const int wq   = w * 16;

    // ldmatrix lane offsets
    const int arow  = lane & 15;
    const int akoff = (lane >> 4) * 16;
    const int bn    = (lane & 7) + ((lane >> 4) << 3);
    const int bkoff = ((lane >> 3) & 1) * 16;
    const int vrow  = lane & 15;
    const int vcol  = (lane >> 4) << 3;

    // ---- Load Q tile to smem, then hoist to registers ----
    {
        #pragma unroll
        for (int i = 0; i < 8; i++) {
            int idx  = t + 128 * i;
            int row  = idx >> 4;
            int chnk = idx & 15;
            size_t g = (size_t)(b * S + q0 + row) * D + h * DH + chnk * 8;
            uint32_t so = row * AT_LDB + chnk * 16;
            cp_async16(Qh + so, g_qh + g);
            cp_async16(Ql + so, g_ql + g);
        }
        CP_COMMIT();
        CP_WAIT0();
        __syncthreads();
    }
    uint32_t qh[8][4], qlr[8][4];
    #pragma unroll
    for (int kt = 0; kt < 8; kt++) {
        uint32_t ad = Qh + (wq + arow) * AT_LDB + kt * 32 + akoff;
        ldsm_x4(qh[kt], ad);
        ldsm_x4(qlr[kt], ad + AT_TILE);
    }

    float o[16][4];
    #pragma unroll
    for (int i = 0; i < 16; i++)
        #pragma unroll
        for (int r = 0; r < 4; r++) o[i][r] = 0.f;
    float m0 = -1e30f, m1 = -1e30f, l0 = 0.f, l1 = 0.f;

    const int r0g = q0 + wq + (lane >> 2);
    const int r1g = r0g + 8;

    for (int jb = 0; jb <= iq; jb++) {
        const int k0 = jb * 64;
        __syncthreads();                 // prev K/V reads done (and Q regs on jb=0)
        // Load K/V tiles (hi/lo)
        #pragma unroll
        for (int i = 0; i < 8; i++) {
            int idx  = t + 128 * i;
            int row  = idx >> 4;
            int chnk = idx & 15;
            size_t g = (size_t)(b * S + k0 + row) * D + h * DH + chnk * 8;
            uint32_t so = row * AT_LDB + chnk * 16;
            cp_async16(Kh + so, g_kh + g);
            cp_async16(Kl + so, g_kl + g);
            cp_async16(Vh + so, g_vh + g);
            cp_async16(Vl + so, g_vl + g);
        }
        CP_COMMIT();
        CP_WAIT0();
        __syncthreads();

        // ---- S = Q K^T (3-pass split) ----
        float c[8][4];
        #pragma unroll
        for (int j = 0; j < 8; j++)
            #pragma unroll
            for (int r = 0; r < 4; r++) c[j][r] = 0.f;

        #pragma unroll
        for (int kt = 0; kt < 8; kt++) {
            #pragma unroll
            for (int nb = 0; nb < 4; nb++) {
                uint32_t kh4[4], kl4[4];
                uint32_t bd = Kh + (nb * 16 + bn) * AT_LDB + kt * 32 + bkoff;
                ldsm_x4(kh4, bd);
                ldsm_x4(kl4, bd + AT_TILE);
                #pragma unroll
                for (int half = 0; half < 2; half++) {
                    int nf = nb * 2 + half;
                    mma16816(c[nf], qh[kt],  &kh4[half * 2]);
                    mma16816(c[nf], qh[kt],  &kl4[half * 2]);
                    mma16816(c[nf], qlr[kt], &kh4[half * 2]);
                }
            }
        }

        // ---- scale + causal mask ----
        const bool diag = (jb == iq);
        #pragma unroll
        for (int j = 0; j < 8; j++) {
            int cc = k0 + j * 8 + (lane & 3) * 2;
            #pragma unroll
            for (int r = 0; r < 4; r++) {
                float v = c[j][r] * SCALE_LOG2E;
                if (diag) {
                    int col = cc + (r & 1);
                    int row = (r < 2) ? r0g : r1g;
                    if (col > row) v = -1e30f;
                }
                c[j][r] = v;
            }
        }

        // ---- online softmax (log2 domain) ----
        float mx0 = -1e30f, mx1 = -1e30f;
        #pragma unroll
        for (int j = 0; j < 8; j++) {
            mx0 = fmaxf(mx0, fmaxf(c[j][0], c[j][1]));
            mx1 = fmaxf(mx1, fmaxf(c[j][2], c[j][3]));
        }
        mx0 = fmaxf(mx0, __shfl_xor_sync(0xffffffffu, mx0, 1));
        mx0 = fmaxf(mx0, __shfl_xor_sync(0xffffffffu, mx0, 2));
        mx1 = fmaxf(mx1, __shfl_xor_sync(0xffffffffu, mx1, 1));
        mx1 = fmaxf(mx1, __shfl_xor_sync(0xffffffffu, mx1, 2));
        float mn0 = fmaxf(m0, mx0), mn1 = fmaxf(m1, mx1);
        float sc0 = exp2_fast(m0 - mn0), sc1 = exp2_fast(m1 - mn1);
        m0 = mn0; m1 = mn1;

        float ls0 = 0.f, ls1 = 0.f;
        #pragma unroll
        for (int j = 0; j < 8; j++) {
            c[j][0] = exp2_fast(c[j][0] - mn0);
            c[j][1] = exp2_fast(c[j][1] - mn0);
            c[j][2] = exp2_fast(c[j][2] - mn1);
            c[j][3] = exp2_fast(c[j][3] - mn1);
            ls0 += c[j][0] + c[j][1];
            ls1 += c[j][2] + c[j][3];
        }
        ls0 += __shfl_xor_sync(0xffffffffu, ls0, 1);
        ls0 += __shfl_xor_sync(0xffffffffu, ls0, 2);
        ls1 += __shfl_xor_sync(0xffffffffu, ls1, 1);
        ls1 += __shfl_xor_sync(0xffffffffu, ls1, 2);
        l0 = l0 * sc0 + ls0;
        l1 = l1 * sc1 + ls1;

        // rescale O
        #pragma unroll
        for (int nf = 0; nf < 16; nf++) {
            o[nf][0] *= sc0; o[nf][1] *= sc0;
            o[nf][2] *= sc1; o[nf][3] *= sc1;
        }

        // ---- pack P to hi/lo A-fragments ----
        uint32_t pah[4][4], pal[4][4];
        #pragma unroll
        for (int g = 0; g < 4; g++) {
            #pragma unroll
            for (int q = 0; q < 4; q++) {
                int j = 2 * g + (q >> 1);
                int e = (q & 1) * 2;
                float p0v = c[j][e], p1v = c[j][e + 1];
                uint32_t hp = pack_bf16(p0v, p1v);
                float h0 = __uint_as_float(hp << 16);
                float h1 = __uint_as_float(hp & 0xffff0000u);
                pah[g][q] = hp;
                pal[g][q] = pack_bf16(p0v - h0, p1v - h1);
            }
        }

        // ---- O += P V (3-pass split), V via ldmatrix.trans ----
        #pragma unroll
        for (int g = 0; g < 4; g++) {
            #pragma unroll
            for (int vb = 0; vb < 8; vb++) {
                uint32_t vh4[4], vl4[4];
                uint32_t vd = Vh + (g * 16 + vrow) * AT_LDB + (vb * 16 + vcol) * 2;
                ldsm_x4_t(vh4, vd);
                ldsm_x4_t(vl4, vd + AT_TILE);
                #pragma unroll
                for (int half = 0; half < 2; half++) {
                    int nf = vb * 2 + half;
                    mma16816(o[nf], pah[g], &vh4[half * 2]);
                    mma16816(o[nf], pah[g], &vl4[half * 2]);
                    mma16816(o[nf], pal[g], &vh4[half * 2]);
                }
            }
        }
    }

    // ---- finalize: O/l, write ctx as bf16 hi/lo ----
    const float inv0 = 1.f / l0, inv1 = 1.f / l1;
    const int colb = h * DH + (lane & 3) * 2;
    #pragma unroll
    for (int nf = 0; nf < 16; nf++) {
        int col = colb + nf * 8;
        float v0 = o[nf][0] * inv0, v1 = o[nf][1] * inv0;
        float v2 = o[nf][2] * inv1, v3 = o[nf][3] * inv1;
        uint32_t h01 = pack_bf16(v0, v1);
        float h0 = __uint_as_float(h01 << 16);
        float h1 = __uint_as_float(h01 & 0xffff0000u);
        uint32_t l01 = pack_bf16(v0 - h0, v1 - h1);
        uint32_t h23 = pack_bf16(v2, v3);
        float h2 = __uint_as_float(h23 << 16);
        float h3 = __uint_as_float(h23 & 0xffff0000u);
        uint32_t l23 = pack_bf16(v2 - h2, v3 - h3);
        size_t g0 = (size_t)(b * S + r0g) * D + col;
        size_t g1 = (size_t)(b * S + r1g) * D + col;
        *(uint32_t*)(g_c_h + g0) = h01;
        *(uint32_t*)(g_c_l + g0) = l01;
        *(uint32_t*)(g_c_h + g1) = h23;
        *(uint32_t*)(g_c_l + g1) = l23;
    }
}

// ---------------------------------------------------------------------------
extern "C" void kernel_launch(void* const* d_in, const int* in_sizes, int n_in,
                              void* d_out, int out_size)
{
    const float* X  = (const float*)d_in[0];
    const float* Wq = (const float*)d_in[1];
    const float* bq = (const float*)d_in[2];
    const float* Wk = (const float*)d_in[3];
    const float* bk = (const float*)d_in[4];
    const float* Wv = (const float*)d_in[5];
    const float* bv = (const float*)d_in[6];
    const float* Wo = (const float*)d_in[7];
    const float* bo = (const float*)d_in[8];
    float* out = (float*)d_out;

    cudaFuncSetAttribute(attn_tc_kernel, cudaFuncAttributeMaxDynamicSharedMemorySize, ATTN_SMEM);
    cudaFuncSetAttribute(qkv_tc_gemm, cudaFuncAttributeMaxDynamicSharedMemorySize, GEMM_SMEM);
    cudaFuncSetAttribute(out_tc_gemm, cudaFuncAttributeMaxDynamicSharedMemorySize, GEMM_SMEM);

    split_x_kernel<<<(M * D / 4) / 256, 256>>>((const float4*)X);
    wsplit_kernel<<<dim3(D / 32, D / 32, 4), 256>>>(Wq, Wk, Wv, Wo);
    qkv_tc_gemm<<<dim3(D / 128, M / 128, 3), 128, GEMM_SMEM>>>(bq, bk, bv);
    attn_tc_kernel<<<dim3(S / 64, B * H), 128, ATTN_SMEM>>>();
    out_tc_gemm<<<dim3(D / 128, M / 128), 128, GEMM_SMEM>>>(bo, out);
}

// round 6
// speedup vs baseline: 3.7279x; 1.0380x over previous
#include <cuda_runtime.h>
#include <cuda_bf16.h>
#include <math.h>
#include <cstdint>

// Problem constants
constexpr int B  = 4;
constexpr int S  = 2048;
constexpr int D  = 2048;
constexpr int H  = 16;
constexpr int DH = 128;
constexpr int M  = B * S;          // 8192 rows

// ---------------------------------------------------------------------------
// Scratch (allocation-free rule: device globals). All bf16 hi/lo split pairs.
// ---------------------------------------------------------------------------
__device__ __nv_bfloat16 g_x_h[(size_t)M * D];
__device__ __nv_bfloat16 g_x_l[(size_t)M * D];
__device__ __nv_bfloat16 g_qh[(size_t)M * D];
__device__ __nv_bfloat16 g_ql[(size_t)M * D];
__device__ __nv_bfloat16 g_kh[(size_t)M * D];
__device__ __nv_bfloat16 g_kl[(size_t)M * D];
__device__ __nv_bfloat16 g_vh[(size_t)M * D];
__device__ __nv_bfloat16 g_vl[(size_t)M * D];
__device__ __nv_bfloat16 g_c_h[(size_t)M * D];
__device__ __nv_bfloat16 g_c_l[(size_t)M * D];
__device__ __nv_bfloat16 g_wT_h[(size_t)4 * D * D];   // [w][N][K]
__device__ __nv_bfloat16 g_wT_l[(size_t)4 * D * D];

// ---------------------------------------------------------------------------
// PTX helpers (sm_103 baseline: mma.sync + ldmatrix + cp.async only)
// ---------------------------------------------------------------------------
__device__ __forceinline__ uint32_t smem_u32(const void* p) {
    uint32_t a;
    asm("{ .reg .u64 t; cvta.to.shared.u64 t, %1; cvt.u32.u64 %0, t; }" : "=r"(a) : "l"(p));
    return a;
}

__device__ __forceinline__ void cp_async16(uint32_t dst, const void* src) {
    asm volatile("cp.async.cg.shared.global [%0], [%1], 16;" :: "r"(dst), "l"(src));
}
#define CP_COMMIT() asm volatile("cp.async.commit_group;" ::: "memory")
#define CP_WAIT0()  asm volatile("cp.async.wait_group 0;" ::: "memory")
#define CP_WAIT1()  asm volatile("cp.async.wait_group 1;" ::: "memory")

__device__ __forceinline__ void ldsm_x4(uint32_t* r, uint32_t addr) {
    asm volatile("ldmatrix.sync.aligned.m8n8.x4.shared.b16 {%0,%1,%2,%3}, [%4];"
        : "=r"(r[0]), "=r"(r[1]), "=r"(r[2]), "=r"(r[3]) : "r"(addr));
}
__device__ __forceinline__ void ldsm_x4_t(uint32_t* r, uint32_t addr) {
    asm volatile("ldmatrix.sync.aligned.m8n8.x4.trans.shared.b16 {%0,%1,%2,%3}, [%4];"
        : "=r"(r[0]), "=r"(r[1]), "=r"(r[2]), "=r"(r[3]) : "r"(addr));
}

__device__ __forceinline__ void mma16816(float* c, const uint32_t* a, const uint32_t* b) {
    asm volatile("mma.sync.aligned.m16n8k16.row.col.f32.bf16.bf16.f32 "
        "{%0,%1,%2,%3}, {%4,%5,%6,%7}, {%8,%9}, {%0,%1,%2,%3};"
        : "+f"(c[0]), "+f"(c[1]), "+f"(c[2]), "+f"(c[3])
        : "r"(a[0]), "r"(a[1]), "r"(a[2]), "r"(a[3]), "r"(b[0]), "r"(b[1]));
}

// pack(lo, hi): lo -> bits[15:0], hi -> bits[31:16]
__device__ __forceinline__ uint32_t pack_bf16(float lo, float hi) {
    uint32_t d;
    asm("cvt.rn.bf16x2.f32 %0, %1, %2;" : "=r"(d) : "f"(hi), "f"(lo));
    return d;
}

// fast 2^z for z <= 0 (quartic Taylor after rint reduction, err ~4e-5)
__device__ __forceinline__ float exp2_fast(float z) {
    z = fmaxf(z, -126.f);
    float fi = rintf(z);
    float f  = z - fi;
    float p  = 0.00961813f;
    p = fmaf(p, f, 0.0555041f);
    p = fmaf(p, f, 0.2402265f);
    p = fmaf(p, f, 0.6931472f);
    p = fmaf(p, f, 1.0f);
    int e = (int)fi;
    return p * __int_as_float((uint32_t)(e + 127) << 23);
}

// ---------------------------------------------------------------------------
// Split / transpose conversion kernels
// ---------------------------------------------------------------------------
__global__ __launch_bounds__(256) void split_x_kernel(const float4* __restrict__ in) {
    size_t i = (size_t)blockIdx.x * blockDim.x + threadIdx.x;
    float4 v = in[i];
    float f[4] = {v.x, v.y, v.z, v.w};
    __nv_bfloat16 h[4], l[4];
    #pragma unroll
    for (int j = 0; j < 4; j++) {
        h[j] = __float2bfloat16(f[j]);
        l[j] = __float2bfloat16(f[j] - __bfloat162float(h[j]));
    }
    *(uint2*)(g_x_h + i * 4) = *(const uint2*)h;
    *(uint2*)(g_x_l + i * 4) = *(const uint2*)l;
}

// Weights: W [K][N] fp32 -> transposed split bf16 [N][K]
__global__ __launch_bounds__(256) void wsplit_kernel(const float* __restrict__ Wq,
                                                     const float* __restrict__ Wk,
                                                     const float* __restrict__ Wv,
                                                     const float* __restrict__ Wo) {
    __shared__ float tile[32][33];
    int z = blockIdx.z;
    const float* W = (z == 0) ? Wq : (z == 1) ? Wk : (z == 2) ? Wv : Wo;
    __nv_bfloat16* oh = g_wT_h + (size_t)z * D * D;
    __nv_bfloat16* ol = g_wT_l + (size_t)z * D * D;
    int n0 = blockIdx.x * 32, k0 = blockIdx.y * 32;
    int tx = threadIdx.x & 31, ty = threadIdx.x >> 5;
    #pragma unroll
    for (int i = 0; i < 4; i++) {
        int k = ty + i * 8;
        tile[k][tx] = W[(size_t)(k0 + k) * D + n0 + tx];
    }
    __syncthreads();
    #pragma unroll
    for (int i = 0; i < 4; i++) {
        int n = ty + i * 8;
        float v = tile[tx][n];
        __nv_bfloat16 h = __float2bfloat16(v);
        __nv_bfloat16 l = __float2bfloat16(v - __bfloat162float(h));
        oh[(size_t)(n0 + n) * D + k0 + tx] = h;
        ol[(size_t)(n0 + n) * D + k0 + tx] = l;
    }
}

// ---------------------------------------------------------------------------
// mma.sync split-bf16 GEMM: C[128x128 tile] = A(hi+lo) @ B(hi+lo)^T + bias
// 4 warps (2x2), warp tile 64x64, BK=32, double-buffered cp.async, 128 thr.
// ---------------------------------------------------------------------------
constexpr int BKG      = 32;
constexpr int LDT      = 40;                 // bf16 stride per tile row (80 B)
constexpr int TILE_BY  = 128 * LDT * 2;      // 10240 B per tile
constexpr int STAGE_BY = 4 * TILE_BY;        // Ah, Al, Bh, Bl = 40960 B
constexpr int GEMM_SMEM = 2 * STAGE_BY;      // 81920 B
constexpr int NITER    = D / BKG;            // 64

__device__ __forceinline__ void load_stage(uint32_t sbase,
                                           const __nv_bfloat16* Ah,
                                           const __nv_bfloat16* Al,
                                           const __nv_bfloat16* Bh,
                                           const __nv_bfloat16* Bl,
                                           int k0, int t) {
    const __nv_bfloat16* bases[4] = {Ah, Al, Bh, Bl};
    #pragma unroll
    for (int i = 0; i < 16; i++) {
        const int tile = i >> 2;              // 4 slots per tile per thread
        int idx  = t + 128 * (i & 3);         // 0..511
        int row  = idx >> 2;                  // 0..127
        int chnk = idx & 3;                   // 16B chunk
        const __nv_bfloat16* src = bases[tile] + (size_t)row * D + k0 + chnk * 8;
        uint32_t dst = sbase + tile * TILE_BY + row * (LDT * 2) + chnk * 16;
        cp_async16(dst, src);
    }
    CP_COMMIT();
}

template <int SPLIT_OUT>
__device__ __forceinline__ void tc_gemm_body(const __nv_bfloat16* __restrict__ Ahp,
                                             const __nv_bfloat16* __restrict__ Alp,
                                             const __nv_bfloat16* __restrict__ Bhp,
                                             const __nv_bfloat16* __restrict__ Blp,
                                             const float* __restrict__ bias,
                                             float* __restrict__ C,
                                             __nv_bfloat16* __restrict__ Ch,
                                             __nv_bfloat16* __restrict__ Cl) {
    extern __shared__ char smem[];
    const uint32_t sb = smem_u32(smem);
    const int t    = threadIdx.x;
    const int lane = t & 31;
    const int w    = t >> 5;
    const int wm   = (w & 1) * 64;
    const int wn   = (w >> 1) * 64;
    const int m0   = blockIdx.y * 128;
    const int n0   = blockIdx.x * 128;

    const __nv_bfloat16* Arow  = Ahp + (size_t)m0 * D;
    const __nv_bfloat16* AlRow = Alp + (size_t)m0 * D;
    const __nv_bfloat16* Brow  = Bhp + (size_t)n0 * D;
    const __nv_bfloat16* BlRow = Blp + (size_t)n0 * D;

    float acc[4][8][4];
    #pragma unroll
    for (int i = 0; i < 4; i++)
        #pragma unroll
        for (int j = 0; j < 8; j++)
            #pragma unroll
            for (int r = 0; r < 4; r++) acc[i][j][r] = 0.f;

    const int arow  = lane & 15;
    const int akoff = (lane >> 4) * 16;
    const int bn    = (lane & 7) + ((lane >> 4) << 3);
    const int bkoff = ((lane >> 3) & 1) * 16;

    load_stage(sb, Arow, AlRow, Brow, BlRow, 0, t);

    for (int c = 0; c < NITER; c++) {
        if (c + 1 < NITER) {
            load_stage(sb + ((c + 1) & 1) * STAGE_BY, Arow, AlRow, Brow, BlRow,
                       (c + 1) * BKG, t);
            CP_WAIT1();
        } else {
            CP_WAIT0();
        }
        __syncthreads();                       // stage c visible to all

        const uint32_t sbase = sb + (c & 1) * STAGE_BY;
        #pragma unroll
        for (int kk = 0; kk < 2; kk++) {
            const uint32_t kbyte = kk * 32;
            uint32_t ah[4][4], al[4][4];
            #pragma unroll
            for (int mf = 0; mf < 4; mf++) {
                uint32_t ad = sbase + (wm + mf * 16 + arow) * (LDT * 2) + kbyte + akoff;
                ldsm_x4(ah[mf], ad);
                ldsm_x4(al[mf], ad + TILE_BY);
            }
            #pragma unroll
            for (int nb = 0; nb < 4; nb++) {
                uint32_t bh4[4], bl4[4];
                uint32_t bd = sbase + 2 * TILE_BY + (wn + nb * 16 + bn) * (LDT * 2) + kbyte + bkoff;
                ldsm_x4(bh4, bd);
                ldsm_x4(bl4, bd + TILE_BY);
                #pragma unroll
                for (int mf = 0; mf < 4; mf++)
                    #pragma unroll
                    for (int half = 0; half < 2; half++) {
                        int nf = nb * 2 + half;
                        mma16816(acc[mf][nf], ah[mf], &bh4[half * 2]);
                        mma16816(acc[mf][nf], ah[mf], &bl4[half * 2]);
                        mma16816(acc[mf][nf], al[mf], &bh4[half * 2]);
                    }
            }
        }
        __syncthreads();                       // done reading stage c
    }

    // Epilogue
    const int rbase = m0 + wm + (lane >> 2);
    const int cbase = n0 + wn + (lane & 3) * 2;
    #pragma unroll
    for (int mf = 0; mf < 4; mf++) {
        #pragma unroll
        for (int nf = 0; nf < 8; nf++) {
            int col = cbase + nf * 8;
            float2 bv = *(const float2*)(bias + col);
            int r0 = rbase + mf * 16;
            float v0 = acc[mf][nf][0] + bv.x, v1 = acc[mf][nf][1] + bv.y;
            float v2 = acc[mf][nf][2] + bv.x, v3 = acc[mf][nf][3] + bv.y;
            if (SPLIT_OUT) {
                uint32_t h01 = pack_bf16(v0, v1);
                float h0 = __uint_as_float(h01 << 16);
                float h1 = __uint_as_float(h01 & 0xffff0000u);
                uint32_t l01 = pack_bf16(v0 - h0, v1 - h1);
                uint32_t h23 = pack_bf16(v2, v3);
                float h2 = __uint_as_float(h23 << 16);
                float h3 = __uint_as_float(h23 & 0xffff0000u);
                uint32_t l23 = pack_bf16(v2 - h2, v3 - h3);
                *(uint32_t*)(Ch + (size_t)r0 * D + col)       = h01;
                *(uint32_t*)(Cl + (size_t)r0 * D + col)       = l01;
                *(uint32_t*)(Ch + (size_t)(r0 + 8) * D + col) = h23;
                *(uint32_t*)(Cl + (size_t)(r0 + 8) * D + col) = l23;
            } else {
                float2 o0 = {v0, v1}, o1 = {v2, v3};
                *(float2*)(C + (size_t)r0 * D + col)       = o0;
                *(float2*)(C + (size_t)(r0 + 8) * D + col) = o1;
            }
        }
    }
}

__global__ __launch_bounds__(128, 2) void qkv_tc_gemm(const float* __restrict__ bq,
                                                      const float* __restrict__ bk,
                                                      const float* __restrict__ bv) {
    const int z = blockIdx.z;
    const __nv_bfloat16* Bh = g_wT_h + (size_t)z * D * D;
    const __nv_bfloat16* Bl = g_wT_l + (size_t)z * D * D;
    const float* bias = (z == 0) ? bq : (z == 1) ? bk : bv;
    __nv_bfloat16* Ch = (z == 0) ? g_qh : (z == 1) ? g_kh : g_vh;
    __nv_bfloat16* Cl = (z == 0) ? g_ql : (z == 1) ? g_kl : g_vl;
    tc_gemm_body<1>(g_x_h, g_x_l, Bh, Bl, bias, nullptr, Ch, Cl);
}

__global__ __launch_bounds__(128, 2) void out_tc_gemm(const float* __restrict__ bo,
                                                      float* __restrict__ out) {
    tc_gemm_body<0>(g_c_h, g_c_l, g_wT_h + (size_t)3 * D * D, g_wT_l + (size_t)3 * D * D,
                    bo, out, nullptr, nullptr);
}

// ---------------------------------------------------------------------------
// Tensor-core flash attention (split-bf16, causal). Br=Bc=64, 128 threads.
// Q hi held in registers (Q lo re-read from smem); 2 CTAs/SM target.
// ---------------------------------------------------------------------------
constexpr int AT_LDB   = 272;                    // bytes per tile row (136 bf16)
constexpr int AT_TILE  = 64 * AT_LDB;            // 17408 B
constexpr int ATTN_SMEM = 6 * AT_TILE;           // 104448 B
constexpr float SCALE_LOG2E = 0.12751650f;       // (1/sqrt(128)) * log2(e)

__global__ __launch_bounds__(128, 2) void attn_tc_kernel() {
    extern __shared__ char sm8[];
    const uint32_t sb = smem_u32(sm8);
    const uint32_t Qh = sb,               Ql = sb + AT_TILE;
    const uint32_t Kh = sb + 2 * AT_TILE, Kl = sb + 3 * AT_TILE;
    const uint32_t Vh = sb + 4 * AT_TILE, Vl = sb + 5 * AT_TILE;

    const int t    = threadIdx.x;
    const int lane = t & 31;
    const int w    = t >> 5;
    const int iq   = (gridDim.x - 1) - blockIdx.x;      // big blocks first
    const int bh   = blockIdx.y;
    const int b    = bh >> 4;
    const int h    = bh & 15;
    const int q0   = iq * 64;
    const int wq   = w * 16;

    // ldmatrix lane offsets
    const int arow  = lane & 15;
    const int akoff = (lane >> 4) * 16;
    const int bn    = (lane & 7) + ((lane >> 4) << 3);
    const int bkoff = ((lane >> 3) & 1) * 16;
    const int vrow  = lane & 15;
    const int vcol  = (lane >> 4) << 3;

    // ---- Load Q tile to smem, hoist Q-hi to registers ----
    {
        #pragma unroll
        for (int i = 0; i < 8; i++) {
            int idx  = t + 128 * i;
            int row  = idx >> 4;
            int chnk = idx & 15;
            size_t g = (size_t)(b * S + q0 + row) * D + h * DH + chnk * 8;
            uint32_t so = row * AT_LDB + chnk * 16;
            cp_async16(Qh + so, g_qh + g);
            cp_async16(Ql + so, g_ql + g);
        }
        CP_COMMIT();
        CP_WAIT0();
        __syncthreads();
    }
    uint32_t qh[8][4];
    #pragma unroll
    for (int kt = 0; kt < 8; kt++) {
        uint32_t ad = Qh + (wq + arow) * AT_LDB + kt * 32 + akoff;
        ldsm_x4(qh[kt], ad);
    }

    float o[16][4];
    #pragma unroll
    for (int i = 0; i < 16; i++)
        #pragma unroll
        for (int r = 0; r < 4; r++) o[i][r] = 0.f;
    float m0 = -1e30f, m1 = -1e30f, l0 = 0.f, l1 = 0.f;

    const int r0g = q0 + wq + (lane >> 2);
    const int r1g = r0g + 8;

    for (int jb = 0; jb <= iq; jb++) {
        const int k0 = jb * 64;
        __syncthreads();                 // prev K/V reads done (and Q regs on jb=0)
        // Load K/V tiles (hi/lo)
        #pragma unroll
        for (int i = 0; i < 8; i++) {
            int idx  = t + 128 * i;
            int row  = idx >> 4;
            int chnk = idx & 15;
            size_t g = (size_t)(b * S + k0 + row) * D + h * DH + chnk * 8;
            uint32_t so = row * AT_LDB + chnk * 16;
            cp_async16(Kh + so, g_kh + g);
            cp_async16(Kl + so, g_kl + g);
            cp_async16(Vh + so, g_vh + g);
            cp_async16(Vl + so, g_vl + g);
        }
        CP_COMMIT();
        CP_WAIT0();
        __syncthreads();

        // ---- S = Q K^T (3-pass split) ----
        float c[8][4];
        #pragma unroll
        for (int j = 0; j < 8; j++)
            #pragma unroll
            for (int r = 0; r < 4; r++) c[j][r] = 0.f;

        #pragma unroll
        for (int kt = 0; kt < 8; kt++) {
            uint32_t ql4[4];
            ldsm_x4(ql4, Ql + (wq + arow) * AT_LDB + kt * 32 + akoff);
            #pragma unroll
            for (int nb = 0; nb < 4; nb++) {
                uint32_t kh4[4], kl4[4];
                uint32_t bd = Kh + (nb * 16 + bn) * AT_LDB + kt * 32 + bkoff;
                ldsm_x4(kh4, bd);
                ldsm_x4(kl4, bd + AT_TILE);
                #pragma unroll
                for (int half = 0; half < 2; half++) {
                    int nf = nb * 2 + half;
                    mma16816(c[nf], qh[kt], &kh4[half * 2]);
                    mma16816(c[nf], qh[kt], &kl4[half * 2]);
                    mma16816(c[nf], ql4,    &kh4[half * 2]);
                }
            }
        }

        // ---- scale + causal mask ----
        const bool diag = (jb == iq);
        #pragma unroll
        for (int j = 0; j < 8; j++) {
            int cc = k0 + j * 8 + (lane & 3) * 2;
            #pragma unroll
            for (int r = 0; r < 4; r++) {
                float v = c[j][r] * SCALE_LOG2E;
                if (diag) {
                    int col = cc + (r & 1);
                    int row = (r < 2) ? r0g : r1g;
                    if (col > row) v = -1e30f;
                }
                c[j][r] = v;
            }
        }

        // ---- online softmax (log2 domain) ----
        float mx0 = -1e30f, mx1 = -1e30f;
        #pragma unroll
        for (int j = 0; j < 8; j++) {
            mx0 = fmaxf(mx0, fmaxf(c[j][0], c[j][1]));
            mx1 = fmaxf(mx1, fmaxf(c[j][2], c[j][3]));
        }
        mx0 = fmaxf(mx0, __shfl_xor_sync(0xffffffffu, mx0, 1));
        mx0 = fmaxf(mx0, __shfl_xor_sync(0xffffffffu, mx0, 2));
        mx1 = fmaxf(mx1, __shfl_xor_sync(0xffffffffu, mx1, 1));
        mx1 = fmaxf(mx1, __shfl_xor_sync(0xffffffffu, mx1, 2));
        float mn0 = fmaxf(m0, mx0), mn1 = fmaxf(m1, mx1);
        float sc0 = exp2_fast(m0 - mn0), sc1 = exp2_fast(m1 - mn1);
        m0 = mn0; m1 = mn1;

        float ls0 = 0.f, ls1 = 0.f;
        #pragma unroll
        for (int j = 0; j < 8; j++) {
            c[j][0] = exp2_fast(c[j][0] - mn0);
            c[j][1] = exp2_fast(c[j][1] - mn0);
            c[j][2] = exp2_fast(c[j][2] - mn1);
            c[j][3] = exp2_fast(c[j][3] - mn1);
            ls0 += c[j][0] + c[j][1];
            ls1 += c[j][2] + c[j][3];
        }
        ls0 += __shfl_xor_sync(0xffffffffu, ls0, 1);
        ls0 += __shfl_xor_sync(0xffffffffu, ls0, 2);
        ls1 += __shfl_xor_sync(0xffffffffu, ls1, 1);
        ls1 += __shfl_xor_sync(0xffffffffu, ls1, 2);
        l0 = l0 * sc0 + ls0;
        l1 = l1 * sc1 + ls1;

        // rescale O
        #pragma unroll
        for (int nf = 0; nf < 16; nf++) {
            o[nf][0] *= sc0; o[nf][1] *= sc0;
            o[nf][2] *= sc1; o[nf][3] *= sc1;
        }

        // ---- pack P to hi/lo A-fragments ----
        uint32_t pah[4][4], pal[4][4];
        #pragma unroll
        for (int g = 0; g < 4; g++) {
            #pragma unroll
            for (int q = 0; q < 4; q++) {
                int j = 2 * g + (q >> 1);
                int e = (q & 1) * 2;
                float p0v = c[j][e], p1v = c[j][e + 1];
                uint32_t hp = pack_bf16(p0v, p1v);
                float h0 = __uint_as_float(hp << 16);
                float h1 = __uint_as_float(hp & 0xffff0000u);
                pah[g][q] = hp;
                pal[g][q] = pack_bf16(p0v - h0, p1v - h1);
            }
        }

        // ---- O += P V (3-pass split), V via ldmatrix.trans ----
        #pragma unroll
        for (int g = 0; g < 4; g++) {
            #pragma unroll
            for (int vb = 0; vb < 8; vb++) {
                uint32_t vh4[4], vl4[4];
                uint32_t vd = Vh + (g * 16 + vrow) * AT_LDB + (vb * 16 + vcol) * 2;
                ldsm_x4_t(vh4, vd);
                ldsm_x4_t(vl4, vd + AT_TILE);
                #pragma unroll
                for (int half = 0; half < 2; half++) {
                    int nf = vb * 2 + half;
                    mma16816(o[nf], pah[g], &vh4[half * 2]);
                    mma16816(o[nf], pah[g], &vl4[half * 2]);
                    mma16816(o[nf], pal[g], &vh4[half * 2]);
                }
            }
        }
    }

    // ---- finalize: O/l, write ctx as bf16 hi/lo ----
    const float inv0 = 1.f / l0, inv1 = 1.f / l1;
    const int colb = h * DH + (lane & 3) * 2;
    #pragma unroll
    for (int nf = 0; nf < 16; nf++) {
        int col = colb + nf * 8;
        float v0 = o[nf][0] * inv0, v1 = o[nf][1] * inv0;
        float v2 = o[nf][2] * inv1, v3 = o[nf][3] * inv1;
        uint32_t h01 = pack_bf16(v0, v1);
        float h0 = __uint_as_float(h01 << 16);
        float h1 = __uint_as_float(h01 & 0xffff0000u);
        uint32_t l01 = pack_bf16(v0 - h0, v1 - h1);
        uint32_t h23 = pack_bf16(v2, v3);
        float h2 = __uint_as_float(h23 << 16);
        float h3 = __uint_as_float(h23 & 0xffff0000u);
        uint32_t l23 = pack_bf16(v2 - h2, v3 - h3);
        size_t g0 = (size_t)(b * S + r0g) * D + col;
        size_t g1 = (size_t)(b * S + r1g) * D + col;
        *(uint32_t*)(g_c_h + g0) = h01;
        *(uint32_t*)(g_c_l + g0) = l01;
        *(uint32_t*)(g_c_h + g1) = h23;
        *(uint32_t*)(g_c_l + g1) = l23;
    }
}

// ---------------------------------------------------------------------------
extern "C" void kernel_launch(void* const* d_in, const int* in_sizes, int n_in,
                              void* d_out, int out_size)
{
    const float* X  = (const float*)d_in[0];
    const float* Wq = (const float*)d_in[1];
    const float* bq = (const float*)d_in[2];
    const float* Wk = (const float*)d_in[3];
    const float* bk = (const float*)d_in[4];
    const float* Wv = (const float*)d_in[5];
    const float* bv = (const float*)d_in[6];
    const float* Wo = (const float*)d_in[7];
    const float* bo = (const float*)d_in[8];
    float* out = (float*)d_out;

    cudaFuncSetAttribute(attn_tc_kernel, cudaFuncAttributeMaxDynamicSharedMemorySize, ATTN_SMEM);
    cudaFuncSetAttribute(qkv_tc_gemm, cudaFuncAttributeMaxDynamicSharedMemorySize, GEMM_SMEM);
    cudaFuncSetAttribute(out_tc_gemm, cudaFuncAttributeMaxDynamicSharedMemorySize, GEMM_SMEM);

    split_x_kernel<<<(M * D / 4) / 256, 256>>>((const float4*)X);
    wsplit_kernel<<<dim3(D / 32, D / 32, 4), 256>>>(Wq, Wk, Wv, Wo);
    qkv_tc_gemm<<<dim3(D / 128, M / 128, 3), 128, GEMM_SMEM>>>(bq, bk, bv);
    attn_tc_kernel<<<dim3(S / 64, B * H), 128, ATTN_SMEM>>>();
    out_tc_gemm<<<dim3(D / 128, M / 128), 128, GEMM_SMEM>>>(bo, out);
}

// round 7
// speedup vs baseline: 3.9591x; 1.0620x over previous
#include <cuda_runtime.h>
#include <cuda_bf16.h>
#include <cuda_fp16.h>
#include <math.h>
#include <cstdint>

// Problem constants
constexpr int B  = 4;
constexpr int S  = 2048;
constexpr int D  = 2048;
constexpr int H  = 16;
constexpr int DH = 128;
constexpr int M  = B * S;          // 8192 rows

// ---------------------------------------------------------------------------
// Scratch (allocation-free rule: device globals).
// ---------------------------------------------------------------------------
__device__ __nv_bfloat16 g_x_h[(size_t)M * D];
__device__ __nv_bfloat16 g_x_l[(size_t)M * D];
__device__ __half        g_q16h[(size_t)M * D];
__device__ __half        g_q16l[(size_t)M * D];
__device__ __half        g_k16[(size_t)M * D];
__device__ __half        g_v16[(size_t)M * D];
__device__ __nv_bfloat16 g_c_h[(size_t)M * D];
__device__ __nv_bfloat16 g_c_l[(size_t)M * D];
__device__ __nv_bfloat16 g_wT_h[(size_t)4 * D * D];   // [w][N][K]
__device__ __nv_bfloat16 g_wT_l[(size_t)4 * D * D];

// ---------------------------------------------------------------------------
// PTX helpers (sm_103 baseline: mma.sync + ldmatrix + cp.async only)
// ---------------------------------------------------------------------------
__device__ __forceinline__ uint32_t smem_u32(const void* p) {
    uint32_t a;
    asm("{ .reg .u64 t; cvta.to.shared.u64 t, %1; cvt.u32.u64 %0, t; }" : "=r"(a) : "l"(p));
    return a;
}

__device__ __forceinline__ void cp_async16(uint32_t dst, const void* src) {
    asm volatile("cp.async.cg.shared.global [%0], [%1], 16;" :: "r"(dst), "l"(src));
}
#define CP_COMMIT() asm volatile("cp.async.commit_group;" ::: "memory")
#define CP_WAIT0()  asm volatile("cp.async.wait_group 0;" ::: "memory")
#define CP_WAIT1()  asm volatile("cp.async.wait_group 1;" ::: "memory")

__device__ __forceinline__ void ldsm_x4(uint32_t* r, uint32_t addr) {
    asm volatile("ldmatrix.sync.aligned.m8n8.x4.shared.b16 {%0,%1,%2,%3}, [%4];"
        : "=r"(r[0]), "=r"(r[1]), "=r"(r[2]), "=r"(r[3]) : "r"(addr));
}
__device__ __forceinline__ void ldsm_x4_t(uint32_t* r, uint32_t addr) {
    asm volatile("ldmatrix.sync.aligned.m8n8.x4.trans.shared.b16 {%0,%1,%2,%3}, [%4];"
        : "=r"(r[0]), "=r"(r[1]), "=r"(r[2]), "=r"(r[3]) : "r"(addr));
}

__device__ __forceinline__ void mma16816(float* c, const uint32_t* a, const uint32_t* b) {
    asm volatile("mma.sync.aligned.m16n8k16.row.col.f32.bf16.bf16.f32 "
        "{%0,%1,%2,%3}, {%4,%5,%6,%7}, {%8,%9}, {%0,%1,%2,%3};"
        : "+f"(c[0]), "+f"(c[1]), "+f"(c[2]), "+f"(c[3])
        : "r"(a[0]), "r"(a[1]), "r"(a[2]), "r"(a[3]), "r"(b[0]), "r"(b[1]));
}
__device__ __forceinline__ void mma16816h(float* c, const uint32_t* a, const uint32_t* b) {
    asm volatile("mma.sync.aligned.m16n8k16.row.col.f32.f16.f16.f32 "
        "{%0,%1,%2,%3}, {%4,%5,%6,%7}, {%8,%9}, {%0,%1,%2,%3};"
        : "+f"(c[0]), "+f"(c[1]), "+f"(c[2]), "+f"(c[3])
        : "r"(a[0]), "r"(a[1]), "r"(a[2]), "r"(a[3]), "r"(b[0]), "r"(b[1]));
}

// pack(lo, hi): lo -> bits[15:0], hi -> bits[31:16]
__device__ __forceinline__ uint32_t pack_bf16(float lo, float hi) {
    uint32_t d;
    asm("cvt.rn.bf16x2.f32 %0, %1, %2;" : "=r"(d) : "f"(hi), "f"(lo));
    return d;
}
__device__ __forceinline__ uint32_t pack_f16(__half lo, __half hi) {
    __half2 h2 = __halves2half2(lo, hi);
    return *(uint32_t*)&h2;
}

// fast 2^z for z <= 0 (quartic Taylor after rint reduction, err ~4e-5)
__device__ __forceinline__ float exp2_fast(float z) {
    z = fmaxf(z, -126.f);
    float fi = rintf(z);
    float f  = z - fi;
    float p  = 0.00961813f;
    p = fmaf(p, f, 0.0555041f);
    p = fmaf(p, f, 0.2402265f);
    p = fmaf(p, f, 0.6931472f);
    p = fmaf(p, f, 1.0f);
    int e = (int)fi;
    return p * __int_as_float((uint32_t)(e + 127) << 23);
}

// ---------------------------------------------------------------------------
// Split / transpose conversion kernels
// ---------------------------------------------------------------------------
__global__ __launch_bounds__(256) void split_x_kernel(const float4* __restrict__ in) {
    size_t i = (size_t)blockIdx.x * blockDim.x + threadIdx.x;
    float4 v = in[i];
    float f[4] = {v.x, v.y, v.z, v.w};
    __nv_bfloat16 h[4], l[4];
    #pragma unroll
    for (int j = 0; j < 4; j++) {
        h[j] = __float2bfloat16(f[j]);
        l[j] = __float2bfloat16(f[j] - __bfloat162float(h[j]));
    }
    *(uint2*)(g_x_h + i * 4) = *(const uint2*)h;
    *(uint2*)(g_x_l + i * 4) = *(const uint2*)l;
}

// Weights: W [K][N] fp32 -> transposed split bf16 [N][K]
__global__ __launch_bounds__(256) void wsplit_kernel(const float* __restrict__ Wq,
                                                     const float* __restrict__ Wk,
                                                     const float* __restrict__ Wv,
                                                     const float* __restrict__ Wo) {
    __shared__ float tile[32][33];
    int z = blockIdx.z;
    const float* W = (z == 0) ? Wq : (z == 1) ? Wk : (z == 2) ? Wv : Wo;
    __nv_bfloat16* oh = g_wT_h + (size_t)z * D * D;
    __nv_bfloat16* ol = g_wT_l + (size_t)z * D * D;
    int n0 = blockIdx.x * 32, k0 = blockIdx.y * 32;
    int tx = threadIdx.x & 31, ty = threadIdx.x >> 5;
    #pragma unroll
    for (int i = 0; i < 4; i++) {
        int k = ty + i * 8;
        tile[k][tx] = W[(size_t)(k0 + k) * D + n0 + tx];
    }
    __syncthreads();
    #pragma unroll
    for (int i = 0; i < 4; i++) {
        int n = ty + i * 8;
        float v = tile[tx][n];
        __nv_bfloat16 h = __float2bfloat16(v);
        __nv_bfloat16 l = __float2bfloat16(v - __bfloat162float(h));
        oh[(size_t)(n0 + n) * D + k0 + tx] = h;
        ol[(size_t)(n0 + n) * D + k0 + tx] = l;
    }
}

// ---------------------------------------------------------------------------
// mma.sync split-bf16 GEMM: C[128x128 tile] = A(hi+lo) @ B(hi+lo)^T + bias
// 4 warps (2x2), warp tile 64x64, BK=32, double-buffered cp.async, 128 thr.
// out mode: 0 = fp32, 1 = fp16 hi/lo pair, 2 = fp16 single
// ---------------------------------------------------------------------------
constexpr int BKG      = 32;
constexpr int LDT      = 40;                 // bf16 stride per tile row (80 B)
constexpr int TILE_BY  = 128 * LDT * 2;      // 10240 B per tile
constexpr int STAGE_BY = 4 * TILE_BY;        // Ah, Al, Bh, Bl = 40960 B
constexpr int GEMM_SMEM = 2 * STAGE_BY;      // 81920 B
constexpr int NITER    = D / BKG;            // 64

__device__ __forceinline__ void load_stage(uint32_t sbase,
                                           const __nv_bfloat16* Ah,
                                           const __nv_bfloat16* Al,
                                           const __nv_bfloat16* Bh,
                                           const __nv_bfloat16* Bl,
                                           int k0, int t) {
    const __nv_bfloat16* bases[4] = {Ah, Al, Bh, Bl};
    #pragma unroll
    for (int i = 0; i < 16; i++) {
        const int tile = i >> 2;              // 4 slots per tile per thread
        int idx  = t + 128 * (i & 3);         // 0..511
        int row  = idx >> 2;                  // 0..127
        int chnk = idx & 3;                   // 16B chunk
        const __nv_bfloat16* src = bases[tile] + (size_t)row * D + k0 + chnk * 8;
        uint32_t dst = sbase + tile * TILE_BY + row * (LDT * 2) + chnk * 16;
        cp_async16(dst, src);
    }
    CP_COMMIT();
}

__device__ __forceinline__ void tc_gemm_body(const __nv_bfloat16* __restrict__ Ahp,
                                             const __nv_bfloat16* __restrict__ Alp,
                                             const __nv_bfloat16* __restrict__ Bhp,
                                             const __nv_bfloat16* __restrict__ Blp,
                                             const float* __restrict__ bias,
                                             int mode,
                                             float* __restrict__ C,
                                             __half* __restrict__ Fh,
                                             __half* __restrict__ Fl) {
    extern __shared__ char smem[];
    const uint32_t sb = smem_u32(smem);
    const int t    = threadIdx.x;
    const int lane = t & 31;
    const int w    = t >> 5;
    const int wm   = (w & 1) * 64;
    const int wn   = (w >> 1) * 64;
    const int m0   = blockIdx.y * 128;
    const int n0   = blockIdx.x * 128;

    const __nv_bfloat16* Arow  = Ahp + (size_t)m0 * D;
    const __nv_bfloat16* AlRow = Alp + (size_t)m0 * D;
    const __nv_bfloat16* Brow  = Bhp + (size_t)n0 * D;
    const __nv_bfloat16* BlRow = Blp + (size_t)n0 * D;

    float acc[4][8][4];
    #pragma unroll
    for (int i = 0; i < 4; i++)
        #pragma unroll
        for (int j = 0; j < 8; j++)
            #pragma unroll
            for (int r = 0; r < 4; r++) acc[i][j][r] = 0.f;

    const int arow  = lane & 15;
    const int akoff = (lane >> 4) * 16;
    const int bn    = (lane & 7) + ((lane >> 4) << 3);
    const int bkoff = ((lane >> 3) & 1) * 16;

    load_stage(sb, Arow, AlRow, Brow, BlRow, 0, t);

    for (int c = 0; c < NITER; c++) {
        if (c + 1 < NITER) {
            load_stage(sb + ((c + 1) & 1) * STAGE_BY, Arow, AlRow, Brow, BlRow,
                       (c + 1) * BKG, t);
            CP_WAIT1();
        } else {
            CP_WAIT0();
        }
        __syncthreads();                       // stage c visible to all

        const uint32_t sbase = sb + (c & 1) * STAGE_BY;
        #pragma unroll
        for (int kk = 0; kk < 2; kk++) {
            const uint32_t kbyte = kk * 32;
            uint32_t ah[4][4], al[4][4];
            #pragma unroll
            for (int mf = 0; mf < 4; mf++) {
                uint32_t ad = sbase + (wm + mf * 16 + arow) * (LDT * 2) + kbyte + akoff;
                ldsm_x4(ah[mf], ad);
                ldsm_x4(al[mf], ad + TILE_BY);
            }
            #pragma unroll
            for (int nb = 0; nb < 4; nb++) {
                uint32_t bh4[4], bl4[4];
                uint32_t bd = sbase + 2 * TILE_BY + (wn + nb * 16 + bn) * (LDT * 2) + kbyte + bkoff;
                ldsm_x4(bh4, bd);
                ldsm_x4(bl4, bd + TILE_BY);
                #pragma unroll
                for (int mf = 0; mf < 4; mf++)
                    #pragma unroll
                    for (int half = 0; half < 2; half++) {
                        int nf = nb * 2 + half;
                        mma16816(acc[mf][nf], ah[mf], &bh4[half * 2]);
                        mma16816(acc[mf][nf], ah[mf], &bl4[half * 2]);
                        mma16816(acc[mf][nf], al[mf], &bh4[half * 2]);
                    }
            }
        }
        __syncthreads();                       // done reading stage c
    }

    // Epilogue
    const int rbase = m0 + wm + (lane >> 2);
    const int cbase = n0 + wn + (lane & 3) * 2;
    #pragma unroll
    for (int mf = 0; mf < 4; mf++) {
        #pragma unroll
        for (int nf = 0; nf < 8; nf++) {
            int col = cbase + nf * 8;
            float2 bv = *(const float2*)(bias + col);
            int r0 = rbase + mf * 16;
            float v0 = acc[mf][nf][0] + bv.x, v1 = acc[mf][nf][1] + bv.y;
            float v2 = acc[mf][nf][2] + bv.x, v3 = acc[mf][nf][3] + bv.y;
            if (mode == 0) {
                float2 o0 = {v0, v1}, o1 = {v2, v3};
                *(float2*)(C + (size_t)r0 * D + col)       = o0;
                *(float2*)(C + (size_t)(r0 + 8) * D + col) = o1;
            } else {
                __half h0 = __float2half_rn(v0), h1 = __float2half_rn(v1);
                __half h2 = __float2half_rn(v2), h3 = __float2half_rn(v3);
                *(uint32_t*)(Fh + (size_t)r0 * D + col)       = pack_f16(h0, h1);
                *(uint32_t*)(Fh + (size_t)(r0 + 8) * D + col) = pack_f16(h2, h3);
                if (mode == 1) {
                    __half l0 = __float2half_rn(v0 - __half2float(h0));
                    __half l1 = __float2half_rn(v1 - __half2float(h1));
                    __half l2 = __float2half_rn(v2 - __half2float(h2));
                    __half l3 = __float2half_rn(v3 - __half2float(h3));
                    *(uint32_t*)(Fl + (size_t)r0 * D + col)       = pack_f16(l0, l1);
                    *(uint32_t*)(Fl + (size_t)(r0 + 8) * D + col) = pack_f16(l2, l3);
                }
            }
        }
    }
}

__global__ __launch_bounds__(128, 2) void qkv_tc_gemm(const float* __restrict__ bq,
                                                      const float* __restrict__ bk,
                                                      const float* __restrict__ bv) {
    const int z = blockIdx.z;
    const __nv_bfloat16* Bh = g_wT_h + (size_t)z * D * D;
    const __nv_bfloat16* Bl = g_wT_l + (size_t)z * D * D;
    const float* bias = (z == 0) ? bq : (z == 1) ? bk : bv;
    __half* Fh = (z == 0) ? g_q16h : (z == 1) ? g_k16 : g_v16;
    __half* Fl = (z == 0) ? g_q16l : nullptr;
    tc_gemm_body(g_x_h, g_x_l, Bh, Bl, bias, (z == 0) ? 1 : 2, nullptr, Fh, Fl);
}

__global__ __launch_bounds__(128, 2) void out_tc_gemm(const float* __restrict__ bo,
                                                      float* __restrict__ out) {
    tc_gemm_body(g_c_h, g_c_l, g_wT_h + (size_t)3 * D * D, g_wT_l + (size_t)3 * D * D,
                 bo, 0, out, nullptr, nullptr);
}

// ---------------------------------------------------------------------------
// Tensor-core flash attention (fp16 2-pass, causal). Br=Bc=64, 128 threads.
// Q = hi+lo fp16 pair (exact), K/V = single fp16 (residual dropped).
// K/V double-buffered in smem; Q-hi in registers.
// ---------------------------------------------------------------------------
constexpr int AT_LDB   = 272;                    // bytes per tile row (128 f16 + pad)
constexpr int AT_TILE  = 64 * AT_LDB;            // 17408 B
constexpr int ATTN_SMEM = 6 * AT_TILE;           // Qh Ql + (Kh,Vh)x2 = 104448 B
constexpr float SCALE_LOG2E = 0.12751650f;       // (1/sqrt(128)) * log2(e)

__global__ __launch_bounds__(128, 2) void attn_tc_kernel() {
    extern __shared__ char sm8[];
    const uint32_t sb  = smem_u32(sm8);
    const uint32_t Qh  = sb;
    const uint32_t Ql  = sb + AT_TILE;
    const uint32_t KV0 = sb + 2 * AT_TILE;       // Kh then Vh
    const uint32_t KV1 = sb + 4 * AT_TILE;

    const int t    = threadIdx.x;
    const int lane = t & 31;
    const int w    = t >> 5;
    const int iq   = (gridDim.x - 1) - blockIdx.x;      // big blocks first
    const int bh   = blockIdx.y;
    const int b    = bh >> 4;
    const int h    = bh & 15;
    const int q0   = iq * 64;
    const int wq   = w * 16;

    // ldmatrix lane offsets
    const int arow  = lane & 15;
    const int akoff = (lane >> 4) * 16;
    const int bn    = (lane & 7) + ((lane >> 4) << 3);
    const int bkoff = ((lane >> 3) & 1) * 16;
    const int vrow  = lane & 15;
    const int vcol  = (lane >> 4) << 3;

    // ---- Load Q tiles (hi/lo), hoist Q-hi to registers ----
    {
        #pragma unroll
        for (int i = 0; i < 8; i++) {
            int idx  = t + 128 * i;
            int row  = idx >> 4;
            int chnk = idx & 15;
            size_t g = (size_t)(b * S + q0 + row) * D + h * DH + chnk * 8;
            uint32_t so = row * AT_LDB + chnk * 16;
            cp_async16(Qh + so, g_q16h + g);
            cp_async16(Ql + so, g_q16l + g);
        }
        CP_COMMIT();
        CP_WAIT0();
        __syncthreads();
    }
    uint32_t qhr[8][4];
    #pragma unroll
    for (int kt = 0; kt < 8; kt++) {
        uint32_t ad = Qh + (wq + arow) * AT_LDB + kt * 32 + akoff;
        ldsm_x4(qhr[kt], ad);
    }

    // ---- Preload K/V block 0 into buffer 0 ----
    {
        #pragma unroll
        for (int i = 0; i < 8; i++) {
            int idx  = t + 128 * i;
            int row  = idx >> 4;
            int chnk = idx & 15;
            size_t g = (size_t)(b * S + row) * D + h * DH + chnk * 8;
            uint32_t so = row * AT_LDB + chnk * 16;
            cp_async16(KV0 + so, g_k16 + g);
            cp_async16(KV0 + AT_TILE + so, g_v16 + g);
        }
        CP_COMMIT();
    }

    float o[16][4];
    #pragma unroll
    for (int i = 0; i < 16; i++)
        #pragma unroll
        for (int r = 0; r < 4; r++) o[i][r] = 0.f;
    float m0 = -1e30f, m1 = -1e30f, l0 = 0.f, l1 = 0.f;

    const int r0g = q0 + wq + (lane >> 2);
    const int r1g = r0g + 8;

    for (int jb = 0; jb <= iq; jb++) {
        __syncthreads();   // all warps done reading buffer (jb+1)&1 (iter jb-1)
        if (jb + 1 <= iq) {
            const int kn = (jb + 1) * 64;
            const uint32_t buf = ((jb + 1) & 1) ? KV1 : KV0;
            #pragma unroll
            for (int i = 0; i < 8; i++) {
                int idx  = t + 128 * i;
                int row  = idx >> 4;
                int chnk = idx & 15;
                size_t g = (size_t)(b * S + kn + row) * D + h * DH + chnk * 8;
                uint32_t so = row * AT_LDB + chnk * 16;
                cp_async16(buf + so, g_k16 + g);
                cp_async16(buf + AT_TILE + so, g_v16 + g);
            }
            CP_COMMIT();
            CP_WAIT1();    // block jb's loads (issued last iter) complete
        } else {
            CP_WAIT0();
        }
        __syncthreads();

        const uint32_t Kb = (jb & 1) ? KV1 : KV0;
        const uint32_t Vb = Kb + AT_TILE;
        const int k0 = jb * 64;

        // ---- S = Q K^T: Qh*Kh + Ql*Kh (2-pass, K single fp16) ----
        float c[8][4];
        #pragma unroll
        for (int j = 0; j < 8; j++)
            #pragma unroll
            for (int r = 0; r < 4; r++) c[j][r] = 0.f;

        #pragma unroll
        for (int kt = 0; kt < 8; kt++) {
            uint32_t ql4[4];
            ldsm_x4(ql4, Ql + (wq + arow) * AT_LDB + kt * 32 + akoff);
            #pragma unroll
            for (int nb = 0; nb < 4; nb++) {
                uint32_t kh4[4];
                ldsm_x4(kh4, Kb + (nb * 16 + bn) * AT_LDB + kt * 32 + bkoff);
                #pragma unroll
                for (int half = 0; half < 2; half++) {
                    int nf = nb * 2 + half;
                    mma16816h(c[nf], qhr[kt], &kh4[half * 2]);
                    mma16816h(c[nf], ql4,     &kh4[half * 2]);
                }
            }
        }

        // ---- scale + causal mask ----
        const bool diag = (jb == iq);
        #pragma unroll
        for (int j = 0; j < 8; j++) {
            int cc = k0 + j * 8 + (lane & 3) * 2;
            #pragma unroll
            for (int r = 0; r < 4; r++) {
                float v = c[j][r] * SCALE_LOG2E;
                if (diag) {
                    int col = cc + (r & 1);
                    int row = (r < 2) ? r0g : r1g;
                    if (col > row) v = -1e30f;
                }
                c[j][r] = v;
            }
        }

        // ---- online softmax (log2 domain) ----
        float mx0 = -1e30f, mx1 = -1e30f;
        #pragma unroll
        for (int j = 0; j < 8; j++) {
            mx0 = fmaxf(mx0, fmaxf(c[j][0], c[j][1]));
            mx1 = fmaxf(mx1, fmaxf(c[j][2], c[j][3]));
        }
        mx0 = fmaxf(mx0, __shfl_xor_sync(0xffffffffu, mx0, 1));
        mx0 = fmaxf(mx0, __shfl_xor_sync(0xffffffffu, mx0, 2));
        mx1 = fmaxf(mx1, __shfl_xor_sync(0xffffffffu, mx1, 1));
        mx1 = fmaxf(mx1, __shfl_xor_sync(0xffffffffu, mx1, 2));
        float mn0 = fmaxf(m0, mx0), mn1 = fmaxf(m1, mx1);
        float sc0 = exp2_fast(m0 - mn0), sc1 = exp2_fast(m1 - mn1);
        m0 = mn0; m1 = mn1;

        float ls0 = 0.f, ls1 = 0.f;
        #pragma unroll
        for (int j = 0; j < 8; j++) {
            c[j][0] = exp2_fast(c[j][0] - mn0);
            c[j][1] = exp2_fast(c[j][1] - mn0);
            c[j][2] = exp2_fast(c[j][2] - mn1);
            c[j][3] = exp2_fast(c[j][3] - mn1);
            ls0 += c[j][0] + c[j][1];
            ls1 += c[j][2] + c[j][3];
        }
        ls0 += __shfl_xor_sync(0xffffffffu, ls0, 1);
        ls0 += __shfl_xor_sync(0xffffffffu, ls0, 2);
        ls1 += __shfl_xor_sync(0xffffffffu, ls1, 1);
        ls1 += __shfl_xor_sync(0xffffffffu, ls1, 2);
        l0 = l0 * sc0 + ls0;
        l1 = l1 * sc1 + ls1;

        // rescale O
        #pragma unroll
        for (int nf = 0; nf < 16; nf++) {
            o[nf][0] *= sc0; o[nf][1] *= sc0;
            o[nf][2] *= sc1; o[nf][3] *= sc1;
        }

        // ---- pack P to fp16 hi/lo A-fragments ----
        uint32_t pah[4][4], pal[4][4];
        #pragma unroll
        for (int g = 0; g < 4; g++) {
            #pragma unroll
            for (int q = 0; q < 4; q++) {
                int j = 2 * g + (q >> 1);
                int e = (q & 1) * 2;
                float p0v = c[j][e], p1v = c[j][e + 1];
                __half h0 = __float2half_rn(p0v), h1 = __float2half_rn(p1v);
                pah[g][q] = pack_f16(h0, h1);
                __half r0 = __float2half_rn(p0v - __half2float(h0));
                __half r1 = __float2half_rn(p1v - __half2float(h1));
                pal[g][q] = pack_f16(r0, r1);
            }
        }

        // ---- O += P V: Ph*Vh + Pl*Vh (2-pass, V single fp16) ----
        #pragma unroll
        for (int g = 0; g < 4; g++) {
            #pragma unroll
            for (int vb = 0; vb < 8; vb++) {
                uint32_t vh4[4];
                ldsm_x4_t(vh4, Vb + (g * 16 + vrow) * AT_LDB + (vb * 16 + vcol) * 2);
                #pragma unroll
                for (int half = 0; half < 2; half++) {
                    int nf = vb * 2 + half;
                    mma16816h(o[nf], pah[g], &vh4[half * 2]);
                    mma16816h(o[nf], pal[g], &vh4[half * 2]);
                }
            }
        }
    }

    // ---- finalize: O/l, write ctx as bf16 hi/lo (for bf16 3-pass out GEMM) ----
    const float inv0 = 1.f / l0, inv1 = 1.f / l1;
    const int colb = h * DH + (lane & 3) * 2;
    #pragma unroll
    for (int nf = 0; nf < 16; nf++) {
        int col = colb + nf * 8;
        float v0 = o[nf][0] * inv0, v1 = o[nf][1] * inv0;
        float v2 = o[nf][2] * inv1, v3 = o[nf][3] * inv1;
        uint32_t h01 = pack_bf16(v0, v1);
        float h0 = __uint_as_float(h01 << 16);
        float h1 = __uint_as_float(h01 & 0xffff0000u);
        uint32_t l01 = pack_bf16(v0 - h0, v1 - h1);
        uint32_t h23 = pack_bf16(v2, v3);
        float h2 = __uint_as_float(h23 << 16);
        float h3 = __uint_as_float(h23 & 0xffff0000u);
        uint32_t l23 = pack_bf16(v2 - h2, v3 - h3);
        size_t g0 = (size_t)(b * S + r0g) * D + col;
        size_t g1 = (size_t)(b * S + r1g) * D + col;
        *(uint32_t*)(g_c_h + g0) = h01;
        *(uint32_t*)(g_c_l + g0) = l01;
        *(uint32_t*)(g_c_h + g1) = h23;
        *(uint32_t*)(g_c_l + g1) = l23;
    }
}

// ---------------------------------------------------------------------------
extern "C" void kernel_launch(void* const* d_in, const int* in_sizes, int n_in,
                              void* d_out, int out_size)
{
    const float* X  = (const float*)d_in[0];
    const float* Wq = (const float*)d_in[1];
    const float* bq = (const float*)d_in[2];
    const float* Wk = (const float*)d_in[3];
    const float* bk = (const float*)d_in[4];
    const float* Wv = (const float*)d_in[5];
    const float* bv = (const float*)d_in[6];
    const float* Wo = (const float*)d_in[7];
    const float* bo = (const float*)d_in[8];
    float* out = (float*)d_out;

    cudaFuncSetAttribute(attn_tc_kernel, cudaFuncAttributeMaxDynamicSharedMemorySize, ATTN_SMEM);
    cudaFuncSetAttribute(qkv_tc_gemm, cudaFuncAttributeMaxDynamicSharedMemorySize, GEMM_SMEM);
    cudaFuncSetAttribute(out_tc_gemm, cudaFuncAttributeMaxDynamicSharedMemorySize, GEMM_SMEM);

    split_x_kernel<<<(M * D / 4) / 256, 256>>>((const float4*)X);
    wsplit_kernel<<<dim3(D / 32, D / 32, 4), 256>>>(Wq, Wk, Wv, Wo);
    qkv_tc_gemm<<<dim3(D / 128, M / 128, 3), 128, GEMM_SMEM>>>(bq, bk, bv);
    attn_tc_kernel<<<dim3(S / 64, B * H), 128, ATTN_SMEM>>>();
    out_tc_gemm<<<dim3(D / 128, M / 128), 128, GEMM_SMEM>>>(bo, out);
}

// round 8
// speedup vs baseline: 5.0391x; 1.2728x over previous
#include <cuda_runtime.h>
#include <cuda_bf16.h>
#include <cuda_fp16.h>
#include <math.h>
#include <cstdint>

// Problem constants
constexpr int B  = 4;
constexpr int S  = 2048;
constexpr int D  = 2048;
constexpr int H  = 16;
constexpr int DH = 128;
constexpr int M  = B * S;          // 8192 rows

// ---------------------------------------------------------------------------
// Scratch (allocation-free rule: device globals). fp16 everywhere.
// ---------------------------------------------------------------------------
__device__ __half g_x16h[(size_t)M * D];
__device__ __half g_x16l[(size_t)M * D];
__device__ __half g_q16h[(size_t)M * D];
__device__ __half g_q16l[(size_t)M * D];
__device__ __half g_k16[(size_t)M * D];
__device__ __half g_v16[(size_t)M * D];
__device__ __half g_c16h[(size_t)M * D];
__device__ __half g_c16l[(size_t)M * D];
__device__ __half g_wT16[(size_t)4 * D * D];   // [w][N][K] single fp16
// ---------------------------------------------------------------------------
// PTX helpers (sm_103 baseline: mma.sync + ldmatrix + cp.async only)
// ---------------------------------------------------------------------------
__device__ __forceinline__ uint32_t smem_u32(const void* p) {
    uint32_t a;
    asm("{ .reg .u64 t; cvta.to.shared.u64 t, %1; cvt.u32.u64 %0, t; }" : "=r"(a) : "l"(p));
    return a;
}

__device__ __forceinline__ void cp_async16(uint32_t dst, const void* src) {
    asm volatile("cp.async.cg.shared.global [%0], [%1], 16;" :: "r"(dst), "l"(src));
}
#define CP_COMMIT() asm volatile("cp.async.commit_group;" ::: "memory")
#define CP_WAIT0()  asm volatile("cp.async.wait_group 0;" ::: "memory")
#define CP_WAIT1()  asm volatile("cp.async.wait_group 1;" ::: "memory")

__device__ __forceinline__ void ldsm_x4(uint32_t* r, uint32_t addr) {
    asm volatile("ldmatrix.sync.aligned.m8n8.x4.shared.b16 {%0,%1,%2,%3}, [%4];"
        : "=r"(r[0]), "=r"(r[1]), "=r"(r[2]), "=r"(r[3]) : "r"(addr));
}
__device__ __forceinline__ void ldsm_x4_t(uint32_t* r, uint32_t addr) {
    asm volatile("ldmatrix.sync.aligned.m8n8.x4.trans.shared.b16 {%0,%1,%2,%3}, [%4];"
        : "=r"(r[0]), "=r"(r[1]), "=r"(r[2]), "=r"(r[3]) : "r"(addr));
}

__device__ __forceinline__ void mma16816h(float* c, const uint32_t* a, const uint32_t* b) {
    asm volatile("mma.sync.aligned.m16n8k16.row.col.f32.f16.f16.f32 "
        "{%0,%1,%2,%3}, {%4,%5,%6,%7}, {%8,%9}, {%0,%1,%2,%3};"
        : "+f"(c[0]), "+f"(c[1]), "+f"(c[2]), "+f"(c[3])
        : "r"(a[0]), "r"(a[1]), "r"(a[2]), "r"(a[3]), "r"(b[0]), "r"(b[1]));
}

__device__ __forceinline__ uint32_t pack_f16(__half lo, __half hi) {
    __half2 h2 = __halves2half2(lo, hi);
    return *(uint32_t*)&h2;
}

// fast 2^z for z <= 0 (quartic Taylor after rint reduction, err ~4e-5)
__device__ __forceinline__ float exp2_fast(float z) {
    z = fmaxf(z, -126.f);
    float fi = rintf(z);
    float f  = z - fi;
    float p  = 0.00961813f;
    p = fmaf(p, f, 0.0555041f);
    p = fmaf(p, f, 0.2402265f);
    p = fmaf(p, f, 0.6931472f);
    p = fmaf(p, f, 1.0f);
    int e = (int)fi;
    return p * __int_as_float((uint32_t)(e + 127) << 23);
}

// ---------------------------------------------------------------------------
// Split / transpose conversion kernels
// ---------------------------------------------------------------------------
__global__ __launch_bounds__(256) void split_x_kernel(const float4* __restrict__ in) {
    size_t i = (size_t)blockIdx.x * blockDim.x + threadIdx.x;
    float4 v = in[i];
    float f[4] = {v.x, v.y, v.z, v.w};
    __half h[4], l[4];
    #pragma unroll
    for (int j = 0; j < 4; j++) {
        h[j] = __float2half_rn(f[j]);
        l[j] = __float2half_rn(f[j] - __half2float(h[j]));
    }
    *(uint2*)(g_x16h + i * 4) = *(const uint2*)h;
    *(uint2*)(g_x16l + i * 4) = *(const uint2*)l;
}

// Weights: W [K][N] fp32 -> transposed single fp16 [N][K]
__global__ __launch_bounds__(256) void wsplit_kernel(const float* __restrict__ Wq,
                                                     const float* __restrict__ Wk,
                                                     const float* __restrict__ Wv,
                                                     const float* __restrict__ Wo) {
    __shared__ float tile[32][33];
    int z = blockIdx.z;
    const float* W = (z == 0) ? Wq : (z == 1) ? Wk : (z == 2) ? Wv : Wo;
    __half* oh = g_wT16 + (size_t)z * D * D;
    int n0 = blockIdx.x * 32, k0 = blockIdx.y * 32;
    int tx = threadIdx.x & 31, ty = threadIdx.x >> 5;
    #pragma unroll
    for (int i = 0; i < 4; i++) {
        int k = ty + i * 8;
        tile[k][tx] = W[(size_t)(k0 + k) * D + n0 + tx];
    }
    __syncthreads();
    #pragma unroll
    for (int i = 0; i < 4; i++) {
        int n = ty + i * 8;
        oh[(size_t)(n0 + n) * D + k0 + tx] = __float2half_rn(tile[tx][n]);
    }
}

// ---------------------------------------------------------------------------
// mma.sync fp16 2-pass GEMM: C[128x128] = (Ah+Al) @ Bh^T + bias
// A: [M,K] fp16 hi/lo. B: [N,K] single fp16 = col operand.
// 4 warps (2x2), warp tile 64x64, BK=32, double-buffered cp.async, 128 thr.
// out mode: 0 = fp32, 1 = fp16 hi/lo pair, 2 = fp16 single
// ---------------------------------------------------------------------------
constexpr int BKG      = 32;
constexpr int LDT      = 40;                 // f16 stride per tile row (80 B)
constexpr int TILE_BY  = 128 * LDT * 2;      // 10240 B per tile
constexpr int STAGE_BY = 3 * TILE_BY;        // Ah, Al, Bh = 30720 B
constexpr int GEMM_SMEM = 2 * STAGE_BY;      // 61440 B
constexpr int NITER    = D / BKG;            // 64

__device__ __forceinline__ void load_stage(uint32_t sbase,
                                           const __half* Ah,
                                           const __half* Al,
                                           const __half* Bh,
                                           int k0, int t) {
    const __half* bases[3] = {Ah, Al, Bh};
    #pragma unroll
    for (int i = 0; i < 12; i++) {
        const int tile = i >> 2;              // 4 slots per tile per thread
        int idx  = t + 128 * (i & 3);         // 0..511
        int row  = idx >> 2;                  // 0..127
        int chnk = idx & 3;                   // 16B chunk
        const __half* src = bases[tile] + (size_t)row * D + k0 + chnk * 8;
        uint32_t dst = sbase + tile * TILE_BY + row * (LDT * 2) + chnk * 16;
        cp_async16(dst, src);
    }
    CP_COMMIT();
}

__device__ __forceinline__ void tc_gemm_body(const __half* __restrict__ Ahp,
                                             const __half* __restrict__ Alp,
                                             const __half* __restrict__ Bhp,
                                             const float* __restrict__ bias,
                                             int mode,
                                             float* __restrict__ C,
                                             __half* __restrict__ Fh,
                                             __half* __restrict__ Fl) {
    extern __shared__ char smem[];
    const uint32_t sb = smem_u32(smem);
    const int t    = threadIdx.x;
    const int lane = t & 31;
    const int w    = t >> 5;
    const int wm   = (w & 1) * 64;
    const int wn   = (w >> 1) * 64;
    const int m0   = blockIdx.y * 128;
    const int n0   = blockIdx.x * 128;

    const __half* Arow  = Ahp + (size_t)m0 * D;
    const __half* AlRow = Alp + (size_t)m0 * D;
    const __half* Brow  = Bhp + (size_t)n0 * D;

    float acc[4][8][4];
    #pragma unroll
    for (int i = 0; i < 4; i++)
        #pragma unroll
        for (int j = 0; j < 8; j++)
            #pragma unroll
            for (int r = 0; r < 4; r++) acc[i][j][r] = 0.f;

    const int arow  = lane & 15;
    const int akoff = (lane >> 4) * 16;
    const int bn    = (lane & 7) + ((lane >> 4) << 3);
    const int bkoff = ((lane >> 3) & 1) * 16;

    load_stage(sb, Arow, AlRow, Brow, 0, t);

    for (int c = 0; c < NITER; c++) {
        if (c + 1 < NITER) {
            load_stage(sb + ((c + 1) & 1) * STAGE_BY, Arow, AlRow, Brow,
                       (c + 1) * BKG, t);
            CP_WAIT1();
        } else {
            CP_WAIT0();
        }
        __syncthreads();                       // stage c visible to all

        const uint32_t sbase = sb + (c & 1) * STAGE_BY;
        #pragma unroll
        for (int kk = 0; kk < 2; kk++) {
            const uint32_t kbyte = kk * 32;
            uint32_t ah[4][4], al[4][4];
            #pragma unroll
            for (int mf = 0; mf < 4; mf++) {
                uint32_t ad = sbase + (wm + mf * 16 + arow) * (LDT * 2) + kbyte + akoff;
                ldsm_x4(ah[mf], ad);
                ldsm_x4(al[mf], ad + TILE_BY);
            }
            #pragma unroll
            for (int nb = 0; nb < 4; nb++) {
                uint32_t bh4[4];
                uint32_t bd = sbase + 2 * TILE_BY + (wn + nb * 16 + bn) * (LDT * 2) + kbyte + bkoff;
                ldsm_x4(bh4, bd);
                #pragma unroll
                for (int mf = 0; mf < 4; mf++)
                    #pragma unroll
                    for (int half = 0; half < 2; half++) {
                        int nf = nb * 2 + half;
                        mma16816h(acc[mf][nf], ah[mf], &bh4[half * 2]);
                        mma16816h(acc[mf][nf], al[mf], &bh4[half * 2]);
                    }
            }
        }
        __syncthreads();                       // done reading stage c
    }

    // Epilogue
    const int rbase = m0 + wm + (lane >> 2);
    const int cbase = n0 + wn + (lane & 3) * 2;
    #pragma unroll
    for (int mf = 0; mf < 4; mf++) {
        #pragma unroll
        for (int nf = 0; nf < 8; nf++) {
            int col = cbase + nf * 8;
            float2 bv = *(const float2*)(bias + col);
            int r0 = rbase + mf * 16;
            float v0 = acc[mf][nf][0] + bv.x, v1 = acc[mf][nf][1] + bv.y;
            float v2 = acc[mf][nf][2] + bv.x, v3 = acc[mf][nf][3] + bv.y;
            if (mode == 0) {
                float2 o0 = {v0, v1}, o1 = {v2, v3};
                *(float2*)(C + (size_t)r0 * D + col)       = o0;
                *(float2*)(C + (size_t)(r0 + 8) * D + col) = o1;
            } else {
                __half h0 = __float2half_rn(v0), h1 = __float2half_rn(v1);
                __half h2 = __float2half_rn(v2), h3 = __float2half_rn(v3);
                *(uint32_t*)(Fh + (size_t)r0 * D + col)       = pack_f16(h0, h1);
                *(uint32_t*)(Fh + (size_t)(r0 + 8) * D + col) = pack_f16(h2, h3);
                if (mode == 1) {
                    __half l0 = __float2half_rn(v0 - __half2float(h0));
                    __half l1 = __float2half_rn(v1 - __half2float(h1));
                    __half l2 = __float2half_rn(v2 - __half2float(h2));
                    __half l3 = __float2half_rn(v3 - __half2float(h3));
                    *(uint32_t*)(Fl + (size_t)r0 * D + col)       = pack_f16(l0, l1);
                    *(uint32_t*)(Fl + (size_t)(r0 + 8) * D + col) = pack_f16(l2, l3);
                }
            }
        }
    }
}

__global__ __launch_bounds__(128, 2) void qkv_tc_gemm(const float* __restrict__ bq,
                                                      const float* __restrict__ bk,
                                                      const float* __restrict__ bv) {
    const int z = blockIdx.z;
    const __half* Bh = g_wT16 + (size_t)z * D * D;
    const float* bias = (z == 0) ? bq : (z == 1) ? bk : bv;
    __half* Fh = (z == 0) ? g_q16h : (z == 1) ? g_k16 : g_v16;
    __half* Fl = (z == 0) ? g_q16l : nullptr;
    tc_gemm_body(g_x16h, g_x16l, Bh, bias, (z == 0) ? 1 : 2, nullptr, Fh, Fl);
}

__global__ __launch_bounds__(128, 2) void out_tc_gemm(const float* __restrict__ bo,
                                                      float* __restrict__ out) {
    tc_gemm_body(g_c16h, g_c16l, g_wT16 + (size_t)3 * D * D,
                 bo, 0, out, nullptr, nullptr);
}

// ---------------------------------------------------------------------------
// Tensor-core flash attention (fp16 2-pass, causal). Br=Bc=64, 128 threads.
// Q = hi+lo fp16 pair (exact), K/V = single fp16 (residual dropped).
// K/V double-buffered in smem; Q-hi in registers.
// ---------------------------------------------------------------------------
constexpr int AT_LDB   = 272;                    // bytes per tile row (128 f16 + pad)
constexpr int AT_TILE  = 64 * AT_LDB;            // 17408 B
constexpr int ATTN_SMEM = 6 * AT_TILE;           // Qh Ql + (Kh,Vh)x2 = 104448 B
constexpr float SCALE_LOG2E = 0.12751650f;       // (1/sqrt(128)) * log2(e)

__global__ __launch_bounds__(128, 2) void attn_tc_kernel() {
    extern __shared__ char sm8[];
    const uint32_t sb  = smem_u32(sm8);
    const uint32_t Qh  = sb;
    const uint32_t Ql  = sb + AT_TILE;
    const uint32_t KV0 = sb + 2 * AT_TILE;       // Kh then Vh
    const uint32_t KV1 = sb + 4 * AT_TILE;

    const int t    = threadIdx.x;
    const int lane = t & 31;
    const int w    = t >> 5;
    const int iq   = (gridDim.x - 1) - blockIdx.x;      // big blocks first
    const int bh   = blockIdx.y;
    const int b    = bh >> 4;
    const int h    = bh & 15;
    const int q0   = iq * 64;
    const int wq   = w * 16;

    // ldmatrix lane offsets
    const int arow  = lane & 15;
    const int akoff = (lane >> 4) * 16;
    const int bn    = (lane & 7) + ((lane >> 4) << 3);
    const int bkoff = ((lane >> 3) & 1) * 16;
    const int vrow  = lane & 15;
    const int vcol  = (lane >> 4) << 3;

    // ---- Load Q tiles (hi/lo), hoist Q-hi to registers ----
    {
        #pragma unroll
        for (int i = 0; i < 8; i++) {
            int idx  = t + 128 * i;
            int row  = idx >> 4;
            int chnk = idx & 15;
            size_t g = (size_t)(b * S + q0 + row) * D + h * DH + chnk * 8;
            uint32_t so = row * AT_LDB + chnk * 16;
            cp_async16(Qh + so, g_q16h + g);
            cp_async16(Ql + so, g_q16l + g);
        }
        CP_COMMIT();
        CP_WAIT0();
        __syncthreads();
    }
    uint32_t qhr[8][4];
    #pragma unroll
    for (int kt = 0; kt < 8; kt++) {
        uint32_t ad = Qh + (wq + arow) * AT_LDB + kt * 32 + akoff;
        ldsm_x4(qhr[kt], ad);
    }

    // ---- Preload K/V block 0 into buffer 0 ----
    {
        #pragma unroll
        for (int i = 0; i < 8; i++) {
            int idx  = t + 128 * i;
            int row  = idx >> 4;
            int chnk = idx & 15;
            size_t g = (size_t)(b * S + row) * D + h * DH + chnk * 8;
            uint32_t so = row * AT_LDB + chnk * 16;
            cp_async16(KV0 + so, g_k16 + g);
            cp_async16(KV0 + AT_TILE + so, g_v16 + g);
        }
        CP_COMMIT();
    }

    float o[16][4];
    #pragma unroll
    for (int i = 0; i < 16; i++)
        #pragma unroll
        for (int r = 0; r < 4; r++) o[i][r] = 0.f;
    float m0 = -1e30f, m1 = -1e30f, l0 = 0.f, l1 = 0.f;

    const int r0g = q0 + wq + (lane >> 2);
    const int r1g = r0g + 8;

    for (int jb = 0; jb <= iq; jb++) {
        __syncthreads();   // all warps done reading buffer (jb+1)&1 (iter jb-1)
        if (jb + 1 <= iq) {
            const int kn = (jb + 1) * 64;
            const uint32_t buf = ((jb + 1) & 1) ? KV1 : KV0;
            #pragma unroll
            for (int i = 0; i < 8; i++) {
                int idx  = t + 128 * i;
                int row  = idx >> 4;
                int chnk = idx & 15;
                size_t g = (size_t)(b * S + kn + row) * D + h * DH + chnk * 8;
                uint32_t so = row * AT_LDB + chnk * 16;
                cp_async16(buf + so, g_k16 + g);
                cp_async16(buf + AT_TILE + so, g_v16 + g);
            }
            CP_COMMIT();
            CP_WAIT1();    // block jb's loads (issued last iter) complete
        } else {
            CP_WAIT0();
        }
        __syncthreads();

        const uint32_t Kb = (jb & 1) ? KV1 : KV0;
        const uint32_t Vb = Kb + AT_TILE;
        const int k0 = jb * 64;

        // ---- S = Q K^T: Qh*Kh + Ql*Kh (2-pass, K single fp16) ----
        float c[8][4];
        #pragma unroll
        for (int j = 0; j < 8; j++)
            #pragma unroll
            for (int r = 0; r < 4; r++) c[j][r] = 0.f;

        #pragma unroll
        for (int kt = 0; kt < 8; kt++) {
            uint32_t ql4[4];
            ldsm_x4(ql4, Ql + (wq + arow) * AT_LDB + kt * 32 + akoff);
            #pragma unroll
            for (int nb = 0; nb < 4; nb++) {
                uint32_t kh4[4];
                ldsm_x4(kh4, Kb + (nb * 16 + bn) * AT_LDB + kt * 32 + bkoff);
                #pragma unroll
                for (int half = 0; half < 2; half++) {
                    int nf = nb * 2 + half;
                    mma16816h(c[nf], qhr[kt], &kh4[half * 2]);
                    mma16816h(c[nf], ql4,     &kh4[half * 2]);
                }
            }
        }

        // ---- scale + causal mask ----
        const bool diag = (jb == iq);
        #pragma unroll
        for (int j = 0; j < 8; j++) {
            int cc = k0 + j * 8 + (lane & 3) * 2;
            #pragma unroll
            for (int r = 0; r < 4; r++) {
                float v = c[j][r] * SCALE_LOG2E;
                if (diag) {
                    int col = cc + (r & 1);
                    int row = (r < 2) ? r0g : r1g;
                    if (col > row) v = -1e30f;
                }
                c[j][r] = v;
            }
        }

        // ---- online softmax (log2 domain) ----
        float mx0 = -1e30f, mx1 = -1e30f;
        #pragma unroll
        for (int j = 0; j < 8; j++) {
            mx0 = fmaxf(mx0, fmaxf(c[j][0], c[j][1]));
            mx1 = fmaxf(mx1, fmaxf(c[j][2], c[j][3]));
        }
        mx0 = fmaxf(mx0, __shfl_xor_sync(0xffffffffu, mx0, 1));
        mx0 = fmaxf(mx0, __shfl_xor_sync(0xffffffffu, mx0, 2));
        mx1 = fmaxf(mx1, __shfl_xor_sync(0xffffffffu, mx1, 1));
        mx1 = fmaxf(mx1, __shfl_xor_sync(0xffffffffu, mx1, 2));
        float mn0 = fmaxf(m0, mx0), mn1 = fmaxf(m1, mx1);
        float sc0 = exp2_fast(m0 - mn0), sc1 = exp2_fast(m1 - mn1);
        m0 = mn0; m1 = mn1;

        float ls0 = 0.f, ls1 = 0.f;
        #pragma unroll
        for (int j = 0; j < 8; j++) {
            c[j][0] = exp2_fast(c[j][0] - mn0);
            c[j][1] = exp2_fast(c[j][1] - mn0);
            c[j][2] = exp2_fast(c[j][2] - mn1);
            c[j][3] = exp2_fast(c[j][3] - mn1);
            ls0 += c[j][0] + c[j][1];
            ls1 += c[j][2] + c[j][3];
        }
        ls0 += __shfl_xor_sync(0xffffffffu, ls0, 1);
        ls0 += __shfl_xor_sync(0xffffffffu, ls0, 2);
        ls1 += __shfl_xor_sync(0xffffffffu, ls1, 1);
        ls1 += __shfl_xor_sync(0xffffffffu, ls1, 2);
        l0 = l0 * sc0 + ls0;
        l1 = l1 * sc1 + ls1;

        // rescale O
        #pragma unroll
        for (int nf = 0; nf < 16; nf++) {
            o[nf][0] *= sc0; o[nf][1] *= sc0;
            o[nf][2] *= sc1; o[nf][3] *= sc1;
        }

        // ---- pack P to fp16 hi/lo A-fragments ----
        uint32_t pah[4][4], pal[4][4];
        #pragma unroll
        for (int g = 0; g < 4; g++) {
            #pragma unroll
            for (int q = 0; q < 4; q++) {
                int j = 2 * g + (q >> 1);
                int e = (q & 1) * 2;
                float p0v = c[j][e], p1v = c[j][e + 1];
                __half h0 = __float2half_rn(p0v), h1 = __float2half_rn(p1v);
                pah[g][q] = pack_f16(h0, h1);
                __half r0 = __float2half_rn(p0v - __half2float(h0));
                __half r1 = __float2half_rn(p1v - __half2float(h1));
                pal[g][q] = pack_f16(r0, r1);
            }
        }

        // ---- O += P V: Ph*Vh + Pl*Vh (2-pass, V single fp16) ----
        #pragma unroll
        for (int g = 0; g < 4; g++) {
            #pragma unroll
            for (int vb = 0; vb < 8; vb++) {
                uint32_t vh4[4];
                ldsm_x4_t(vh4, Vb + (g * 16 + vrow) * AT_LDB + (vb * 16 + vcol) * 2);
                #pragma unroll
                for (int half = 0; half < 2; half++) {
                    int nf = vb * 2 + half;
                    mma16816h(o[nf], pah[g], &vh4[half * 2]);
                    mma16816h(o[nf], pal[g], &vh4[half * 2]);
                }
            }
        }
    }

    // ---- finalize: O/l, write ctx as fp16 hi/lo (for fp16 2-pass out GEMM) ----
    const float inv0 = 1.f / l0, inv1 = 1.f / l1;
    const int colb = h * DH + (lane & 3) * 2;
    #pragma unroll
    for (int nf = 0; nf < 16; nf++) {
        int col = colb + nf * 8;
        float v0 = o[nf][0] * inv0, v1 = o[nf][1] * inv0;
        float v2 = o[nf][2] * inv1, v3 = o[nf][3] * inv1;
        __half h0 = __float2half_rn(v0), h1 = __float2half_rn(v1);
        __half h2 = __float2half_rn(v2), h3 = __float2half_rn(v3);
        __half l0h = __float2half_rn(v0 - __half2float(h0));
        __half l1h = __float2half_rn(v1 - __half2float(h1));
        __half l2h = __float2half_rn(v2 - __half2float(h2));
        __half l3h = __float2half_rn(v3 - __half2float(h3));
        size_t g0 = (size_t)(b * S + r0g) * D + col;
        size_t g1 = (size_t)(b * S + r1g) * D + col;
        *(uint32_t*)(g_c16h + g0) = pack_f16(h0, h1);
        *(uint32_t*)(g_c16l + g0) = pack_f16(l0h, l1h);
        *(uint32_t*)(g_c16h + g1) = pack_f16(h2, h3);
        *(uint32_t*)(g_c16l + g1) = pack_f16(l2h, l3h);
    }
}

// ---------------------------------------------------------------------------
extern "C" void kernel_launch(void* const* d_in, const int* in_sizes, int n_in,
                              void* d_out, int out_size)
{
    const float* X  = (const float*)d_in[0];
    const float* Wq = (const float*)d_in[1];
    const float* bq = (const float*)d_in[2];
    const float* Wk = (const float*)d_in[3];
    const float* bk = (const float*)d_in[4];
    const float* Wv = (const float*)d_in[5];
    const float* bv = (const float*)d_in[6];
    const float* Wo = (const float*)d_in[7];
    const float* bo = (const float*)d_in[8];
    float* out = (float*)d_out;

    cudaFuncSetAttribute(attn_tc_kernel, cudaFuncAttributeMaxDynamicSharedMemorySize, ATTN_SMEM);
    cudaFuncSetAttribute(qkv_tc_gemm, cudaFuncAttributeMaxDynamicSharedMemorySize, GEMM_SMEM);
    cudaFuncSetAttribute(out_tc_gemm, cudaFuncAttributeMaxDynamicSharedMemorySize, GEMM_SMEM);

    split_x_kernel<<<(M * D / 4) / 256, 256>>>((const float4*)X);
    wsplit_kernel<<<dim3(D / 32, D / 32, 4), 256>>>(Wq, Wk, Wv, Wo);
    qkv_tc_gemm<<<dim3(D / 128, M / 128, 3), 128, GEMM_SMEM>>>(bq, bk, bv);
    attn_tc_kernel<<<dim3(S / 64, B * H), 128, ATTN_SMEM>>>();
    out_tc_gemm<<<dim3(D / 128, M / 128), 128, GEMM_SMEM>>>(bo, out);
}

// round 9
// speedup vs baseline: 6.1315x; 1.2168x over previous
#include <cuda_runtime.h>
#include <cuda_bf16.h>
#include <cuda_fp16.h>
#include <math.h>
#include <cstdint>

// Problem constants
constexpr int B  = 4;
constexpr int S  = 2048;
constexpr int D  = 2048;
constexpr int H  = 16;
constexpr int DH = 128;
constexpr int M  = B * S;          // 8192 rows

// ---------------------------------------------------------------------------
// Scratch (allocation-free rule: device globals). fp16 everywhere.
// ---------------------------------------------------------------------------
__device__ __half g_x16h[(size_t)M * D];
__device__ __half g_x16l[(size_t)M * D];
__device__ __half g_q16h[(size_t)M * D];
__device__ __half g_q16l[(size_t)M * D];
__device__ __half g_k16[(size_t)M * D];
__device__ __half g_v16[(size_t)M * D];
__device__ __half g_c16h[(size_t)M * D];
__device__ __half g_c16l[(size_t)M * D];
__device__ __half g_wT16[(size_t)4 * D * D];   // [w][N][K] single fp16

// ---------------------------------------------------------------------------
// PTX helpers (sm_103 baseline: mma.sync + ldmatrix + cp.async only)
// ---------------------------------------------------------------------------
__device__ __forceinline__ uint32_t smem_u32(const void* p) {
    uint32_t a;
    asm("{ .reg .u64 t; cvta.to.shared.u64 t, %1; cvt.u32.u64 %0, t; }" : "=r"(a) : "l"(p));
    return a;
}

__device__ __forceinline__ void cp_async16(uint32_t dst, const void* src) {
    asm volatile("cp.async.cg.shared.global [%0], [%1], 16;" :: "r"(dst), "l"(src));
}
#define CP_COMMIT() asm volatile("cp.async.commit_group;" ::: "memory")
#define CP_WAIT0()  asm volatile("cp.async.wait_group 0;" ::: "memory")
#define CP_WAIT1()  asm volatile("cp.async.wait_group 1;" ::: "memory")
#define CP_WAIT2()  asm volatile("cp.async.wait_group 2;" ::: "memory")

__device__ __forceinline__ void ldsm_x4(uint32_t* r, uint32_t addr) {
    asm volatile("ldmatrix.sync.aligned.m8n8.x4.shared.b16 {%0,%1,%2,%3}, [%4];"
        : "=r"(r[0]), "=r"(r[1]), "=r"(r[2]), "=r"(r[3]) : "r"(addr));
}
__device__ __forceinline__ void ldsm_x4_t(uint32_t* r, uint32_t addr) {
    asm volatile("ldmatrix.sync.aligned.m8n8.x4.trans.shared.b16 {%0,%1,%2,%3}, [%4];"
        : "=r"(r[0]), "=r"(r[1]), "=r"(r[2]), "=r"(r[3]) : "r"(addr));
}

__device__ __forceinline__ void mma16816h(float* c, const uint32_t* a, const uint32_t* b) {
    asm volatile("mma.sync.aligned.m16n8k16.row.col.f32.f16.f16.f32 "
        "{%0,%1,%2,%3}, {%4,%5,%6,%7}, {%8,%9}, {%0,%1,%2,%3};"
        : "+f"(c[0]), "+f"(c[1]), "+f"(c[2]), "+f"(c[3])
        : "r"(a[0]), "r"(a[1]), "r"(a[2]), "r"(a[3]), "r"(b[0]), "r"(b[1]));
}

__device__ __forceinline__ uint32_t pack_f16(__half lo, __half hi) {
    __half2 h2 = __halves2half2(lo, hi);
    return *(uint32_t*)&h2;
}

// fast 2^z for z <= 0 (quartic Taylor after rint reduction, err ~4e-5)
__device__ __forceinline__ float exp2_fast(float z) {
    z = fmaxf(z, -126.f);
    float fi = rintf(z);
    float f  = z - fi;
    float p  = 0.00961813f;
    p = fmaf(p, f, 0.0555041f);
    p = fmaf(p, f, 0.2402265f);
    p = fmaf(p, f, 0.6931472f);
    p = fmaf(p, f, 1.0f);
    int e = (int)fi;
    return p * __int_as_float((uint32_t)(e + 127) << 23);
}

// ---------------------------------------------------------------------------
// Split / transpose conversion kernels
// ---------------------------------------------------------------------------
__global__ __launch_bounds__(256) void split_x_kernel(const float4* __restrict__ in) {
    size_t i = (size_t)blockIdx.x * blockDim.x + threadIdx.x;
    float4 v = in[i];
    float f[4] = {v.x, v.y, v.z, v.w};
    __half h[4], l[4];
    #pragma unroll
    for (int j = 0; j < 4; j++) {
        h[j] = __float2half_rn(f[j]);
        l[j] = __float2half_rn(f[j] - __half2float(h[j]));
    }
    *(uint2*)(g_x16h + i * 4) = *(const uint2*)h;
    *(uint2*)(g_x16l + i * 4) = *(const uint2*)l;
}

// Weights: W [K][N] fp32 -> transposed single fp16 [N][K]
__global__ __launch_bounds__(256) void wsplit_kernel(const float* __restrict__ Wq,
                                                     const float* __restrict__ Wk,
                                                     const float* __restrict__ Wv,
                                                     const float* __restrict__ Wo) {
    __shared__ float tile[32][33];
    int z = blockIdx.z;
    const float* W = (z == 0) ? Wq : (z == 1) ? Wk : (z == 2) ? Wv : Wo;
    __half* oh = g_wT16 + (size_t)z * D * D;
    int n0 = blockIdx.x * 32, k0 = blockIdx.y * 32;
    int tx = threadIdx.x & 31, ty = threadIdx.x >> 5;
    #pragma unroll
    for (int i = 0; i < 4; i++) {
        int k = ty + i * 8;
        tile[k][tx] = W[(size_t)(k0 + k) * D + n0 + tx];
    }
    __syncthreads();
    #pragma unroll
    for (int i = 0; i < 4; i++) {
        int n = ty + i * 8;
        oh[(size_t)(n0 + n) * D + k0 + tx] = __float2half_rn(tile[tx][n]);
    }
}

// ---------------------------------------------------------------------------
// mma.sync fp16 GEMM. NT=3: 2-pass C=(Ah+Al)@B^T; NT=2: 1-pass C=Ah@B^T.
// 4 warps (2x2), warp tile 64x64, BK=32, 3-stage cp.async pipeline, 128 thr.
// MODE: 0 = fp32 out, 1 = fp16 hi/lo out, 2 = fp16 single out
// ---------------------------------------------------------------------------
constexpr int BKG      = 32;
constexpr int LDT      = 40;                 // f16 stride per tile row (80 B)
constexpr int TILE_BY  = 128 * LDT * 2;      // 10240 B per tile
constexpr int NITER    = D / BKG;            // 64
constexpr int GEMM_SMEM3 = 3 * 3 * TILE_BY;  // 92160 B (2-pass)
constexpr int GEMM_SMEM2 = 3 * 2 * TILE_BY;  // 61440 B (1-pass)

template <int NT>
__device__ __forceinline__ void load_stage(uint32_t sbase,
                                           const __half* const* bases,
                                           int k0, int t) {
    #pragma unroll
    for (int i = 0; i < 4 * NT; i++) {
        const int tile = i >> 2;              // 4 slots per tile per thread
        int idx  = t + 128 * (i & 3);         // 0..511
        int row  = idx >> 2;                  // 0..127
        int chnk = idx & 3;                   // 16B chunk
        const __half* src = bases[tile] + (size_t)row * D + k0 + chnk * 8;
        uint32_t dst = sbase + tile * TILE_BY + row * (LDT * 2) + chnk * 16;
        cp_async16(dst, src);
    }
    CP_COMMIT();
}

template <int NT, int MODE>
__device__ __forceinline__ void tc_gemm_body(const __half* __restrict__ Ahp,
                                             const __half* __restrict__ Alp,
                                             const __half* __restrict__ Bhp,
                                             const float* __restrict__ bias,
                                             float* __restrict__ C,
                                             __half* __restrict__ Fh,
                                             __half* __restrict__ Fl) {
    constexpr int STAGE = NT * TILE_BY;
    extern __shared__ char smem[];
    const uint32_t sb = smem_u32(smem);
    const int t    = threadIdx.x;
    const int lane = t & 31;
    const int w    = t >> 5;
    const int wm   = (w & 1) * 64;
    const int wn   = (w >> 1) * 64;
    const int m0   = blockIdx.y * 128;
    const int n0   = blockIdx.x * 128;

    const __half* bases[3];
    bases[0] = Ahp + (size_t)m0 * D;
    bases[NT - 1] = Bhp + (size_t)n0 * D;
    if (NT == 3) bases[1] = Alp + (size_t)m0 * D;

    float acc[4][8][4];
    #pragma unroll
    for (int i = 0; i < 4; i++)
        #pragma unroll
        for (int j = 0; j < 8; j++)
            #pragma unroll
            for (int r = 0; r < 4; r++) acc[i][j][r] = 0.f;

    const int arow  = lane & 15;
    const int akoff = (lane >> 4) * 16;
    const int bn    = (lane & 7) + ((lane >> 4) << 3);
    const int bkoff = ((lane >> 3) & 1) * 16;

    load_stage<NT>(sb + 0 * STAGE, bases, 0, t);
    load_stage<NT>(sb + 1 * STAGE, bases, BKG, t);

    int bufc = 0;
    for (int c = 0; c < NITER; c++) {
        if (c + 2 < NITER) {
            int bufn = bufc + 2; if (bufn >= 3) bufn -= 3;
            load_stage<NT>(sb + bufn * STAGE, bases, (c + 2) * BKG, t);
            CP_WAIT2();                        // stage c complete
        } else {
            CP_WAIT0();
        }
        __syncthreads();

        const uint32_t sbase = sb + bufc * STAGE;
        #pragma unroll
        for (int kk = 0; kk < 2; kk++) {
            const uint32_t kbyte = kk * 32;
            uint32_t ah[4][4], al[4][4];
            #pragma unroll
            for (int mf = 0; mf < 4; mf++) {
                uint32_t ad = sbase + (wm + mf * 16 + arow) * (LDT * 2) + kbyte + akoff;
                ldsm_x4(ah[mf], ad);
                if (NT == 3) ldsm_x4(al[mf], ad + TILE_BY);
            }
            #pragma unroll
            for (int nb = 0; nb < 4; nb++) {
                uint32_t bh4[4];
                uint32_t bd = sbase + (NT - 1) * TILE_BY + (wn + nb * 16 + bn) * (LDT * 2) + kbyte + bkoff;
                ldsm_x4(bh4, bd);
                #pragma unroll
                for (int mf = 0; mf < 4; mf++)
                    #pragma unroll
                    for (int half = 0; half < 2; half++) {
                        int nf = nb * 2 + half;
                        mma16816h(acc[mf][nf], ah[mf], &bh4[half * 2]);
                        if (NT == 3) mma16816h(acc[mf][nf], al[mf], &bh4[half * 2]);
                    }
            }
        }
        __syncthreads();                       // done reading stage c
        if (++bufc == 3) bufc = 0;
    }

    // Epilogue
    const int rbase = m0 + wm + (lane >> 2);
    const int cbase = n0 + wn + (lane & 3) * 2;
    #pragma unroll
    for (int mf = 0; mf < 4; mf++) {
        #pragma unroll
        for (int nf = 0; nf < 8; nf++) {
            int col = cbase + nf * 8;
            float2 bv = *(const float2*)(bias + col);
            int r0 = rbase + mf * 16;
            float v0 = acc[mf][nf][0] + bv.x, v1 = acc[mf][nf][1] + bv.y;
            float v2 = acc[mf][nf][2] + bv.x, v3 = acc[mf][nf][3] + bv.y;
            if (MODE == 0) {
                float2 o0 = {v0, v1}, o1 = {v2, v3};
                *(float2*)(C + (size_t)r0 * D + col)       = o0;
                *(float2*)(C + (size_t)(r0 + 8) * D + col) = o1;
            } else {
                __half h0 = __float2half_rn(v0), h1 = __float2half_rn(v1);
                __half h2 = __float2half_rn(v2), h3 = __float2half_rn(v3);
                *(uint32_t*)(Fh + (size_t)r0 * D + col)       = pack_f16(h0, h1);
                *(uint32_t*)(Fh + (size_t)(r0 + 8) * D + col) = pack_f16(h2, h3);
                if (MODE == 1) {
                    __half l0 = __float2half_rn(v0 - __half2float(h0));
                    __half l1 = __float2half_rn(v1 - __half2float(h1));
                    __half l2 = __float2half_rn(v2 - __half2float(h2));
                    __half l3 = __float2half_rn(v3 - __half2float(h3));
                    *(uint32_t*)(Fl + (size_t)r0 * D + col)       = pack_f16(l0, l1);
                    *(uint32_t*)(Fl + (size_t)(r0 + 8) * D + col) = pack_f16(l2, l3);
                }
            }
        }
    }
}

// Q projection: 2-pass (feeds scores directly), fp16 hi/lo output
__global__ __launch_bounds__(128, 2) void q_tc_gemm(const float* __restrict__ bq) {
    tc_gemm_body<3, 1>(g_x16h, g_x16l, g_wT16, bq, nullptr, g_q16h, g_q16l);
}

// K/V projections: 1-pass (attention drops their residuals anyway), fp16 out
__global__ __launch_bounds__(128, 2) void kv_tc_gemm(const float* __restrict__ bk,
                                                     const float* __restrict__ bv) {
    const int z = blockIdx.z;
    tc_gemm_body<2, 2>(g_x16h, nullptr, g_wT16 + (size_t)(1 + z) * D * D,
                       (z == 0) ? bk : bv, nullptr, (z == 0) ? g_k16 : g_v16, nullptr);
}

// Output projection: 2-pass, fp32 out
__global__ __launch_bounds__(128, 2) void out_tc_gemm(const float* __restrict__ bo,
                                                      float* __restrict__ out) {
    tc_gemm_body<3, 0>(g_c16h, g_c16l, g_wT16 + (size_t)3 * D * D,
                       bo, out, nullptr, nullptr);
}

// ---------------------------------------------------------------------------
// Tensor-core flash attention (fp16 2-pass, causal). Br=Bc=64, 128 threads.
// Q = hi+lo fp16 pair (exact), K/V = single fp16 (residual dropped).
// K/V double-buffered in smem; Q-hi in registers.
// ---------------------------------------------------------------------------
constexpr int AT_LDB   = 272;                    // bytes per tile row (128 f16 + pad)
constexpr int AT_TILE  = 64 * AT_LDB;            // 17408 B
constexpr int ATTN_SMEM = 6 * AT_TILE;           // Qh Ql + (Kh,Vh)x2 = 104448 B
constexpr float SCALE_LOG2E = 0.12751650f;       // (1/sqrt(128)) * log2(e)

__global__ __launch_bounds__(128, 2) void attn_tc_kernel() {
    extern __shared__ char sm8[];
    const uint32_t sb  = smem_u32(sm8);
    const uint32_t Qh  = sb;
    const uint32_t Ql  = sb + AT_TILE;
    const uint32_t KV0 = sb + 2 * AT_TILE;       // Kh then Vh
    const uint32_t KV1 = sb + 4 * AT_TILE;

    const int t    = threadIdx.x;
    const int lane = t & 31;
    const int w    = t >> 5;
    const int iq   = (gridDim.x - 1) - blockIdx.x;      // big blocks first
    const int bh   = blockIdx.y;
    const int b    = bh >> 4;
    const int h    = bh & 15;
    const int q0   = iq * 64;
    const int wq   = w * 16;

    // ldmatrix lane offsets
    const int arow  = lane & 15;
    const int akoff = (lane >> 4) * 16;
    const int bn    = (lane & 7) + ((lane >> 4) << 3);
    const int bkoff = ((lane >> 3) & 1) * 16;
    const int vrow  = lane & 15;
    const int vcol  = (lane >> 4) << 3;

    // ---- Load Q tiles (hi/lo), hoist Q-hi to registers ----
    {
        #pragma unroll
        for (int i = 0; i < 8; i++) {
            int idx  = t + 128 * i;
            int row  = idx >> 4;
            int chnk = idx & 15;
            size_t g = (size_t)(b * S + q0 + row) * D + h * DH + chnk * 8;
            uint32_t so = row * AT_LDB + chnk * 16;
            cp_async16(Qh + so, g_q16h + g);
            cp_async16(Ql + so, g_q16l + g);
        }
        CP_COMMIT();
        CP_WAIT0();
        __syncthreads();
    }
    uint32_t qhr[8][4];
    #pragma unroll
    for (int kt = 0; kt < 8; kt++) {
        uint32_t ad = Qh + (wq + arow) * AT_LDB + kt * 32 + akoff;
        ldsm_x4(qhr[kt], ad);
    }

    // ---- Preload K/V block 0 into buffer 0 ----
    {
        #pragma unroll
        for (int i = 0; i < 8; i++) {
            int idx  = t + 128 * i;
            int row  = idx >> 4;
            int chnk = idx & 15;
            size_t g = (size_t)(b * S + row) * D + h * DH + chnk * 8;
            uint32_t so = row * AT_LDB + chnk * 16;
            cp_async16(KV0 + so, g_k16 + g);
            cp_async16(KV0 + AT_TILE + so, g_v16 + g);
        }
        CP_COMMIT();
    }

    float o[16][4];
    #pragma unroll
    for (int i = 0; i < 16; i++)
        #pragma unroll
        for (int r = 0; r < 4; r++) o[i][r] = 0.f;
    float m0 = -1e30f, m1 = -1e30f, l0 = 0.f, l1 = 0.f;

    const int r0g = q0 + wq + (lane >> 2);
    const int r1g = r0g + 8;

    for (int jb = 0; jb <= iq; jb++) {
        __syncthreads();   // all warps done reading buffer (jb+1)&1 (iter jb-1)
        if (jb + 1 <= iq) {
            const int kn = (jb + 1) * 64;
            const uint32_t buf = ((jb + 1) & 1) ? KV1 : KV0;
            #pragma unroll
            for (int i = 0; i < 8; i++) {
                int idx  = t + 128 * i;
                int row  = idx >> 4;
                int chnk = idx & 15;
                size_t g = (size_t)(b * S + kn + row) * D + h * DH + chnk * 8;
                uint32_t so = row * AT_LDB + chnk * 16;
                cp_async16(buf + so, g_k16 + g);
                cp_async16(buf + AT_TILE + so, g_v16 + g);
            }
            CP_COMMIT();
            CP_WAIT1();    // block jb's loads (issued last iter) complete
        } else {
            CP_WAIT0();
        }
        __syncthreads();

        const uint32_t Kb = (jb & 1) ? KV1 : KV0;
        const uint32_t Vb = Kb + AT_TILE;
        const int k0 = jb * 64;

        // ---- S = Q K^T: Qh*Kh + Ql*Kh (2-pass, K single fp16) ----
        float c[8][4];
        #pragma unroll
        for (int j = 0; j < 8; j++)
            #pragma unroll
            for (int r = 0; r < 4; r++) c[j][r] = 0.f;

        #pragma unroll
        for (int kt = 0; kt < 8; kt++) {
            uint32_t ql4[4];
            ldsm_x4(ql4, Ql + (wq + arow) * AT_LDB + kt * 32 + akoff);
            #pragma unroll
            for (int nb = 0; nb < 4; nb++) {
                uint32_t kh4[4];
                ldsm_x4(kh4, Kb + (nb * 16 + bn) * AT_LDB + kt * 32 + bkoff);
                #pragma unroll
                for (int half = 0; half < 2; half++) {
                    int nf = nb * 2 + half;
                    mma16816h(c[nf], qhr[kt], &kh4[half * 2]);
                    mma16816h(c[nf], ql4,     &kh4[half * 2]);
                }
            }
        }

        // ---- scale + causal mask ----
        const bool diag = (jb == iq);
        #pragma unroll
        for (int j = 0; j < 8; j++) {
            int cc = k0 + j * 8 + (lane & 3) * 2;
            #pragma unroll
            for (int r = 0; r < 4; r++) {
                float v = c[j][r] * SCALE_LOG2E;
                if (diag) {
                    int col = cc + (r & 1);
                    int row = (r < 2) ? r0g : r1g;
                    if (col > row) v = -1e30f;
                }
                c[j][r] = v;
            }
        }

        // ---- online softmax (log2 domain) ----
        float mx0 = -1e30f, mx1 = -1e30f;
        #pragma unroll
        for (int j = 0; j < 8; j++) {
            mx0 = fmaxf(mx0, fmaxf(c[j][0], c[j][1]));
            mx1 = fmaxf(mx1, fmaxf(c[j][2], c[j][3]));
        }
        mx0 = fmaxf(mx0, __shfl_xor_sync(0xffffffffu, mx0, 1));
        mx0 = fmaxf(mx0, __shfl_xor_sync(0xffffffffu, mx0, 2));
        mx1 = fmaxf(mx1, __shfl_xor_sync(0xffffffffu, mx1, 1));
        mx1 = fmaxf(mx1, __shfl_xor_sync(0xffffffffu, mx1, 2));
        float mn0 = fmaxf(m0, mx0), mn1 = fmaxf(m1, mx1);
        float sc0 = exp2_fast(m0 - mn0), sc1 = exp2_fast(m1 - mn1);
        m0 = mn0; m1 = mn1;

        float ls0 = 0.f, ls1 = 0.f;
        #pragma unroll
        for (int j = 0; j < 8; j++) {
            c[j][0] = exp2_fast(c[j][0] - mn0);
            c[j][1] = exp2_fast(c[j][1] - mn0);
            c[j][2] = exp2_fast(c[j][2] - mn1);
            c[j][3] = exp2_fast(c[j][3] - mn1);
            ls0 += c[j][0] + c[j][1];
            ls1 += c[j][2] + c[j][3];
        }
        ls0 += __shfl_xor_sync(0xffffffffu, ls0, 1);
        ls0 += __shfl_xor_sync(0xffffffffu, ls0, 2);
        ls1 += __shfl_xor_sync(0xffffffffu, ls1, 1);
        ls1 += __shfl_xor_sync(0xffffffffu, ls1, 2);
        l0 = l0 * sc0 + ls0;
        l1 = l1 * sc1 + ls1;

        // rescale O
        #pragma unroll
        for (int nf = 0; nf < 16; nf++) {
            o[nf][0] *= sc0; o[nf][1] *= sc0;
            o[nf][2] *= sc1; o[nf][3] *= sc1;
        }

        // ---- pack P to fp16 hi/lo A-fragments ----
        uint32_t pah[4][4], pal[4][4];
        #pragma unroll
        for (int g = 0; g < 4; g++) {
            #pragma unroll
            for (int q = 0; q < 4; q++) {
                int j = 2 * g + (q >> 1);
                int e = (q & 1) * 2;
                float p0v = c[j][e], p1v = c[j][e + 1];
                __half h0 = __float2half_rn(p0v), h1 = __float2half_rn(p1v);
                pah[g][q] = pack_f16(h0, h1);
                __half r0 = __float2half_rn(p0v - __half2float(h0));
                __half r1 = __float2half_rn(p1v - __half2float(h1));
                pal[g][q] = pack_f16(r0, r1);
            }
        }

        // ---- O += P V: Ph*Vh + Pl*Vh (2-pass, V single fp16) ----
        #pragma unroll
        for (int g = 0; g < 4; g++) {
            #pragma unroll
            for (int vb = 0; vb < 8; vb++) {
                uint32_t vh4[4];
                ldsm_x4_t(vh4, Vb + (g * 16 + vrow) * AT_LDB + (vb * 16 + vcol) * 2);
                #pragma unroll
                for (int half = 0; half < 2; half++) {
                    int nf = vb * 2 + half;
                    mma16816h(o[nf], pah[g], &vh4[half * 2]);
                    mma16816h(o[nf], pal[g], &vh4[half * 2]);
                }
            }
        }
    }

    // ---- finalize: O/l, write ctx as fp16 hi/lo (for fp16 2-pass out GEMM) ----
    const float inv0 = 1.f / l0, inv1 = 1.f / l1;
    const int colb = h * DH + (lane & 3) * 2;
    #pragma unroll
    for (int nf = 0; nf < 16; nf++) {
        int col = colb + nf * 8;
        float v0 = o[nf][0] * inv0, v1 = o[nf][1] * inv0;
        float v2 = o[nf][2] * inv1, v3 = o[nf][3] * inv1;
        __half h0 = __float2half_rn(v0), h1 = __float2half_rn(v1);
        __half h2 = __float2half_rn(v2), h3 = __float2half_rn(v3);
        __half l0h = __float2half_rn(v0 - __half2float(h0));
        __half l1h = __float2half_rn(v1 - __half2float(h1));
        __half l2h = __float2half_rn(v2 - __half2float(h2));
        __half l3h = __float2half_rn(v3 - __half2float(h3));
        size_t g0 = (size_t)(b * S + r0g) * D + col;
        size_t g1 = (size_t)(b * S + r1g) * D + col;
        *(uint32_t*)(g_c16h + g0) = pack_f16(h0, h1);
        *(uint32_t*)(g_c16l + g0) = pack_f16(l0h, l1h);
        *(uint32_t*)(g_c16h + g1) = pack_f16(h2, h3);
        *(uint32_t*)(g_c16l + g1) = pack_f16(l2h, l3h);
    }
}

// ---------------------------------------------------------------------------
extern "C" void kernel_launch(void* const* d_in, const int* in_sizes, int n_in,
                              void* d_out, int out_size)
{
    const float* X  = (const float*)d_in[0];
    const float* Wq = (const float*)d_in[1];
    const float* bq = (const float*)d_in[2];
    const float* Wk = (const float*)d_in[3];
    const float* bk = (const float*)d_in[4];
    const float* Wv = (const float*)d_in[5];
    const float* bv = (const float*)d_in[6];
    const float* Wo = (const float*)d_in[7];
    const float* bo = (const float*)d_in[8];
    float* out = (float*)d_out;

    cudaFuncSetAttribute(attn_tc_kernel, cudaFuncAttributeMaxDynamicSharedMemorySize, ATTN_SMEM);
    cudaFuncSetAttribute(q_tc_gemm,   cudaFuncAttributeMaxDynamicSharedMemorySize, GEMM_SMEM3);
    cudaFuncSetAttribute(kv_tc_gemm,  cudaFuncAttributeMaxDynamicSharedMemorySize, GEMM_SMEM2);
    cudaFuncSetAttribute(out_tc_gemm, cudaFuncAttributeMaxDynamicSharedMemorySize, GEMM_SMEM3);

    split_x_kernel<<<(M * D / 4) / 256, 256>>>((const float4*)X);
    wsplit_kernel<<<dim3(D / 32, D / 32, 4), 256>>>(Wq, Wk, Wv, Wo);
    q_tc_gemm<<<dim3(D / 128, M / 128), 128, GEMM_SMEM3>>>(bq);
    kv_tc_gemm<<<dim3(D / 128, M / 128, 2), 128, GEMM_SMEM2>>>(bk, bv);
    attn_tc_kernel<<<dim3(S / 64, B * H), 128, ATTN_SMEM>>>();
    out_tc_gemm<<<dim3(D / 128, M / 128), 128, GEMM_SMEM3>>>(bo, out);
}

// round 10
// speedup vs baseline: 8.2323x; 1.3426x over previous
#include <cuda_runtime.h>
#include <cuda_bf16.h>
#include <cuda_fp16.h>
#include <math.h>
#include <cstdint>

// Problem constants
constexpr int B  = 4;
constexpr int S  = 2048;
constexpr int D  = 2048;
constexpr int H  = 16;
constexpr int DH = 128;
constexpr int M  = B * S;          // 8192 rows

// ---------------------------------------------------------------------------
// Scratch (allocation-free rule: device globals). fp16 everywhere.
// ---------------------------------------------------------------------------
__device__ __half g_x16[(size_t)M * D];
__device__ __half g_q16[(size_t)M * D];
__device__ __half g_k16[(size_t)M * D];
__device__ __half g_v16[(size_t)M * D];
__device__ __half g_c16h[(size_t)M * D];
__device__ __half g_c16l[(size_t)M * D];
__device__ __half g_wT16[(size_t)4 * D * D];   // [w][N][K] single fp16

// ---------------------------------------------------------------------------
// PTX helpers (sm_103 baseline: mma.sync + ldmatrix + cp.async only)
// ---------------------------------------------------------------------------
__device__ __forceinline__ uint32_t smem_u32(const void* p) {
    uint32_t a;
    asm("{ .reg .u64 t; cvta.to.shared.u64 t, %1; cvt.u32.u64 %0, t; }" : "=r"(a) : "l"(p));
    return a;
}

__device__ __forceinline__ void cp_async16(uint32_t dst, const void* src) {
    asm volatile("cp.async.cg.shared.global [%0], [%1], 16;" :: "r"(dst), "l"(src));
}
#define CP_COMMIT() asm volatile("cp.async.commit_group;" ::: "memory")
#define CP_WAIT0()  asm volatile("cp.async.wait_group 0;" ::: "memory")
#define CP_WAIT1()  asm volatile("cp.async.wait_group 1;" ::: "memory")

__device__ __forceinline__ void ldsm_x4(uint32_t* r, uint32_t addr) {
    asm volatile("ldmatrix.sync.aligned.m8n8.x4.shared.b16 {%0,%1,%2,%3}, [%4];"
        : "=r"(r[0]), "=r"(r[1]), "=r"(r[2]), "=r"(r[3]) : "r"(addr));
}
__device__ __forceinline__ void ldsm_x4_t(uint32_t* r, uint32_t addr) {
    asm volatile("ldmatrix.sync.aligned.m8n8.x4.trans.shared.b16 {%0,%1,%2,%3}, [%4];"
        : "=r"(r[0]), "=r"(r[1]), "=r"(r[2]), "=r"(r[3]) : "r"(addr));
}

__device__ __forceinline__ void mma16816h(float* c, const uint32_t* a, const uint32_t* b) {
    asm volatile("mma.sync.aligned.m16n8k16.row.col.f32.f16.f16.f32 "
        "{%0,%1,%2,%3}, {%4,%5,%6,%7}, {%8,%9}, {%0,%1,%2,%3};"
        : "+f"(c[0]), "+f"(c[1]), "+f"(c[2]), "+f"(c[3])
        : "r"(a[0]), "r"(a[1]), "r"(a[2]), "r"(a[3]), "r"(b[0]), "r"(b[1]));
}

__device__ __forceinline__ uint32_t pack_f16(__half lo, __half hi) {
    __half2 h2 = __halves2half2(lo, hi);
    return *(uint32_t*)&h2;
}

// fast 2^z for z <= 0 (quartic Taylor after rint reduction, err ~4e-5)
__device__ __forceinline__ float exp2_fast(float z) {
    z = fmaxf(z, -126.f);
    float fi = rintf(z);
    float f  = z - fi;
    float p  = 0.00961813f;
    p = fmaf(p, f, 0.0555041f);
    p = fmaf(p, f, 0.2402265f);
    p = fmaf(p, f, 0.6931472f);
    p = fmaf(p, f, 1.0f);
    int e = (int)fi;
    return p * __int_as_float((uint32_t)(e + 127) << 23);
}

// ---------------------------------------------------------------------------
// Conversion kernels
// ---------------------------------------------------------------------------
__global__ __launch_bounds__(256) void conv_x_kernel(const float4* __restrict__ in) {
    size_t i = (size_t)blockIdx.x * blockDim.x + threadIdx.x;
    float4 v = in[i];
    __half h[4] = {__float2half_rn(v.x), __float2half_rn(v.y),
                   __float2half_rn(v.z), __float2half_rn(v.w)};
    *(uint2*)(g_x16 + i * 4) = *(const uint2*)h;
}

// Weights: W [K][N] fp32 -> transposed single fp16 [N][K]
__global__ __launch_bounds__(256) void wsplit_kernel(const float* __restrict__ Wq,
                                                     const float* __restrict__ Wk,
                                                     const float* __restrict__ Wv,
                                                     const float* __restrict__ Wo) {
    __shared__ float tile[32][33];
    int z = blockIdx.z;
    const float* W = (z == 0) ? Wq : (z == 1) ? Wk : (z == 2) ? Wv : Wo;
    __half* oh = g_wT16 + (size_t)z * D * D;
    int n0 = blockIdx.x * 32, k0 = blockIdx.y * 32;
    int tx = threadIdx.x & 31, ty = threadIdx.x >> 5;
    #pragma unroll
    for (int i = 0; i < 4; i++) {
        int k = ty + i * 8;
        tile[k][tx] = W[(size_t)(k0 + k) * D + n0 + tx];
    }
    __syncthreads();
    #pragma unroll
    for (int i = 0; i < 4; i++) {
        int n = ty + i * 8;
        oh[(size_t)(n0 + n) * D + k0 + tx] = __float2half_rn(tile[tx][n]);
    }
}

// ---------------------------------------------------------------------------
// mma.sync fp16 GEMM. NT=3: 2-pass C=(Ah+Al)@B^T; NT=2: 1-pass C=Ah@B^T.
// 4 warps (2x2), warp tile 64x64, BK=32, 3-stage cp.async, ONE sync/iter.
// MODE: 0 = fp32 out, 1 = fp16 hi/lo out, 2 = fp16 single out
// ---------------------------------------------------------------------------
constexpr int BKG      = 32;
constexpr int LDT      = 40;                 // f16 stride per tile row (80 B)
constexpr int TILE_BY  = 128 * LDT * 2;      // 10240 B per tile
constexpr int NITER    = D / BKG;            // 64
constexpr int GEMM_SMEM3 = 3 * 3 * TILE_BY;  // 92160 B (2-pass)
constexpr int GEMM_SMEM2 = 3 * 2 * TILE_BY;  // 61440 B (1-pass)

template <int NT>
__device__ __forceinline__ void load_stage(uint32_t sbase,
                                           const __half* const* bases,
                                           int k0, int t) {
    #pragma unroll
    for (int i = 0; i < 4 * NT; i++) {
        const int tile = i >> 2;              // 4 slots per tile per thread
        int idx  = t + 128 * (i & 3);         // 0..511
        int row  = idx >> 2;                  // 0..127
        int chnk = idx & 3;                   // 16B chunk
        const __half* src = bases[tile] + (size_t)row * D + k0 + chnk * 8;
        uint32_t dst = sbase + tile * TILE_BY + row * (LDT * 2) + chnk * 16;
        cp_async16(dst, src);
    }
    CP_COMMIT();
}

template <int NT, int MODE>
__device__ __forceinline__ void tc_gemm_body(const __half* __restrict__ Ahp,
                                             const __half* __restrict__ Alp,
                                             const __half* __restrict__ Bhp,
                                             const float* __restrict__ bias,
                                             float* __restrict__ C,
                                             __half* __restrict__ Fh,
                                             __half* __restrict__ Fl) {
    constexpr int STAGE = NT * TILE_BY;
    extern __shared__ char smem[];
    const uint32_t sb = smem_u32(smem);
    const int t    = threadIdx.x;
    const int lane = t & 31;
    const int w    = t >> 5;
    const int wm   = (w & 1) * 64;
    const int wn   = (w >> 1) * 64;
    const int m0   = blockIdx.y * 128;
    const int n0   = blockIdx.x * 128;

    const __half* bases[3];
    bases[0] = Ahp + (size_t)m0 * D;
    bases[NT - 1] = Bhp + (size_t)n0 * D;
    if (NT == 3) bases[1] = Alp + (size_t)m0 * D;

    float acc[4][8][4];
    #pragma unroll
    for (int i = 0; i < 4; i++)
        #pragma unroll
        for (int j = 0; j < 8; j++)
            #pragma unroll
            for (int r = 0; r < 4; r++) acc[i][j][r] = 0.f;

    const int arow  = lane & 15;
    const int akoff = (lane >> 4) * 16;
    const int bn    = (lane & 7) + ((lane >> 4) << 3);
    const int bkoff = ((lane >> 3) & 1) * 16;

    load_stage<NT>(sb + 0 * STAGE, bases, 0, t);
    load_stage<NT>(sb + 1 * STAGE, bases, BKG, t);

    int bufc = 0;
    for (int c = 0; c < NITER; c++) {
        if (c + 1 < NITER) { CP_WAIT1(); } else { CP_WAIT0(); }
        __syncthreads();                       // stage c visible; buf (c+2)%3 free

        const uint32_t sbase = sb + bufc * STAGE;
        #pragma unroll
        for (int kk = 0; kk < 2; kk++) {
            const uint32_t kbyte = kk * 32;
            uint32_t ah[4][4], al[4][4];
            #pragma unroll
            for (int mf = 0; mf < 4; mf++) {
                uint32_t ad = sbase + (wm + mf * 16 + arow) * (LDT * 2) + kbyte + akoff;
                ldsm_x4(ah[mf], ad);
                if (NT == 3) ldsm_x4(al[mf], ad + TILE_BY);
            }
            #pragma unroll
            for (int nb = 0; nb < 4; nb++) {
                uint32_t bh4[4];
                uint32_t bd = sbase + (NT - 1) * TILE_BY + (wn + nb * 16 + bn) * (LDT * 2) + kbyte + bkoff;
                ldsm_x4(bh4, bd);
                #pragma unroll
                for (int mf = 0; mf < 4; mf++)
                    #pragma unroll
                    for (int half = 0; half < 2; half++) {
                        int nf = nb * 2 + half;
                        mma16816h(acc[mf][nf], ah[mf], &bh4[half * 2]);
                        if (NT == 3) mma16816h(acc[mf][nf], al[mf], &bh4[half * 2]);
                    }
            }
        }
        // Issue next-next stage AFTER compute; its buffer was last read at
        // iter c-1 and all warps passed this iter's barrier -> no hazard.
        if (c + 2 < NITER) {
            int bufn = bufc + 2; if (bufn >= 3) bufn -= 3;
            load_stage<NT>(sb + bufn * STAGE, bases, (c + 2) * BKG, t);
        }
        if (++bufc == 3) bufc = 0;
    }

    // Epilogue
    const int rbase = m0 + wm + (lane >> 2);
    const int cbase = n0 + wn + (lane & 3) * 2;
    #pragma unroll
    for (int mf = 0; mf < 4; mf++) {
        #pragma unroll
        for (int nf = 0; nf < 8; nf++) {
            int col = cbase + nf * 8;
            float2 bv = *(const float2*)(bias + col);
            int r0 = rbase + mf * 16;
            float v0 = acc[mf][nf][0] + bv.x, v1 = acc[mf][nf][1] + bv.y;
            float v2 = acc[mf][nf][2] + bv.x, v3 = acc[mf][nf][3] + bv.y;
            if (MODE == 0) {
                float2 o0 = {v0, v1}, o1 = {v2, v3};
                *(float2*)(C + (size_t)r0 * D + col)       = o0;
                *(float2*)(C + (size_t)(r0 + 8) * D + col) = o1;
            } else {
                __half h0 = __float2half_rn(v0), h1 = __float2half_rn(v1);
                __half h2 = __float2half_rn(v2), h3 = __float2half_rn(v3);
                *(uint32_t*)(Fh + (size_t)r0 * D + col)       = pack_f16(h0, h1);
                *(uint32_t*)(Fh + (size_t)(r0 + 8) * D + col) = pack_f16(h2, h3);
                if (MODE == 1) {
                    __half l0 = __float2half_rn(v0 - __half2float(h0));
                    __half l1 = __float2half_rn(v1 - __half2float(h1));
                    __half l2 = __float2half_rn(v2 - __half2float(h2));
                    __half l3 = __float2half_rn(v3 - __half2float(h3));
                    *(uint32_t*)(Fl + (size_t)r0 * D + col)       = pack_f16(l0, l1);
                    *(uint32_t*)(Fl + (size_t)(r0 + 8) * D + col) = pack_f16(l2, l3);
                }
            }
        }
    }
}

// Q/K/V projections: all 1-pass fp16 (attention consumes single fp16 q/k/v)
__global__ __launch_bounds__(128, 2) void qkv_tc_gemm(const float* __restrict__ bq,
                                                      const float* __restrict__ bk,
                                                      const float* __restrict__ bv) {
    const int z = blockIdx.z;
    const __half* W = g_wT16 + (size_t)z * D * D;
    const float* bias = (z == 0) ? bq : (z == 1) ? bk : bv;
    __half* Out = (z == 0) ? g_q16 : (z == 1) ? g_k16 : g_v16;
    tc_gemm_body<2, 2>(g_x16, nullptr, W, bias, nullptr, Out, nullptr);
}

// Output projection: 2-pass (ctx hi/lo), fp32 out
__global__ __launch_bounds__(128, 2) void out_tc_gemm(const float* __restrict__ bo,
                                                      float* __restrict__ out) {
    tc_gemm_body<3, 0>(g_c16h, g_c16l, g_wT16 + (size_t)3 * D * D,
                       bo, out, nullptr, nullptr);
}

// ---------------------------------------------------------------------------
// Tensor-core flash attention (fp16, causal). Br=Bc=64, 128 threads.
// Q/K/V single fp16; QK single-pass; PV 2-pass (P hi/lo, exact-ish weights).
// K/V double-buffered in smem; Q in registers.
// ---------------------------------------------------------------------------
constexpr int AT_LDB   = 272;                    // bytes per tile row (128 f16 + pad)
constexpr int AT_TILE  = 64 * AT_LDB;            // 17408 B
constexpr int ATTN_SMEM = 5 * AT_TILE;           // Qh + (Kh,Vh)x2 = 87040 B
constexpr float SCALE_LOG2E = 0.12751650f;       // (1/sqrt(128)) * log2(e)

__global__ __launch_bounds__(128, 2) void attn_tc_kernel() {
    extern __shared__ char sm8[];
    const uint32_t sb  = smem_u32(sm8);
    const uint32_t Qh  = sb;
    const uint32_t KV0 = sb + 1 * AT_TILE;       // Kh then Vh
    const uint32_t KV1 = sb + 3 * AT_TILE;

    const int t    = threadIdx.x;
    const int lane = t & 31;
    const int w    = t >> 5;
    const int iq   = (gridDim.x - 1) - blockIdx.x;      // big blocks first
    const int bh   = blockIdx.y;
    const int b    = bh >> 4;
    const int h    = bh & 15;
    const int q0   = iq * 64;
    const int wq   = w * 16;

    // ldmatrix lane offsets
    const int arow  = lane & 15;
    const int akoff = (lane >> 4) * 16;
    const int bn    = (lane & 7) + ((lane >> 4) << 3);
    const int bkoff = ((lane >> 3) & 1) * 16;
    const int vrow  = lane & 15;
    const int vcol  = (lane >> 4) << 3;

    // ---- Load Q tile, hoist to registers ----
    {
        #pragma unroll
        for (int i = 0; i < 8; i++) {
            int idx  = t + 128 * i;
            int row  = idx >> 4;
            int chnk = idx & 15;
            size_t g = (size_t)(b * S + q0 + row) * D + h * DH + chnk * 8;
            uint32_t so = row * AT_LDB + chnk * 16;
            cp_async16(Qh + so, g_q16 + g);
        }
        CP_COMMIT();
        CP_WAIT0();
        __syncthreads();
    }
    uint32_t qhr[8][4];
    #pragma unroll
    for (int kt = 0; kt < 8; kt++) {
        uint32_t ad = Qh + (wq + arow) * AT_LDB + kt * 32 + akoff;
        ldsm_x4(qhr[kt], ad);
    }

    // ---- Preload K/V block 0 into buffer 0 ----
    {
        #pragma unroll
        for (int i = 0; i < 8; i++) {
            int idx  = t + 128 * i;
            int row  = idx >> 4;
            int chnk = idx & 15;
            size_t g = (size_t)(b * S + row) * D + h * DH + chnk * 8;
            uint32_t so = row * AT_LDB + chnk * 16;
            cp_async16(KV0 + so, g_k16 + g);
            cp_async16(KV0 + AT_TILE + so, g_v16 + g);
        }
        CP_COMMIT();
    }

    float o[16][4];
    #pragma unroll
    for (int i = 0; i < 16; i++)
        #pragma unroll
        for (int r = 0; r < 4; r++) o[i][r] = 0.f;
    float m0 = -1e30f, m1 = -1e30f, l0 = 0.f, l1 = 0.f;

    const int r0g = q0 + wq + (lane >> 2);
    const int r1g = r0g + 8;

    for (int jb = 0; jb <= iq; jb++) {
        __syncthreads();   // all warps done reading buffer (jb+1)&1 (iter jb-1)
        if (jb + 1 <= iq) {
            const int kn = (jb + 1) * 64;
            const uint32_t buf = ((jb + 1) & 1) ? KV1 : KV0;
            #pragma unroll
            for (int i = 0; i < 8; i++) {
                int idx  = t + 128 * i;
                int row  = idx >> 4;
                int chnk = idx & 15;
                size_t g = (size_t)(b * S + kn + row) * D + h * DH + chnk * 8;
                uint32_t so = row * AT_LDB + chnk * 16;
                cp_async16(buf + so, g_k16 + g);
                cp_async16(buf + AT_TILE + so, g_v16 + g);
            }
            CP_COMMIT();
            CP_WAIT1();    // block jb's loads (issued last iter) complete
        } else {
            CP_WAIT0();
        }
        __syncthreads();

        const uint32_t Kb = (jb & 1) ? KV1 : KV0;
        const uint32_t Vb = Kb + AT_TILE;
        const int k0 = jb * 64;

        // ---- S = Q K^T (single pass, fp16) ----
        float c[8][4];
        #pragma unroll
        for (int j = 0; j < 8; j++)
            #pragma unroll
            for (int r = 0; r < 4; r++) c[j][r] = 0.f;

        #pragma unroll
        for (int kt = 0; kt < 8; kt++) {
            #pragma unroll
            for (int nb = 0; nb < 4; nb++) {
                uint32_t kh4[4];
                ldsm_x4(kh4, Kb + (nb * 16 + bn) * AT_LDB + kt * 32 + bkoff);
                #pragma unroll
                for (int half = 0; half < 2; half++) {
                    int nf = nb * 2 + half;
                    mma16816h(c[nf], qhr[kt], &kh4[half * 2]);
                }
            }
        }

        // ---- scale + causal mask ----
        const bool diag = (jb == iq);
        #pragma unroll
        for (int j = 0; j < 8; j++) {
            int cc = k0 + j * 8 + (lane & 3) * 2;
            #pragma unroll
            for (int r = 0; r < 4; r++) {
                float v = c[j][r] * SCALE_LOG2E;
                if (diag) {
                    int col = cc + (r & 1);
                    int row = (r < 2) ? r0g : r1g;
                    if (col > row) v = -1e30f;
                }
                c[j][r] = v;
            }
        }

        // ---- online softmax (log2 domain) ----
        float mx0 = -1e30f, mx1 = -1e30f;
        #pragma unroll
        for (int j = 0; j < 8; j++) {
            mx0 = fmaxf(mx0, fmaxf(c[j][0], c[j][1]));
            mx1 = fmaxf(mx1, fmaxf(c[j][2], c[j][3]));
        }
        mx0 = fmaxf(mx0, __shfl_xor_sync(0xffffffffu, mx0, 1));
        mx0 = fmaxf(mx0, __shfl_xor_sync(0xffffffffu, mx0, 2));
        mx1 = fmaxf(mx1, __shfl_xor_sync(0xffffffffu, mx1, 1));
        mx1 = fmaxf(mx1, __shfl_xor_sync(0xffffffffu, mx1, 2));
        float mn0 = fmaxf(m0, mx0), mn1 = fmaxf(m1, mx1);
        float sc0 = exp2_fast(m0 - mn0), sc1 = exp2_fast(m1 - mn1);
        m0 = mn0; m1 = mn1;

        float ls0 = 0.f, ls1 = 0.f;
        #pragma unroll
        for (int j = 0; j < 8; j++) {
            c[j][0] = exp2_fast(c[j][0] - mn0);
            c[j][1] = exp2_fast(c[j][1] - mn0);
            c[j][2] = exp2_fast(c[j][2] - mn1);
            c[j][3] = exp2_fast(c[j][3] - mn1);
            ls0 += c[j][0] + c[j][1];
            ls1 += c[j][2] + c[j][3];
        }
        ls0 += __shfl_xor_sync(0xffffffffu, ls0, 1);
        ls0 += __shfl_xor_sync(0xffffffffu, ls0, 2);
        ls1 += __shfl_xor_sync(0xffffffffu, ls1, 1);
        ls1 += __shfl_xor_sync(0xffffffffu, ls1, 2);
        l0 = l0 * sc0 + ls0;
        l1 = l1 * sc1 + ls1;

        // rescale O
        #pragma unroll
        for (int nf = 0; nf < 16; nf++) {
            o[nf][0] *= sc0; o[nf][1] *= sc0;
            o[nf][2] *= sc1; o[nf][3] *= sc1;
        }

        // ---- pack P to fp16 hi/lo A-fragments ----
        uint32_t pah[4][4], pal[4][4];
        #pragma unroll
        for (int g = 0; g < 4; g++) {
            #pragma unroll
            for (int q = 0; q < 4; q++) {
                int j = 2 * g + (q >> 1);
                int e = (q & 1) * 2;
                float p0v = c[j][e], p1v = c[j][e + 1];
                __half h0 = __float2half_rn(p0v), h1 = __float2half_rn(p1v);
                pah[g][q] = pack_f16(h0, h1);
                __half r0 = __float2half_rn(p0v - __half2float(h0));
                __half r1 = __float2half_rn(p1v - __half2float(h1));
                pal[g][q] = pack_f16(r0, r1);
            }
        }

        // ---- O += P V: Ph*Vh + Pl*Vh (2-pass, V single fp16) ----
        #pragma unroll
        for (int g = 0; g < 4; g++) {
            #pragma unroll
            for (int vb = 0; vb < 8; vb++) {
                uint32_t vh4[4];
                ldsm_x4_t(vh4, Vb + (g * 16 + vrow) * AT_LDB + (vb * 16 + vcol) * 2);
                #pragma unroll
                for (int half = 0; half < 2; half++) {
                    int nf = vb * 2 + half;
                    mma16816h(o[nf], pah[g], &vh4[half * 2]);
                    mma16816h(o[nf], pal[g], &vh4[half * 2]);
                }
            }
        }
    }

    // ---- finalize: O/l, write ctx as fp16 hi/lo (for fp16 2-pass out GEMM) ----
    const float inv0 = 1.f / l0, inv1 = 1.f / l1;
    const int colb = h * DH + (lane & 3) * 2;
    #pragma unroll
    for (int nf = 0; nf < 16; nf++) {
        int col = colb + nf * 8;
        float v0 = o[nf][0] * inv0, v1 = o[nf][1] * inv0;
        float v2 = o[nf][2] * inv1, v3 = o[nf][3] * inv1;
        __half h0 = __float2half_rn(v0), h1 = __float2half_rn(v1);
        __half h2 = __float2half_rn(v2), h3 = __float2half_rn(v3);
        __half l0h = __float2half_rn(v0 - __half2float(h0));
        __half l1h = __float2half_rn(v1 - __half2float(h1));
        __half l2h = __float2half_rn(v2 - __half2float(h2));
        __half l3h = __float2half_rn(v3 - __half2float(h3));
        size_t g0 = (size_t)(b * S + r0g) * D + col;
        size_t g1 = (size_t)(b * S + r1g) * D + col;
        *(uint32_t*)(g_c16h + g0) = pack_f16(h0, h1);
        *(uint32_t*)(g_c16l + g0) = pack_f16(l0h, l1h);
        *(uint32_t*)(g_c16h + g1) = pack_f16(h2, h3);
        *(uint32_t*)(g_c16l + g1) = pack_f16(l2h, l3h);
    }
}

// ---------------------------------------------------------------------------
extern "C" void kernel_launch(void* const* d_in, const int* in_sizes, int n_in,
                              void* d_out, int out_size)
{
    const float* X  = (const float*)d_in[0];
    const float* Wq = (const float*)d_in[1];
    const float* bq = (const float*)d_in[2];
    const float* Wk = (const float*)d_in[3];
    const float* bk = (const float*)d_in[4];
    const float* Wv = (const float*)d_in[5];
    const float* bv = (const float*)d_in[6];
    const float* Wo = (const float*)d_in[7];
    const float* bo = (const float*)d_in[8];
    float* out = (float*)d_out;

    cudaFuncSetAttribute(attn_tc_kernel, cudaFuncAttributeMaxDynamicSharedMemorySize, ATTN_SMEM);
    cudaFuncSetAttribute(qkv_tc_gemm, cudaFuncAttributeMaxDynamicSharedMemorySize, GEMM_SMEM2);
    cudaFuncSetAttribute(out_tc_gemm, cudaFuncAttributeMaxDynamicSharedMemorySize, GEMM_SMEM3);

    conv_x_kernel<<<(M * D / 4) / 256, 256>>>((const float4*)X);
    wsplit_kernel<<<dim3(D / 32, D / 32, 4), 256>>>(Wq, Wk, Wv, Wo);
    qkv_tc_gemm<<<dim3(D / 128, M / 128, 3), 128, GEMM_SMEM2>>>(bq, bk, bv);
    attn_tc_kernel<<<dim3(S / 64, B * H), 128, ATTN_SMEM>>>();
    out_tc_gemm<<<dim3(D / 128, M / 128), 128, GEMM_SMEM3>>>(bo, out);
}

// round 11
// speedup vs baseline: 8.6192x; 1.0470x over previous
#include <cuda_runtime.h>
#include <cuda_bf16.h>
#include <cuda_fp16.h>
#include <math.h>
#include <cstdint>

// Problem constants
constexpr int B  = 4;
constexpr int S  = 2048;
constexpr int D  = 2048;
constexpr int H  = 16;
constexpr int DH = 128;
constexpr int M  = B * S;          // 8192 rows

// ---------------------------------------------------------------------------
// Scratch (allocation-free rule: device globals). fp16 everywhere.
// ---------------------------------------------------------------------------
__device__ __half g_x16[(size_t)M * D];
__device__ __half g_q16[(size_t)M * D];
__device__ __half g_k16[(size_t)M * D];
__device__ __half g_v16[(size_t)M * D];
__device__ __half g_c16h[(size_t)M * D];
__device__ __half g_c16l[(size_t)M * D];
__device__ __half g_wT16[(size_t)4 * D * D];   // [w][N][K] single fp16

// ---------------------------------------------------------------------------
// PTX helpers (sm_103 baseline: mma.sync + ldmatrix + cp.async only)
// ---------------------------------------------------------------------------
__device__ __forceinline__ uint32_t smem_u32(const void* p) {
    uint32_t a;
    asm("{ .reg .u64 t; cvta.to.shared.u64 t, %1; cvt.u32.u64 %0, t; }" : "=r"(a) : "l"(p));
    return a;
}

__device__ __forceinline__ void cp_async16(uint32_t dst, const void* src) {
    asm volatile("cp.async.cg.shared.global [%0], [%1], 16;" :: "r"(dst), "l"(src));
}
#define CP_COMMIT() asm volatile("cp.async.commit_group;" ::: "memory")
#define CP_WAIT0()  asm volatile("cp.async.wait_group 0;" ::: "memory")
#define CP_WAIT1()  asm volatile("cp.async.wait_group 1;" ::: "memory")

__device__ __forceinline__ void ldsm_x4(uint32_t* r, uint32_t addr) {
    asm volatile("ldmatrix.sync.aligned.m8n8.x4.shared.b16 {%0,%1,%2,%3}, [%4];"
        : "=r"(r[0]), "=r"(r[1]), "=r"(r[2]), "=r"(r[3]) : "r"(addr));
}
__device__ __forceinline__ void ldsm_x4_t(uint32_t* r, uint32_t addr) {
    asm volatile("ldmatrix.sync.aligned.m8n8.x4.trans.shared.b16 {%0,%1,%2,%3}, [%4];"
        : "=r"(r[0]), "=r"(r[1]), "=r"(r[2]), "=r"(r[3]) : "r"(addr));
}

__device__ __forceinline__ void mma16816h(float* c, const uint32_t* a, const uint32_t* b) {
    asm volatile("mma.sync.aligned.m16n8k16.row.col.f32.f16.f16.f32 "
        "{%0,%1,%2,%3}, {%4,%5,%6,%7}, {%8,%9}, {%0,%1,%2,%3};"
        : "+f"(c[0]), "+f"(c[1]), "+f"(c[2]), "+f"(c[3])
        : "r"(a[0]), "r"(a[1]), "r"(a[2]), "r"(a[3]), "r"(b[0]), "r"(b[1]));
}

__device__ __forceinline__ uint32_t pack_f16(__half lo, __half hi) {
    __half2 h2 = __halves2half2(lo, hi);
    return *(uint32_t*)&h2;
}

// fast 2^z for z <= 0 (quartic Taylor after rint reduction, err ~4e-5)
__device__ __forceinline__ float exp2_fast(float z) {
    z = fmaxf(z, -126.f);
    float fi = rintf(z);
    float f  = z - fi;
    float p  = 0.00961813f;
    p = fmaf(p, f, 0.0555041f);
    p = fmaf(p, f, 0.2402265f);
    p = fmaf(p, f, 0.6931472f);
    p = fmaf(p, f, 1.0f);
    int e = (int)fi;
    return p * __int_as_float((uint32_t)(e + 127) << 23);
}

// ---------------------------------------------------------------------------
// Conversion kernels
// ---------------------------------------------------------------------------
__global__ __launch_bounds__(256) void conv_x_kernel(const float4* __restrict__ in) {
    size_t i = (size_t)blockIdx.x * blockDim.x + threadIdx.x;
    float4 v = in[i];
    __half h[4] = {__float2half_rn(v.x), __float2half_rn(v.y),
                   __float2half_rn(v.z), __float2half_rn(v.w)};
    *(uint2*)(g_x16 + i * 4) = *(const uint2*)h;
}

// Weights: W [K][N] fp32 -> transposed single fp16 [N][K]
__global__ __launch_bounds__(256) void wsplit_kernel(const float* __restrict__ Wq,
                                                     const float* __restrict__ Wk,
                                                     const float* __restrict__ Wv,
                                                     const float* __restrict__ Wo) {
    __shared__ float tile[32][33];
    int z = blockIdx.z;
    const float* W = (z == 0) ? Wq : (z == 1) ? Wk : (z == 2) ? Wv : Wo;
    __half* oh = g_wT16 + (size_t)z * D * D;
    int n0 = blockIdx.x * 32, k0 = blockIdx.y * 32;
    int tx = threadIdx.x & 31, ty = threadIdx.x >> 5;
    #pragma unroll
    for (int i = 0; i < 4; i++) {
        int k = ty + i * 8;
        tile[k][tx] = W[(size_t)(k0 + k) * D + n0 + tx];
    }
    __syncthreads();
    #pragma unroll
    for (int i = 0; i < 4; i++) {
        int n = ty + i * 8;
        oh[(size_t)(n0 + n) * D + k0 + tx] = __float2half_rn(tile[tx][n]);
    }
}

// ---------------------------------------------------------------------------
// mma.sync fp16 GEMM. NT=3: 2-pass C=(Ah+Al)@B^T; NT=2: 1-pass C=Ah@B^T.
// 4 warps (2x2), warp tile 64x64, BK=32, 3-stage cp.async, ONE sync/iter.
// MODE: 0 = fp32 out, 1 = fp16 hi/lo out, 2 = fp16 single out
// ---------------------------------------------------------------------------
constexpr int BKG      = 32;
constexpr int LDT      = 40;                 // f16 stride per tile row (80 B)
constexpr int TILE_BY  = 128 * LDT * 2;      // 10240 B per tile
constexpr int NITER    = D / BKG;            // 64
constexpr int GEMM_SMEM3 = 3 * 3 * TILE_BY;  // 92160 B (2-pass)
constexpr int GEMM_SMEM2 = 3 * 2 * TILE_BY;  // 61440 B (1-pass)

template <int NT>
__device__ __forceinline__ void load_stage(uint32_t sbase,
                                           const __half* const* bases,
                                           int k0, int t) {
    #pragma unroll
    for (int i = 0; i < 4 * NT; i++) {
        const int tile = i >> 2;              // 4 slots per tile per thread
        int idx  = t + 128 * (i & 3);         // 0..511
        int row  = idx >> 2;                  // 0..127
        int chnk = idx & 3;                   // 16B chunk
        const __half* src = bases[tile] + (size_t)row * D + k0 + chnk * 8;
        uint32_t dst = sbase + tile * TILE_BY + row * (LDT * 2) + chnk * 16;
        cp_async16(dst, src);
    }
    CP_COMMIT();
}

template <int NT, int MODE>
__device__ __forceinline__ void tc_gemm_body(const __half* __restrict__ Ahp,
                                             const __half* __restrict__ Alp,
                                             const __half* __restrict__ Bhp,
                                             const float* __restrict__ bias,
                                             float* __restrict__ C,
                                             __half* __restrict__ Fh,
                                             __half* __restrict__ Fl) {
    constexpr int STAGE = NT * TILE_BY;
    extern __shared__ char smem[];
    const uint32_t sb = smem_u32(smem);
    const int t    = threadIdx.x;
    const int lane = t & 31;
    const int w    = t >> 5;
    const int wm   = (w & 1) * 64;
    const int wn   = (w >> 1) * 64;
    const int m0   = blockIdx.y * 128;
    const int n0   = blockIdx.x * 128;

    const __half* bases[3];
    bases[0] = Ahp + (size_t)m0 * D;
    bases[NT - 1] = Bhp + (size_t)n0 * D;
    if (NT == 3) bases[1] = Alp + (size_t)m0 * D;

    float acc[4][8][4];
    #pragma unroll
    for (int i = 0; i < 4; i++)
        #pragma unroll
        for (int j = 0; j < 8; j++)
            #pragma unroll
            for (int r = 0; r < 4; r++) acc[i][j][r] = 0.f;

    const int arow  = lane & 15;
    const int akoff = (lane >> 4) * 16;
    const int bn    = (lane & 7) + ((lane >> 4) << 3);
    const int bkoff = ((lane >> 3) & 1) * 16;

    load_stage<NT>(sb + 0 * STAGE, bases, 0, t);
    load_stage<NT>(sb + 1 * STAGE, bases, BKG, t);

    int bufc = 0;
    for (int c = 0; c < NITER; c++) {
        if (c + 1 < NITER) { CP_WAIT1(); } else { CP_WAIT0(); }
        __syncthreads();                       // stage c visible; buf (c+2)%3 free

        const uint32_t sbase = sb + bufc * STAGE;
        #pragma unroll
        for (int kk = 0; kk < 2; kk++) {
            const uint32_t kbyte = kk * 32;
            uint32_t ah[4][4], al[4][4];
            #pragma unroll
            for (int mf = 0; mf < 4; mf++) {
                uint32_t ad = sbase + (wm + mf * 16 + arow) * (LDT * 2) + kbyte + akoff;
                ldsm_x4(ah[mf], ad);
                if (NT == 3) ldsm_x4(al[mf], ad + TILE_BY);
            }
            #pragma unroll
            for (int nb = 0; nb < 4; nb++) {
                uint32_t bh4[4];
                uint32_t bd = sbase + (NT - 1) * TILE_BY + (wn + nb * 16 + bn) * (LDT * 2) + kbyte + bkoff;
                ldsm_x4(bh4, bd);
                #pragma unroll
                for (int mf = 0; mf < 4; mf++)
                    #pragma unroll
                    for (int half = 0; half < 2; half++) {
                        int nf = nb * 2 + half;
                        mma16816h(acc[mf][nf], ah[mf], &bh4[half * 2]);
                        if (NT == 3) mma16816h(acc[mf][nf], al[mf], &bh4[half * 2]);
                    }
            }
        }
        // Issue next-next stage AFTER compute; its buffer was last read at
        // iter c-1 and all warps passed this iter's barrier -> no hazard.
        if (c + 2 < NITER) {
            int bufn = bufc + 2; if (bufn >= 3) bufn -= 3;
            load_stage<NT>(sb + bufn * STAGE, bases, (c + 2) * BKG, t);
        }
        if (++bufc == 3) bufc = 0;
    }

    // Epilogue
    const int rbase = m0 + wm + (lane >> 2);
    const int cbase = n0 + wn + (lane & 3) * 2;
    #pragma unroll
    for (int mf = 0; mf < 4; mf++) {
        #pragma unroll
        for (int nf = 0; nf < 8; nf++) {
            int col = cbase + nf * 8;
            float2 bv = *(const float2*)(bias + col);
            int r0 = rbase + mf * 16;
            float v0 = acc[mf][nf][0] + bv.x, v1 = acc[mf][nf][1] + bv.y;
            float v2 = acc[mf][nf][2] + bv.x, v3 = acc[mf][nf][3] + bv.y;
            if (MODE == 0) {
                float2 o0 = {v0, v1}, o1 = {v2, v3};
                *(float2*)(C + (size_t)r0 * D + col)       = o0;
                *(float2*)(C + (size_t)(r0 + 8) * D + col) = o1;
            } else {
                __half h0 = __float2half_rn(v0), h1 = __float2half_rn(v1);
                __half h2 = __float2half_rn(v2), h3 = __float2half_rn(v3);
                *(uint32_t*)(Fh + (size_t)r0 * D + col)       = pack_f16(h0, h1);
                *(uint32_t*)(Fh + (size_t)(r0 + 8) * D + col) = pack_f16(h2, h3);
                if (MODE == 1) {
                    __half l0 = __float2half_rn(v0 - __half2float(h0));
                    __half l1 = __float2half_rn(v1 - __half2float(h1));
                    __half l2 = __float2half_rn(v2 - __half2float(h2));
                    __half l3 = __float2half_rn(v3 - __half2float(h3));
                    *(uint32_t*)(Fl + (size_t)r0 * D + col)       = pack_f16(l0, l1);
                    *(uint32_t*)(Fl + (size_t)(r0 + 8) * D + col) = pack_f16(l2, l3);
                }
            }
        }
    }
}

// Q/K/V projections: all 1-pass fp16 (attention consumes single fp16 q/k/v)
__global__ __launch_bounds__(128, 2) void qkv_tc_gemm(const float* __restrict__ bq,
                                                      const float* __restrict__ bk,
                                                      const float* __restrict__ bv) {
    const int z = blockIdx.z;
    const __half* W = g_wT16 + (size_t)z * D * D;
    const float* bias = (z == 0) ? bq : (z == 1) ? bk : bv;
    __half* Out = (z == 0) ? g_q16 : (z == 1) ? g_k16 : g_v16;
    tc_gemm_body<2, 2>(g_x16, nullptr, W, bias, nullptr, Out, nullptr);
}

// Output projection: 2-pass (ctx hi/lo), fp32 out
__global__ __launch_bounds__(128, 2) void out_tc_gemm(const float* __restrict__ bo,
                                                      float* __restrict__ out) {
    tc_gemm_body<3, 0>(g_c16h, g_c16l, g_wT16 + (size_t)3 * D * D,
                       bo, out, nullptr, nullptr);
}

// ---------------------------------------------------------------------------
// Tensor-core flash attention (fp16, causal). Br=Bc=64, 128 threads.
// Q/K/V/P all single fp16 (calibrated error budget); ctx out stays hi/lo.
// K/V double-buffered in smem; Q in registers.
// ---------------------------------------------------------------------------
constexpr int AT_LDB   = 272;                    // bytes per tile row (128 f16 + pad)
constexpr int AT_TILE  = 64 * AT_LDB;            // 17408 B
constexpr int ATTN_SMEM = 5 * AT_TILE;           // Qh + (Kh,Vh)x2 = 87040 B
constexpr float SCALE_LOG2E = 0.12751650f;       // (1/sqrt(128)) * log2(e)

__global__ __launch_bounds__(128, 2) void attn_tc_kernel() {
    extern __shared__ char sm8[];
    const uint32_t sb  = smem_u32(sm8);
    const uint32_t Qh  = sb;
    const uint32_t KV0 = sb + 1 * AT_TILE;       // Kh then Vh
    const uint32_t KV1 = sb + 3 * AT_TILE;

    const int t    = threadIdx.x;
    const int lane = t & 31;
    const int w    = t >> 5;
    const int iq   = (gridDim.x - 1) - blockIdx.x;      // big blocks first
    const int bh   = blockIdx.y;
    const int b    = bh >> 4;
    const int h    = bh & 15;
    const int q0   = iq * 64;
    const int wq   = w * 16;

    // ldmatrix lane offsets
    const int arow  = lane & 15;
    const int akoff = (lane >> 4) * 16;
    const int bn    = (lane & 7) + ((lane >> 4) << 3);
    const int bkoff = ((lane >> 3) & 1) * 16;
    const int vrow  = lane & 15;
    const int vcol  = (lane >> 4) << 3;

    // ---- Load Q tile, hoist to registers ----
    {
        #pragma unroll
        for (int i = 0; i < 8; i++) {
            int idx  = t + 128 * i;
            int row  = idx >> 4;
            int chnk = idx & 15;
            size_t g = (size_t)(b * S + q0 + row) * D + h * DH + chnk * 8;
            uint32_t so = row * AT_LDB + chnk * 16;
            cp_async16(Qh + so, g_q16 + g);
        }
        CP_COMMIT();
        CP_WAIT0();
        __syncthreads();
    }
    uint32_t qhr[8][4];
    #pragma unroll
    for (int kt = 0; kt < 8; kt++) {
        uint32_t ad = Qh + (wq + arow) * AT_LDB + kt * 32 + akoff;
        ldsm_x4(qhr[kt], ad);
    }

    // ---- Preload K/V block 0 into buffer 0 ----
    {
        #pragma unroll
        for (int i = 0; i < 8; i++) {
            int idx  = t + 128 * i;
            int row  = idx >> 4;
            int chnk = idx & 15;
            size_t g = (size_t)(b * S + row) * D + h * DH + chnk * 8;
            uint32_t so = row * AT_LDB + chnk * 16;
            cp_async16(KV0 + so, g_k16 + g);
            cp_async16(KV0 + AT_TILE + so, g_v16 + g);
        }
        CP_COMMIT();
    }

    float o[16][4];
    #pragma unroll
    for (int i = 0; i < 16; i++)
        #pragma unroll
        for (int r = 0; r < 4; r++) o[i][r] = 0.f;
    float m0 = -1e30f, m1 = -1e30f, l0 = 0.f, l1 = 0.f;

    const int r0g = q0 + wq + (lane >> 2);
    const int r1g = r0g + 8;

    for (int jb = 0; jb <= iq; jb++) {
        __syncthreads();   // all warps done reading buffer (jb+1)&1 (iter jb-1)
        if (jb + 1 <= iq) {
            const int kn = (jb + 1) * 64;
            const uint32_t buf = ((jb + 1) & 1) ? KV1 : KV0;
            #pragma unroll
            for (int i = 0; i < 8; i++) {
                int idx  = t + 128 * i;
                int row  = idx >> 4;
                int chnk = idx & 15;
                size_t g = (size_t)(b * S + kn + row) * D + h * DH + chnk * 8;
                uint32_t so = row * AT_LDB + chnk * 16;
                cp_async16(buf + so, g_k16 + g);
                cp_async16(buf + AT_TILE + so, g_v16 + g);
            }
            CP_COMMIT();
            CP_WAIT1();    // block jb's loads (issued last iter) complete
        } else {
            CP_WAIT0();
        }
        __syncthreads();

        const uint32_t Kb = (jb & 1) ? KV1 : KV0;
        const uint32_t Vb = Kb + AT_TILE;
        const int k0 = jb * 64;

        // ---- S = Q K^T (single pass, fp16) ----
        float c[8][4];
        #pragma unroll
        for (int j = 0; j < 8; j++)
            #pragma unroll
            for (int r = 0; r < 4; r++) c[j][r] = 0.f;

        #pragma unroll
        for (int kt = 0; kt < 8; kt++) {
            #pragma unroll
            for (int nb = 0; nb < 4; nb++) {
                uint32_t kh4[4];
                ldsm_x4(kh4, Kb + (nb * 16 + bn) * AT_LDB + kt * 32 + bkoff);
                #pragma unroll
                for (int half = 0; half < 2; half++) {
                    int nf = nb * 2 + half;
                    mma16816h(c[nf], qhr[kt], &kh4[half * 2]);
                }
            }
        }

        // ---- scale + causal mask ----
        const bool diag = (jb == iq);
        #pragma unroll
        for (int j = 0; j < 8; j++) {
            int cc = k0 + j * 8 + (lane & 3) * 2;
            #pragma unroll
            for (int r = 0; r < 4; r++) {
                float v = c[j][r] * SCALE_LOG2E;
                if (diag) {
                    int col = cc + (r & 1);
                    int row = (r < 2) ? r0g : r1g;
                    if (col > row) v = -1e30f;
                }
                c[j][r] = v;
            }
        }

        // ---- online softmax (log2 domain) ----
        float mx0 = -1e30f, mx1 = -1e30f;
        #pragma unroll
        for (int j = 0; j < 8; j++) {
            mx0 = fmaxf(mx0, fmaxf(c[j][0], c[j][1]));
            mx1 = fmaxf(mx1, fmaxf(c[j][2], c[j][3]));
        }
        mx0 = fmaxf(mx0, __shfl_xor_sync(0xffffffffu, mx0, 1));
        mx0 = fmaxf(mx0, __shfl_xor_sync(0xffffffffu, mx0, 2));
        mx1 = fmaxf(mx1, __shfl_xor_sync(0xffffffffu, mx1, 1));
        mx1 = fmaxf(mx1, __shfl_xor_sync(0xffffffffu, mx1, 2));
        float mn0 = fmaxf(m0, mx0), mn1 = fmaxf(m1, mx1);
        float sc0 = exp2_fast(m0 - mn0), sc1 = exp2_fast(m1 - mn1);
        m0 = mn0; m1 = mn1;

        float ls0 = 0.f, ls1 = 0.f;
        uint32_t pah[4][4];
        #pragma unroll
        for (int j = 0; j < 8; j++) {
            c[j][0] = exp2_fast(c[j][0] - mn0);
            c[j][1] = exp2_fast(c[j][1] - mn0);
            c[j][2] = exp2_fast(c[j][2] - mn1);
            c[j][3] = exp2_fast(c[j][3] - mn1);
            ls0 += c[j][0] + c[j][1];
            ls1 += c[j][2] + c[j][3];
        }
        ls0 += __shfl_xor_sync(0xffffffffu, ls0, 1);
        ls0 += __shfl_xor_sync(0xffffffffu, ls0, 2);
        ls1 += __shfl_xor_sync(0xffffffffu, ls1, 1);
        ls1 += __shfl_xor_sync(0xffffffffu, ls1, 2);
        l0 = l0 * sc0 + ls0;
        l1 = l1 * sc1 + ls1;

        // rescale O
        #pragma unroll
        for (int nf = 0; nf < 16; nf++) {
            o[nf][0] *= sc0; o[nf][1] *= sc0;
            o[nf][2] *= sc1; o[nf][3] *= sc1;
        }

        // ---- pack P to fp16 A-fragments (single precision pass) ----
        #pragma unroll
        for (int g = 0; g < 4; g++) {
            #pragma unroll
            for (int q = 0; q < 4; q++) {
                int j = 2 * g + (q >> 1);
                int e = (q & 1) * 2;
                pah[g][q] = pack_f16(__float2half_rn(c[j][e]),
                                     __float2half_rn(c[j][e + 1]));
            }
        }

        // ---- O += P V (single pass, fp16) ----
        #pragma unroll
        for (int g = 0; g < 4; g++) {
            #pragma unroll
            for (int vb = 0; vb < 8; vb++) {
                uint32_t vh4[4];
                ldsm_x4_t(vh4, Vb + (g * 16 + vrow) * AT_LDB + (vb * 16 + vcol) * 2);
                #pragma unroll
                for (int half = 0; half < 2; half++) {
                    int nf = vb * 2 + half;
                    mma16816h(o[nf], pah[g], &vh4[half * 2]);
                }
            }
        }
    }

    // ---- finalize: O/l, write ctx as fp16 hi/lo (for fp16 2-pass out GEMM) ----
    const float inv0 = 1.f / l0, inv1 = 1.f / l1;
    const int colb = h * DH + (lane & 3) * 2;
    #pragma unroll
    for (int nf = 0; nf < 16; nf++) {
        int col = colb + nf * 8;
        float v0 = o[nf][0] * inv0, v1 = o[nf][1] * inv0;
        float v2 = o[nf][2] * inv1, v3 = o[nf][3] * inv1;
        __half h0 = __float2half_rn(v0), h1 = __float2half_rn(v1);
        __half h2 = __float2half_rn(v2), h3 = __float2half_rn(v3);
        __half l0h = __float2half_rn(v0 - __half2float(h0));
        __half l1h = __float2half_rn(v1 - __half2float(h1));
        __half l2h = __float2half_rn(v2 - __half2float(h2));
        __half l3h = __float2half_rn(v3 - __half2float(h3));
        size_t g0 = (size_t)(b * S + r0g) * D + col;
        size_t g1 = (size_t)(b * S + r1g) * D + col;
        *(uint32_t*)(g_c16h + g0) = pack_f16(h0, h1);
        *(uint32_t*)(g_c16l + g0) = pack_f16(l0h, l1h);
        *(uint32_t*)(g_c16h + g1) = pack_f16(h2, h3);
        *(uint32_t*)(g_c16l + g1) = pack_f16(l2h, l3h);
    }
}

// ---------------------------------------------------------------------------
extern "C" void kernel_launch(void* const* d_in, const int* in_sizes, int n_in,
                              void* d_out, int out_size)
{
    const float* X  = (const float*)d_in[0];
    const float* Wq = (const float*)d_in[1];
    const float* bq = (const float*)d_in[2];
    const float* Wk = (const float*)d_in[3];
    const float* bk = (const float*)d_in[4];
    const float* Wv = (const float*)d_in[5];
    const float* bv = (const float*)d_in[6];
    const float* Wo = (const float*)d_in[7];
    const float* bo = (const float*)d_in[8];
    float* out = (float*)d_out;

    cudaFuncSetAttribute(attn_tc_kernel, cudaFuncAttributeMaxDynamicSharedMemorySize, ATTN_SMEM);
    cudaFuncSetAttribute(qkv_tc_gemm, cudaFuncAttributeMaxDynamicSharedMemorySize, GEMM_SMEM2);
    cudaFuncSetAttribute(out_tc_gemm, cudaFuncAttributeMaxDynamicSharedMemorySize, GEMM_SMEM3);

    conv_x_kernel<<<(M * D / 4) / 256, 256>>>((const float4*)X);
    wsplit_kernel<<<dim3(D / 32, D / 32, 4), 256>>>(Wq, Wk, Wv, Wo);
    qkv_tc_gemm<<<dim3(D / 128, M / 128, 3), 128, GEMM_SMEM2>>>(bq, bk, bv);
    attn_tc_kernel<<<dim3(S / 64, B * H), 128, ATTN_SMEM>>>();
    out_tc_gemm<<<dim3(D / 128, M / 128), 128, GEMM_SMEM3>>>(bo, out);
}

// round 12
// speedup vs baseline: 9.8790x; 1.1462x over previous
#include <cuda_runtime.h>
#include <cuda_bf16.h>
#include <cuda_fp16.h>
#include <math.h>
#include <cstdint>

// Problem constants
constexpr int B  = 4;
constexpr int S  = 2048;
constexpr int D  = 2048;
constexpr int H  = 16;
constexpr int DH = 128;
constexpr int M  = B * S;          // 8192 rows

// ---------------------------------------------------------------------------
// Scratch (allocation-free rule: device globals). fp16 everywhere.
// ---------------------------------------------------------------------------
__device__ __half g_x16[(size_t)M * D];
__device__ __half g_q16[(size_t)M * D];
__device__ __half g_k16[(size_t)M * D];
__device__ __half g_v16[(size_t)M * D];
__device__ __half g_c16[(size_t)M * D];
__device__ __half g_wT16[(size_t)4 * D * D];   // [w][N][K] single fp16

// ---------------------------------------------------------------------------
// PTX helpers (sm_103 baseline: mma.sync + ldmatrix + cp.async only)
// ---------------------------------------------------------------------------
__device__ __forceinline__ uint32_t smem_u32(const void* p) {
    uint32_t a;
    asm("{ .reg .u64 t; cvta.to.shared.u64 t, %1; cvt.u32.u64 %0, t; }" : "=r"(a) : "l"(p));
    return a;
}

__device__ __forceinline__ void cp_async16(uint32_t dst, const void* src) {
    asm volatile("cp.async.cg.shared.global [%0], [%1], 16;" :: "r"(dst), "l"(src));
}
#define CP_COMMIT() asm volatile("cp.async.commit_group;" ::: "memory")
#define CP_WAIT0()  asm volatile("cp.async.wait_group 0;" ::: "memory")
#define CP_WAIT1()  asm volatile("cp.async.wait_group 1;" ::: "memory")

__device__ __forceinline__ void ldsm_x4(uint32_t* r, uint32_t addr) {
    asm volatile("ldmatrix.sync.aligned.m8n8.x4.shared.b16 {%0,%1,%2,%3}, [%4];"
        : "=r"(r[0]), "=r"(r[1]), "=r"(r[2]), "=r"(r[3]) : "r"(addr));
}
__device__ __forceinline__ void ldsm_x4_t(uint32_t* r, uint32_t addr) {
    asm volatile("ldmatrix.sync.aligned.m8n8.x4.trans.shared.b16 {%0,%1,%2,%3}, [%4];"
        : "=r"(r[0]), "=r"(r[1]), "=r"(r[2]), "=r"(r[3]) : "r"(addr));
}

__device__ __forceinline__ void mma16816h(float* c, const uint32_t* a, const uint32_t* b) {
    asm volatile("mma.sync.aligned.m16n8k16.row.col.f32.f16.f16.f32 "
        "{%0,%1,%2,%3}, {%4,%5,%6,%7}, {%8,%9}, {%0,%1,%2,%3};"
        : "+f"(c[0]), "+f"(c[1]), "+f"(c[2]), "+f"(c[3])
        : "r"(a[0]), "r"(a[1]), "r"(a[2]), "r"(a[3]), "r"(b[0]), "r"(b[1]));
}

__device__ __forceinline__ uint32_t pack_f16(__half lo, __half hi) {
    __half2 h2 = __halves2half2(lo, hi);
    return *(uint32_t*)&h2;
}

// fast 2^z for z <= 0 (quartic Taylor after rint reduction, err ~4e-5)
__device__ __forceinline__ float exp2_fast(float z) {
    z = fmaxf(z, -126.f);
    float fi = rintf(z);
    float f  = z - fi;
    float p  = 0.00961813f;
    p = fmaf(p, f, 0.0555041f);
    p = fmaf(p, f, 0.2402265f);
    p = fmaf(p, f, 0.6931472f);
    p = fmaf(p, f, 1.0f);
    int e = (int)fi;
    return p * __int_as_float((uint32_t)(e + 127) << 23);
}

// ---------------------------------------------------------------------------
// Conversion kernels
// ---------------------------------------------------------------------------
__global__ __launch_bounds__(256) void conv_x_kernel(const float4* __restrict__ in) {
    size_t i = (size_t)blockIdx.x * blockDim.x + threadIdx.x;
    float4 v = in[i];
    __half h[4] = {__float2half_rn(v.x), __float2half_rn(v.y),
                   __float2half_rn(v.z), __float2half_rn(v.w)};
    *(uint2*)(g_x16 + i * 4) = *(const uint2*)h;
}

// Weights: W [K][N] fp32 -> transposed single fp16 [N][K]
__global__ __launch_bounds__(256) void wsplit_kernel(const float* __restrict__ Wq,
                                                     const float* __restrict__ Wk,
                                                     const float* __restrict__ Wv,
                                                     const float* __restrict__ Wo) {
    __shared__ float tile[32][33];
    int z = blockIdx.z;
    const float* W = (z == 0) ? Wq : (z == 1) ? Wk : (z == 2) ? Wv : Wo;
    __half* oh = g_wT16 + (size_t)z * D * D;
    int n0 = blockIdx.x * 32, k0 = blockIdx.y * 32;
    int tx = threadIdx.x & 31, ty = threadIdx.x >> 5;
    #pragma unroll
    for (int i = 0; i < 4; i++) {
        int k = ty + i * 8;
        tile[k][tx] = W[(size_t)(k0 + k) * D + n0 + tx];
    }
    __syncthreads();
    #pragma unroll
    for (int i = 0; i < 4; i++) {
        int n = ty + i * 8;
        oh[(size_t)(n0 + n) * D + k0 + tx] = __float2half_rn(tile[tx][n]);
    }
}

// ---------------------------------------------------------------------------
// mma.sync fp16 1-pass GEMM: C[128x128] = A @ B^T + bias
// 4 warps (2x2), warp tile 64x64, BK=32, 3-stage cp.async, ONE sync/iter.
// MODE: 0 = fp32 out, 2 = fp16 out
// ---------------------------------------------------------------------------
constexpr int BKG      = 32;
constexpr int LDT      = 40;                 // f16 stride per tile row (80 B)
constexpr int TILE_BY  = 128 * LDT * 2;      // 10240 B per tile
constexpr int NITER    = D / BKG;            // 64
constexpr int GEMM_SMEM2 = 3 * 2 * TILE_BY;  // 61440 B

__device__ __forceinline__ void load_stage(uint32_t sbase,
                                           const __half* A,
                                           const __half* Bm,
                                           int k0, int t) {
    const __half* bases[2] = {A, Bm};
    #pragma unroll
    for (int i = 0; i < 8; i++) {
        const int tile = i >> 2;              // 4 slots per tile per thread
        int idx  = t + 128 * (i & 3);         // 0..511
        int row  = idx >> 2;                  // 0..127
        int chnk = idx & 3;                   // 16B chunk
        const __half* src = bases[tile] + (size_t)row * D + k0 + chnk * 8;
        uint32_t dst = sbase + tile * TILE_BY + row * (LDT * 2) + chnk * 16;
        cp_async16(dst, src);
    }
    CP_COMMIT();
}

template <int MODE>
__device__ __forceinline__ void tc_gemm_body(const __half* __restrict__ Ap,
                                             const __half* __restrict__ Bp,
                                             const float* __restrict__ bias,
                                             float* __restrict__ C,
                                             __half* __restrict__ F) {
    constexpr int STAGE = 2 * TILE_BY;
    extern __shared__ char smem[];
    const uint32_t sb = smem_u32(smem);
    const int t    = threadIdx.x;
    const int lane = t & 31;
    const int w    = t >> 5;
    const int wm   = (w & 1) * 64;
    const int wn   = (w >> 1) * 64;
    const int m0   = blockIdx.y * 128;
    const int n0   = blockIdx.x * 128;

    const __half* Arow = Ap + (size_t)m0 * D;
    const __half* Brow = Bp + (size_t)n0 * D;

    float acc[4][8][4];
    #pragma unroll
    for (int i = 0; i < 4; i++)
        #pragma unroll
        for (int j = 0; j < 8; j++)
            #pragma unroll
            for (int r = 0; r < 4; r++) acc[i][j][r] = 0.f;

    const int arow  = lane & 15;
    const int akoff = (lane >> 4) * 16;
    const int bn    = (lane & 7) + ((lane >> 4) << 3);
    const int bkoff = ((lane >> 3) & 1) * 16;

    load_stage(sb + 0 * STAGE, Arow, Brow, 0, t);
    load_stage(sb + 1 * STAGE, Arow, Brow, BKG, t);

    int bufc = 0;
    for (int c = 0; c < NITER; c++) {
        if (c + 1 < NITER) { CP_WAIT1(); } else { CP_WAIT0(); }
        __syncthreads();                       // stage c visible; buf (c+2)%3 free

        const uint32_t sbase = sb + bufc * STAGE;
        #pragma unroll
        for (int kk = 0; kk < 2; kk++) {
            const uint32_t kbyte = kk * 32;
            uint32_t ah[4][4];
            #pragma unroll
            for (int mf = 0; mf < 4; mf++) {
                uint32_t ad = sbase + (wm + mf * 16 + arow) * (LDT * 2) + kbyte + akoff;
                ldsm_x4(ah[mf], ad);
            }
            #pragma unroll
            for (int nb = 0; nb < 4; nb++) {
                uint32_t bh4[4];
                uint32_t bd = sbase + TILE_BY + (wn + nb * 16 + bn) * (LDT * 2) + kbyte + bkoff;
                ldsm_x4(bh4, bd);
                #pragma unroll
                for (int mf = 0; mf < 4; mf++)
                    #pragma unroll
                    for (int half = 0; half < 2; half++) {
                        int nf = nb * 2 + half;
                        mma16816h(acc[mf][nf], ah[mf], &bh4[half * 2]);
                    }
            }
        }
        // Issue next-next stage AFTER compute; its buffer was last read at
        // iter c-1 and all warps passed this iter's barrier -> no hazard.
        if (c + 2 < NITER) {
            int bufn = bufc + 2; if (bufn >= 3) bufn -= 3;
            load_stage(sb + bufn * STAGE, Arow, Brow, (c + 2) * BKG, t);
        }
        if (++bufc == 3) bufc = 0;
    }

    // Epilogue
    const int rbase = m0 + wm + (lane >> 2);
    const int cbase = n0 + wn + (lane & 3) * 2;
    #pragma unroll
    for (int mf = 0; mf < 4; mf++) {
        #pragma unroll
        for (int nf = 0; nf < 8; nf++) {
            int col = cbase + nf * 8;
            float2 bv = *(const float2*)(bias + col);
            int r0 = rbase + mf * 16;
            float v0 = acc[mf][nf][0] + bv.x, v1 = acc[mf][nf][1] + bv.y;
            float v2 = acc[mf][nf][2] + bv.x, v3 = acc[mf][nf][3] + bv.y;
            if (MODE == 0) {
                float2 o0 = {v0, v1}, o1 = {v2, v3};
                *(float2*)(C + (size_t)r0 * D + col)       = o0;
                *(float2*)(C + (size_t)(r0 + 8) * D + col) = o1;
            } else {
                *(uint32_t*)(F + (size_t)r0 * D + col) =
                    pack_f16(__float2half_rn(v0), __float2half_rn(v1));
                *(uint32_t*)(F + (size_t)(r0 + 8) * D + col) =
                    pack_f16(__float2half_rn(v2), __float2half_rn(v3));
            }
        }
    }
}

// Q/K/V projections: 1-pass fp16
__global__ __launch_bounds__(128, 2) void qkv_tc_gemm(const float* __restrict__ bq,
                                                      const float* __restrict__ bk,
                                                      const float* __restrict__ bv) {
    const int z = blockIdx.z;
    const __half* W = g_wT16 + (size_t)z * D * D;
    const float* bias = (z == 0) ? bq : (z == 1) ? bk : bv;
    __half* Out = (z == 0) ? g_q16 : (z == 1) ? g_k16 : g_v16;
    tc_gemm_body<2>(g_x16, W, bias, nullptr, Out);
}

// Output projection: 1-pass, fp32 out
__global__ __launch_bounds__(128, 2) void out_tc_gemm(const float* __restrict__ bo,
                                                      float* __restrict__ out) {
    tc_gemm_body<0>(g_c16, g_wT16 + (size_t)3 * D * D, bo, out, nullptr);
}

// ---------------------------------------------------------------------------
// Tensor-core flash attention (fp16, causal). Br=Bc=64, 128 threads.
// Q/K/V/P/ctx all single fp16 (calibrated error budget).
// K/V double-buffered in smem; Q in registers.
// ---------------------------------------------------------------------------
constexpr int AT_LDB   = 272;                    // bytes per tile row (128 f16 + pad)
constexpr int AT_TILE  = 64 * AT_LDB;            // 17408 B
constexpr int ATTN_SMEM = 5 * AT_TILE;           // Qh + (Kh,Vh)x2 = 87040 B
constexpr float SCALE_LOG2E = 0.12751650f;       // (1/sqrt(128)) * log2(e)

__global__ __launch_bounds__(128, 2) void attn_tc_kernel() {
    extern __shared__ char sm8[];
    const uint32_t sb  = smem_u32(sm8);
    const uint32_t Qh  = sb;
    const uint32_t KV0 = sb + 1 * AT_TILE;       // Kh then Vh
    const uint32_t KV1 = sb + 3 * AT_TILE;

    const int t    = threadIdx.x;
    const int lane = t & 31;
    const int w    = t >> 5;
    const int iq   = (gridDim.x - 1) - blockIdx.x;      // big blocks first
    const int bh   = blockIdx.y;
    const int b    = bh >> 4;
    const int h    = bh & 15;
    const int q0   = iq * 64;
    const int wq   = w * 16;

    // ldmatrix lane offsets
    const int arow  = lane & 15;
    const int akoff = (lane >> 4) * 16;
    const int bn    = (lane & 7) + ((lane >> 4) << 3);
    const int bkoff = ((lane >> 3) & 1) * 16;
    const int vrow  = lane & 15;
    const int vcol  = (lane >> 4) << 3;

    // ---- Load Q tile, hoist to registers ----
    {
        #pragma unroll
        for (int i = 0; i < 8; i++) {
            int idx  = t + 128 * i;
            int row  = idx >> 4;
            int chnk = idx & 15;
            size_t g = (size_t)(b * S + q0 + row) * D + h * DH + chnk * 8;
            uint32_t so = row * AT_LDB + chnk * 16;
            cp_async16(Qh + so, g_q16 + g);
        }
        CP_COMMIT();
        CP_WAIT0();
        __syncthreads();
    }
    uint32_t qhr[8][4];
    #pragma unroll
    for (int kt = 0; kt < 8; kt++) {
        uint32_t ad = Qh + (wq + arow) * AT_LDB + kt * 32 + akoff;
        ldsm_x4(qhr[kt], ad);
    }

    // ---- Preload K/V block 0 into buffer 0 ----
    {
        #pragma unroll
        for (int i = 0; i < 8; i++) {
            int idx  = t + 128 * i;
            int row  = idx >> 4;
            int chnk = idx & 15;
            size_t g = (size_t)(b * S + row) * D + h * DH + chnk * 8;
            uint32_t so = row * AT_LDB + chnk * 16;
            cp_async16(KV0 + so, g_k16 + g);
            cp_async16(KV0 + AT_TILE + so, g_v16 + g);
        }
        CP_COMMIT();
    }

    float o[16][4];
    #pragma unroll
    for (int i = 0; i < 16; i++)
        #pragma unroll
        for (int r = 0; r < 4; r++) o[i][r] = 0.f;
    float m0 = -1e30f, m1 = -1e30f, l0 = 0.f, l1 = 0.f;

    const int r0g = q0 + wq + (lane >> 2);
    const int r1g = r0g + 8;

    for (int jb = 0; jb <= iq; jb++) {
        __syncthreads();   // all warps done reading buffer (jb+1)&1 (iter jb-1)
        if (jb + 1 <= iq) {
            const int kn = (jb + 1) * 64;
            const uint32_t buf = ((jb + 1) & 1) ? KV1 : KV0;
            #pragma unroll
            for (int i = 0; i < 8; i++) {
                int idx  = t + 128 * i;
                int row  = idx >> 4;
                int chnk = idx & 15;
                size_t g = (size_t)(b * S + kn + row) * D + h * DH + chnk * 8;
                uint32_t so = row * AT_LDB + chnk * 16;
                cp_async16(buf + so, g_k16 + g);
                cp_async16(buf + AT_TILE + so, g_v16 + g);
            }
            CP_COMMIT();
            CP_WAIT1();    // block jb's loads (issued last iter) complete
        } else {
            CP_WAIT0();
        }
        __syncthreads();

        const uint32_t Kb = (jb & 1) ? KV1 : KV0;
        const uint32_t Vb = Kb + AT_TILE;
        const int k0 = jb * 64;

        // ---- S = Q K^T (single pass, fp16) ----
        float c[8][4];
        #pragma unroll
        for (int j = 0; j < 8; j++)
            #pragma unroll
            for (int r = 0; r < 4; r++) c[j][r] = 0.f;

        #pragma unroll
        for (int kt = 0; kt < 8; kt++) {
            #pragma unroll
            for (int nb = 0; nb < 4; nb++) {
                uint32_t kh4[4];
                ldsm_x4(kh4, Kb + (nb * 16 + bn) * AT_LDB + kt * 32 + bkoff);
                #pragma unroll
                for (int half = 0; half < 2; half++) {
                    int nf = nb * 2 + half;
                    mma16816h(c[nf], qhr[kt], &kh4[half * 2]);
                }
            }
        }

        // ---- scale (+ causal mask only on the diagonal block) ----
        if (jb == iq) {
            #pragma unroll
            for (int j = 0; j < 8; j++) {
                int cc = k0 + j * 8 + (lane & 3) * 2;
                #pragma unroll
                for (int r = 0; r < 4; r++) {
                    float v = c[j][r] * SCALE_LOG2E;
                    int col = cc + (r & 1);
                    int row = (r < 2) ? r0g : r1g;
                    if (col > row) v = -1e30f;
                    c[j][r] = v;
                }
            }
        } else {
            #pragma unroll
            for (int j = 0; j < 8; j++)
                #pragma unroll
                for (int r = 0; r < 4; r++)
                    c[j][r] *= SCALE_LOG2E;
        }

        // ---- online softmax (log2 domain) ----
        float mx0 = -1e30f, mx1 = -1e30f;
        #pragma unroll
        for (int j = 0; j < 8; j++) {
            mx0 = fmaxf(mx0, fmaxf(c[j][0], c[j][1]));
            mx1 = fmaxf(mx1, fmaxf(c[j][2], c[j][3]));
        }
        mx0 = fmaxf(mx0, __shfl_xor_sync(0xffffffffu, mx0, 1));
        mx0 = fmaxf(mx0, __shfl_xor_sync(0xffffffffu, mx0, 2));
        mx1 = fmaxf(mx1, __shfl_xor_sync(0xffffffffu, mx1, 1));
        mx1 = fmaxf(mx1, __shfl_xor_sync(0xffffffffu, mx1, 2));
        float mn0 = fmaxf(m0, mx0), mn1 = fmaxf(m1, mx1);
        float sc0 = exp2_fast(m0 - mn0), sc1 = exp2_fast(m1 - mn1);
        m0 = mn0; m1 = mn1;

        float ls0 = 0.f, ls1 = 0.f;
        uint32_t pah[4][4];
        #pragma unroll
        for (int j = 0; j < 8; j++) {
            c[j][0] = exp2_fast(c[j][0] - mn0);
            c[j][1] = exp2_fast(c[j][1] - mn0);
            c[j][2] = exp2_fast(c[j][2] - mn1);
            c[j][3] = exp2_fast(c[j][3] - mn1);
            ls0 += c[j][0] + c[j][1];
            ls1 += c[j][2] + c[j][3];
        }
        ls0 += __shfl_xor_sync(0xffffffffu, ls0, 1);
        ls0 += __shfl_xor_sync(0xffffffffu, ls0, 2);
        ls1 += __shfl_xor_sync(0xffffffffu, ls1, 1);
        ls1 += __shfl_xor_sync(0xffffffffu, ls1, 2);
        l0 = l0 * sc0 + ls0;
        l1 = l1 * sc1 + ls1;

        // rescale O
        #pragma unroll
        for (int nf = 0; nf < 16; nf++) {
            o[nf][0] *= sc0; o[nf][1] *= sc0;
            o[nf][2] *= sc1; o[nf][3] *= sc1;
        }

        // ---- pack P to fp16 A-fragments (single precision pass) ----
        #pragma unroll
        for (int g = 0; g < 4; g++) {
            #pragma unroll
            for (int q = 0; q < 4; q++) {
                int j = 2 * g + (q >> 1);
                int e = (q & 1) * 2;
                pah[g][q] = pack_f16(__float2half_rn(c[j][e]),
                                     __float2half_rn(c[j][e + 1]));
            }
        }

        // ---- O += P V (single pass, fp16) ----
        #pragma unroll
        for (int g = 0; g < 4; g++) {
            #pragma unroll
            for (int vb = 0; vb < 8; vb++) {
                uint32_t vh4[4];
                ldsm_x4_t(vh4, Vb + (g * 16 + vrow) * AT_LDB + (vb * 16 + vcol) * 2);
                #pragma unroll
                for (int half = 0; half < 2; half++) {
                    int nf = vb * 2 + half;
                    mma16816h(o[nf], pah[g], &vh4[half * 2]);
                }
            }
        }
    }

    // ---- finalize: O/l, write ctx as single fp16 ----
    const float inv0 = 1.f / l0, inv1 = 1.f / l1;
    const int colb = h * DH + (lane & 3) * 2;
    #pragma unroll
    for (int nf = 0; nf < 16; nf++) {
        int col = colb + nf * 8;
        size_t g0 = (size_t)(b * S + r0g) * D + col;
        size_t g1 = (size_t)(b * S + r1g) * D + col;
        *(uint32_t*)(g_c16 + g0) =
            pack_f16(__float2half_rn(o[nf][0] * inv0), __float2half_rn(o[nf][1] * inv0));
        *(uint32_t*)(g_c16 + g1) =
            pack_f16(__float2half_rn(o[nf][2] * inv1), __float2half_rn(o[nf][3] * inv1));
    }
}

// ---------------------------------------------------------------------------
extern "C" void kernel_launch(void* const* d_in, const int* in_sizes, int n_in,
                              void* d_out, int out_size)
{
    const float* X  = (const float*)d_in[0];
    const float* Wq = (const float*)d_in[1];
    const float* bq = (const float*)d_in[2];
    const float* Wk = (const float*)d_in[3];
    const float* bk = (const float*)d_in[4];
    const float* Wv = (const float*)d_in[5];
    const float* bv = (const float*)d_in[6];
    const float* Wo = (const float*)d_in[7];
    const float* bo = (const float*)d_in[8];
    float* out = (float*)d_out;

    cudaFuncSetAttribute(attn_tc_kernel, cudaFuncAttributeMaxDynamicSharedMemorySize, ATTN_SMEM);
    cudaFuncSetAttribute(qkv_tc_gemm, cudaFuncAttributeMaxDynamicSharedMemorySize, GEMM_SMEM2);
    cudaFuncSetAttribute(out_tc_gemm, cudaFuncAttributeMaxDynamicSharedMemorySize, GEMM_SMEM2);

    conv_x_kernel<<<(M * D / 4) / 256, 256>>>((const float4*)X);
    wsplit_kernel<<<dim3(D / 32, D / 32, 4), 256>>>(Wq, Wk, Wv, Wo);
    qkv_tc_gemm<<<dim3(D / 128, M / 128, 3), 128, GEMM_SMEM2>>>(bq, bk, bv);
    attn_tc_kernel<<<dim3(S / 64, B * H), 128, ATTN_SMEM>>>();
    out_tc_gemm<<<dim3(D / 128, M / 128), 128, GEMM_SMEM2>>>(bo, out);
}

// round 13
// speedup vs baseline: 9.9093x; 1.0031x over previous
#include <cuda_runtime.h>
#include <cuda_bf16.h>
#include <cuda_fp16.h>
#include <math.h>
#include <cstdint>

// Problem constants
constexpr int B  = 4;
constexpr int S  = 2048;
constexpr int D  = 2048;
constexpr int H  = 16;
constexpr int DH = 128;
constexpr int M  = B * S;          // 8192 rows

// ---------------------------------------------------------------------------
// Scratch (allocation-free rule: device globals). fp16 everywhere.
// ---------------------------------------------------------------------------
__device__ __half g_x16[(size_t)M * D];
__device__ __half g_q16[(size_t)M * D];
__device__ __half g_k16[(size_t)M * D];
__device__ __half g_v16[(size_t)M * D];
__device__ __half g_c16[(size_t)M * D];
__device__ __half g_wT16[(size_t)4 * D * D];   // [w][N][K] single fp16

// ---------------------------------------------------------------------------
// PTX helpers (sm_103 baseline: mma.sync + ldmatrix + cp.async only)
// ---------------------------------------------------------------------------
__device__ __forceinline__ uint32_t smem_u32(const void* p) {
    uint32_t a;
    asm("{ .reg .u64 t; cvta.to.shared.u64 t, %1; cvt.u32.u64 %0, t; }" : "=r"(a) : "l"(p));
    return a;
}

__device__ __forceinline__ void cp_async16(uint32_t dst, const void* src) {
    asm volatile("cp.async.cg.shared.global [%0], [%1], 16;" :: "r"(dst), "l"(src));
}
#define CP_COMMIT() asm volatile("cp.async.commit_group;" ::: "memory")
#define CP_WAIT0()  asm volatile("cp.async.wait_group 0;" ::: "memory")
#define CP_WAIT1()  asm volatile("cp.async.wait_group 1;" ::: "memory")

__device__ __forceinline__ void ldsm_x4(uint32_t* r, uint32_t addr) {
    asm volatile("ldmatrix.sync.aligned.m8n8.x4.shared.b16 {%0,%1,%2,%3}, [%4];"
        : "=r"(r[0]), "=r"(r[1]), "=r"(r[2]), "=r"(r[3]) : "r"(addr));
}
__device__ __forceinline__ void ldsm_x4_t(uint32_t* r, uint32_t addr) {
    asm volatile("ldmatrix.sync.aligned.m8n8.x4.trans.shared.b16 {%0,%1,%2,%3}, [%4];"
        : "=r"(r[0]), "=r"(r[1]), "=r"(r[2]), "=r"(r[3]) : "r"(addr));
}

__device__ __forceinline__ void mma16816h(float* c, const uint32_t* a, const uint32_t* b) {
    asm volatile("mma.sync.aligned.m16n8k16.row.col.f32.f16.f16.f32 "
        "{%0,%1,%2,%3}, {%4,%5,%6,%7}, {%8,%9}, {%0,%1,%2,%3};"
        : "+f"(c[0]), "+f"(c[1]), "+f"(c[2]), "+f"(c[3])
        : "r"(a[0]), "r"(a[1]), "r"(a[2]), "r"(a[3]), "r"(b[0]), "r"(b[1]));
}

__device__ __forceinline__ uint32_t pack_f16(__half lo, __half hi) {
    __half2 h2 = __halves2half2(lo, hi);
    return *(uint32_t*)&h2;
}

// fast 2^z for z <= 0 (quartic Taylor after rint reduction, err ~4e-5)
__device__ __forceinline__ float exp2_fast(float z) {
    z = fmaxf(z, -126.f);
    float fi = rintf(z);
    float f  = z - fi;
    float p  = 0.00961813f;
    p = fmaf(p, f, 0.0555041f);
    p = fmaf(p, f, 0.2402265f);
    p = fmaf(p, f, 0.6931472f);
    p = fmaf(p, f, 1.0f);
    int e = (int)fi;
    return p * __int_as_float((uint32_t)(e + 127) << 23);
}

// ---------------------------------------------------------------------------
// Conversion kernels
// ---------------------------------------------------------------------------
__global__ __launch_bounds__(256) void conv_x_kernel(const float4* __restrict__ in) {
    size_t i = (size_t)blockIdx.x * blockDim.x + threadIdx.x;
    float4 v = in[i];
    __half h[4] = {__float2half_rn(v.x), __float2half_rn(v.y),
                   __float2half_rn(v.z), __float2half_rn(v.w)};
    *(uint2*)(g_x16 + i * 4) = *(const uint2*)h;
}

// Weights: W [K][N] fp32 -> transposed single fp16 [N][K]
__global__ __launch_bounds__(256) void wsplit_kernel(const float* __restrict__ Wq,
                                                     const float* __restrict__ Wk,
                                                     const float* __restrict__ Wv,
                                                     const float* __restrict__ Wo) {
    __shared__ float tile[32][33];
    int z = blockIdx.z;
    const float* W = (z == 0) ? Wq : (z == 1) ? Wk : (z == 2) ? Wv : Wo;
    __half* oh = g_wT16 + (size_t)z * D * D;
    int n0 = blockIdx.x * 32, k0 = blockIdx.y * 32;
    int tx = threadIdx.x & 31, ty = threadIdx.x >> 5;
    #pragma unroll
    for (int i = 0; i < 4; i++) {
        int k = ty + i * 8;
        tile[k][tx] = W[(size_t)(k0 + k) * D + n0 + tx];
    }
    __syncthreads();
    #pragma unroll
    for (int i = 0; i < 4; i++) {
        int n = ty + i * 8;
        oh[(size_t)(n0 + n) * D + k0 + tx] = __float2half_rn(tile[tx][n]);
    }
}

// ---------------------------------------------------------------------------
// mma.sync fp16 1-pass GEMM: C[128x128] = A @ B^T + bias
// 4 warps (2x2), warp tile 64x64, BK=32, 3-stage cp.async, ONE sync/iter.
// MODE: 0 = fp32 out, 2 = fp16 out
// ---------------------------------------------------------------------------
constexpr int BKG      = 32;
constexpr int LDT      = 40;                 // f16 stride per tile row (80 B)
constexpr int TILE_BY  = 128 * LDT * 2;      // 10240 B per tile
constexpr int NITER    = D / BKG;            // 64
constexpr int GEMM_SMEM2 = 3 * 2 * TILE_BY;  // 61440 B

__device__ __forceinline__ void load_stage(uint32_t sbase,
                                           const __half* A,
                                           const __half* Bm,
                                           int k0, int t) {
    const __half* bases[2] = {A, Bm};
    #pragma unroll
    for (int i = 0; i < 8; i++) {
        const int tile = i >> 2;              // 4 slots per tile per thread
        int idx  = t + 128 * (i & 3);         // 0..511
        int row  = idx >> 2;                  // 0..127
        int chnk = idx & 3;                   // 16B chunk
        const __half* src = bases[tile] + (size_t)row * D + k0 + chnk * 8;
        uint32_t dst = sbase + tile * TILE_BY + row * (LDT * 2) + chnk * 16;
        cp_async16(dst, src);
    }
    CP_COMMIT();
}

template <int MODE>
__device__ __forceinline__ void tc_gemm_body(const __half* __restrict__ Ap,
                                             const __half* __restrict__ Bp,
                                             const float* __restrict__ bias,
                                             float* __restrict__ C,
                                             __half* __restrict__ F) {
    constexpr int STAGE = 2 * TILE_BY;
    extern __shared__ char smem[];
    const uint32_t sb = smem_u32(smem);
    const int t    = threadIdx.x;
    const int lane = t & 31;
    const int w    = t >> 5;
    const int wm   = (w & 1) * 64;
    const int wn   = (w >> 1) * 64;
    const int m0   = blockIdx.y * 128;
    const int n0   = blockIdx.x * 128;

    const __half* Arow = Ap + (size_t)m0 * D;
    const __half* Brow = Bp + (size_t)n0 * D;

    float acc[4][8][4];
    #pragma unroll
    for (int i = 0; i < 4; i++)
        #pragma unroll
        for (int j = 0; j < 8; j++)
            #pragma unroll
            for (int r = 0; r < 4; r++) acc[i][j][r] = 0.f;

    const int arow  = lane & 15;
    const int akoff = (lane >> 4) * 16;
    const int bn    = (lane & 7) + ((lane >> 4) << 3);
    const int bkoff = ((lane >> 3) & 1) * 16;

    load_stage(sb + 0 * STAGE, Arow, Brow, 0, t);
    load_stage(sb + 1 * STAGE, Arow, Brow, BKG, t);

    int bufc = 0;
    for (int c = 0; c < NITER; c++) {
        if (c + 1 < NITER) { CP_WAIT1(); } else { CP_WAIT0(); }
        __syncthreads();                       // stage c visible; buf (c+2)%3 free

        const uint32_t sbase = sb + bufc * STAGE;
        #pragma unroll
        for (int kk = 0; kk < 2; kk++) {
            const uint32_t kbyte = kk * 32;
            uint32_t ah[4][4];
            #pragma unroll
            for (int mf = 0; mf < 4; mf++) {
                uint32_t ad = sbase + (wm + mf * 16 + arow) * (LDT * 2) + kbyte + akoff;
                ldsm_x4(ah[mf], ad);
            }
            #pragma unroll
            for (int nb = 0; nb < 4; nb++) {
                uint32_t bh4[4];
                uint32_t bd = sbase + TILE_BY + (wn + nb * 16 + bn) * (LDT * 2) + kbyte + bkoff;
                ldsm_x4(bh4, bd);
                #pragma unroll
                for (int mf = 0; mf < 4; mf++)
                    #pragma unroll
                    for (int half = 0; half < 2; half++) {
                        int nf = nb * 2 + half;
                        mma16816h(acc[mf][nf], ah[mf], &bh4[half * 2]);
                    }
            }
        }
        // Issue next-next stage AFTER compute; its buffer was last read at
        // iter c-1 and all warps passed this iter's barrier -> no hazard.
        if (c + 2 < NITER) {
            int bufn = bufc + 2; if (bufn >= 3) bufn -= 3;
            load_stage(sb + bufn * STAGE, Arow, Brow, (c + 2) * BKG, t);
        }
        if (++bufc == 3) bufc = 0;
    }

    // Epilogue
    const int rbase = m0 + wm + (lane >> 2);
    const int cbase = n0 + wn + (lane & 3) * 2;
    #pragma unroll
    for (int mf = 0; mf < 4; mf++) {
        #pragma unroll
        for (int nf = 0; nf < 8; nf++) {
            int col = cbase + nf * 8;
            float2 bv = *(const float2*)(bias + col);
            int r0 = rbase + mf * 16;
            float v0 = acc[mf][nf][0] + bv.x, v1 = acc[mf][nf][1] + bv.y;
            float v2 = acc[mf][nf][2] + bv.x, v3 = acc[mf][nf][3] + bv.y;
            if (MODE == 0) {
                float2 o0 = {v0, v1}, o1 = {v2, v3};
                *(float2*)(C + (size_t)r0 * D + col)       = o0;
                *(float2*)(C + (size_t)(r0 + 8) * D + col) = o1;
            } else {
                *(uint32_t*)(F + (size_t)r0 * D + col) =
                    pack_f16(__float2half_rn(v0), __float2half_rn(v1));
                *(uint32_t*)(F + (size_t)(r0 + 8) * D + col) =
                    pack_f16(__float2half_rn(v2), __float2half_rn(v3));
            }
        }
    }
}

// Q/K/V projections: 1-pass fp16
__global__ __launch_bounds__(128, 2) void qkv_tc_gemm(const float* __restrict__ bq,
                                                      const float* __restrict__ bk,
                                                      const float* __restrict__ bv) {
    const int z = blockIdx.z;
    const __half* W = g_wT16 + (size_t)z * D * D;
    const float* bias = (z == 0) ? bq : (z == 1) ? bk : bv;
    __half* Out = (z == 0) ? g_q16 : (z == 1) ? g_k16 : g_v16;
    tc_gemm_body<2>(g_x16, W, bias, nullptr, Out);
}

// Output projection: 1-pass, fp32 out
__global__ __launch_bounds__(128, 2) void out_tc_gemm(const float* __restrict__ bo,
                                                      float* __restrict__ out) {
    tc_gemm_body<0>(g_c16, g_wT16 + (size_t)3 * D * D, bo, out, nullptr);
}

// ---------------------------------------------------------------------------
// Tensor-core flash attention (fp16, causal). Br=Bc=64, 128 threads.
// Software-pipelined: PV(jb-1) fused/interleaved with softmax(jb) so the
// tensor pipe stays busy under the scalar work. 3 K/V smem buffers.
// ---------------------------------------------------------------------------
constexpr int AT_LDB   = 272;                    // bytes per tile row (128 f16 + pad)
constexpr int AT_TILE  = 64 * AT_LDB;            // 17408 B
constexpr int ATTN_SMEM = 6 * AT_TILE;           // 3 KV buffers (Q reuses tile 0)
constexpr float SCALE_LOG2E = 0.12751650f;       // (1/sqrt(128)) * log2(e)

__global__ __launch_bounds__(128, 2) void attn_tc_kernel() {
    extern __shared__ char sm8[];
    const uint32_t sb = smem_u32(sm8);

    const int t    = threadIdx.x;
    const int lane = t & 31;
    const int w    = t >> 5;
    const int iq   = (gridDim.x - 1) - blockIdx.x;      // big blocks first
    const int bh   = blockIdx.y;
    const int b    = bh >> 4;
    const int h    = bh & 15;
    const int q0   = iq * 64;
    const int wq   = w * 16;

    // ldmatrix lane offsets
    const int arow  = lane & 15;
    const int akoff = (lane >> 4) * 16;
    const int bn    = (lane & 7) + ((lane >> 4) << 3);
    const int bkoff = ((lane >> 3) & 1) * 16;
    const int vrow  = lane & 15;
    const int vcol  = (lane >> 4) << 3;

    // ---- Load Q into tile 0, hoist to registers ----
    {
        #pragma unroll
        for (int i = 0; i < 8; i++) {
            int idx  = t + 128 * i;
            int row  = idx >> 4;
            int chnk = idx & 15;
            size_t g = (size_t)(b * S + q0 + row) * D + h * DH + chnk * 8;
            cp_async16(sb + row * AT_LDB + chnk * 16, g_q16 + g);
        }
        CP_COMMIT();
        CP_WAIT0();
        __syncthreads();
    }
    uint32_t qhr[8][4];
    #pragma unroll
    for (int kt = 0; kt < 8; kt++) {
        ldsm_x4(qhr[kt], sb + (wq + arow) * AT_LDB + kt * 32 + akoff);
    }
    // Zero V tile of buffer 2 (tile 5): first-iteration dummy PV reads it.
    for (uint32_t i = (uint32_t)t * 16; i < (uint32_t)AT_TILE; i += 128 * 16) {
        *(uint4*)(sm8 + 5 * AT_TILE + i) = make_uint4(0, 0, 0, 0);
    }
    __syncthreads();   // Q reads + zeroing done before KV(0) overwrites tile 0

    // ---- Issue KV(0) -> buf0, KV(1) -> buf1 ----
    #pragma unroll
    for (int i = 0; i < 8; i++) {
        int idx  = t + 128 * i;
        int row  = idx >> 4;
        int chnk = idx & 15;
        size_t g = (size_t)(b * S + row) * D + h * DH + chnk * 8;
        uint32_t so = row * AT_LDB + chnk * 16;
        cp_async16(sb + so, g_k16 + g);
        cp_async16(sb + AT_TILE + so, g_v16 + g);
    }
    CP_COMMIT();
    if (iq >= 1) {
        #pragma unroll
        for (int i = 0; i < 8; i++) {
            int idx  = t + 128 * i;
            int row  = idx >> 4;
            int chnk = idx & 15;
            size_t g = (size_t)(b * S + 64 + row) * D + h * DH + chnk * 8;
            uint32_t so = row * AT_LDB + chnk * 16;
            cp_async16(sb + 2 * AT_TILE + so, g_k16 + g);
            cp_async16(sb + 3 * AT_TILE + so, g_v16 + g);
        }
        CP_COMMIT();
    }

    float o[16][4];
    #pragma unroll
    for (int i = 0; i < 16; i++)
        #pragma unroll
        for (int r = 0; r < 4; r++) o[i][r] = 0.f;
    float m0 = -1e30f, m1 = -1e30f, l0 = 0.f, l1 = 0.f;
    uint32_t pahp[4][4];
    #pragma unroll
    for (int g = 0; g < 4; g++)
        #pragma unroll
        for (int q = 0; q < 4; q++) pahp[g][q] = 0u;   // P(-1) = 0
    float scp0 = 1.f, scp1 = 1.f;

    const int r0g = q0 + wq + (lane >> 2);
    const int r1g = r0g + 8;

    int cur = 0;
    for (int jb = 0; jb <= iq; jb++) {
        const int prv = (cur + 2 >= 3) ? cur - 1 : cur + 2;   // (jb-1)%3 == (jb+2)%3
        if (jb < iq) { CP_WAIT1(); } else { CP_WAIT0(); }
        __syncthreads();                     // KV(jb) visible to all warps

        const uint32_t Kb = sb + (2 * cur) * AT_TILE;
        const uint32_t Vp = sb + (2 * prv + 1) * AT_TILE;     // V(jb-1)
        const int k0 = jb * 64;

        // ---- S = Q K^T (single pass, fp16) ----
        float c[8][4];
        #pragma unroll
        for (int j = 0; j < 8; j++)
            #pragma unroll
            for (int r = 0; r < 4; r++) c[j][r] = 0.f;

        #pragma unroll
        for (int kt = 0; kt < 8; kt++) {
            #pragma unroll
            for (int nb = 0; nb < 4; nb++) {
                uint32_t kh4[4];
                ldsm_x4(kh4, Kb + (nb * 16 + bn) * AT_LDB + kt * 32 + bkoff);
                #pragma unroll
                for (int half = 0; half < 2; half++) {
                    int nf = nb * 2 + half;
                    mma16816h(c[nf], qhr[kt], &kh4[half * 2]);
                }
            }
        }

        // ---- scale (+ causal mask only on the diagonal block) ----
        if (jb == iq) {
            #pragma unroll
            for (int j = 0; j < 8; j++) {
                int cc = k0 + j * 8 + (lane & 3) * 2;
                #pragma unroll
                for (int r = 0; r < 4; r++) {
                    float v = c[j][r] * SCALE_LOG2E;
                    int col = cc + (r & 1);
                    int row = (r < 2) ? r0g : r1g;
                    if (col > row) v = -1e30f;
                    c[j][r] = v;
                }
            }
        } else {
            #pragma unroll
            for (int j = 0; j < 8; j++)
                #pragma unroll
                for (int r = 0; r < 4; r++)
                    c[j][r] *= SCALE_LOG2E;
        }

        // ---- row max + running max ----
        float mx0 = -1e30f, mx1 = -1e30f;
        #pragma unroll
        for (int j = 0; j < 8; j++) {
            mx0 = fmaxf(mx0, fmaxf(c[j][0], c[j][1]));
            mx1 = fmaxf(mx1, fmaxf(c[j][2], c[j][3]));
        }
        mx0 = fmaxf(mx0, __shfl_xor_sync(0xffffffffu, mx0, 1));
        mx0 = fmaxf(mx0, __shfl_xor_sync(0xffffffffu, mx0, 2));
        mx1 = fmaxf(mx1, __shfl_xor_sync(0xffffffffu, mx1, 1));
        mx1 = fmaxf(mx1, __shfl_xor_sync(0xffffffffu, mx1, 2));
        float mn0 = fmaxf(m0, mx0), mn1 = fmaxf(m1, mx1);
        float sc0 = exp2_fast(m0 - mn0), sc1 = exp2_fast(m1 - mn1);
        m0 = mn0; m1 = mn1;

        // ---- rescale O by PREVIOUS sc (before adding PV(jb-1)) ----
        #pragma unroll
        for (int nf = 0; nf < 16; nf++) {
            o[nf][0] *= scp0; o[nf][1] *= scp0;
            o[nf][2] *= scp1; o[nf][3] *= scp1;
        }

        // ---- FUSED: PV(jb-1) [tensor] interleaved with exp2+pack [scalar] ----
        float ls0 = 0.f, ls1 = 0.f;
        uint32_t pah[4][4];
        #pragma unroll
        for (int g = 0; g < 4; g++) {
            // tensor: PV(jb-1) row-group g
            #pragma unroll
            for (int vb = 0; vb < 8; vb++) {
                uint32_t vh4[4];
                ldsm_x4_t(vh4, Vp + (g * 16 + vrow) * AT_LDB + (vb * 16 + vcol) * 2);
                #pragma unroll
                for (int half = 0; half < 2; half++) {
                    int nf = vb * 2 + half;
                    mma16816h(o[nf], pahp[g], &vh4[half * 2]);
                }
            }
            // scalar: exp2 + partial sums + pack for j = 2g, 2g+1
            #pragma unroll
            for (int jj = 0; jj < 2; jj++) {
                int j = 2 * g + jj;
                c[j][0] = exp2_fast(c[j][0] - mn0);
                c[j][1] = exp2_fast(c[j][1] - mn0);
                c[j][2] = exp2_fast(c[j][2] - mn1);
                c[j][3] = exp2_fast(c[j][3] - mn1);
                ls0 += c[j][0] + c[j][1];
                ls1 += c[j][2] + c[j][3];
            }
            #pragma unroll
            for (int q = 0; q < 4; q++) {
                int j = 2 * g + (q >> 1);
                int e = (q & 1) * 2;
                pah[g][q] = pack_f16(__float2half_rn(c[j][e]),
                                     __float2half_rn(c[j][e + 1]));
            }
        }

        // ---- finish softmax stats ----
        ls0 += __shfl_xor_sync(0xffffffffu, ls0, 1);
        ls0 += __shfl_xor_sync(0xffffffffu, ls0, 2);
        ls1 += __shfl_xor_sync(0xffffffffu, ls1, 1);
        ls1 += __shfl_xor_sync(0xffffffffu, ls1, 2);
        l0 = l0 * sc0 + ls0;
        l1 = l1 * sc1 + ls1;

        // carry P and sc to next iteration
        #pragma unroll
        for (int g = 0; g < 4; g++)
            #pragma unroll
            for (int q = 0; q < 4; q++) pahp[g][q] = pah[g][q];
        scp0 = sc0; scp1 = sc1;

        __syncthreads();                     // everyone done with V(jb-1) buffer
        if (jb + 2 <= iq) {                  // load KV(jb+2) into buffer prv
            const int kn = (jb + 2) * 64;
            const uint32_t buf = sb + (2 * prv) * AT_TILE;
            #pragma unroll
            for (int i = 0; i < 8; i++) {
                int idx  = t + 128 * i;
                int row  = idx >> 4;
                int chnk = idx & 15;
                size_t g = (size_t)(b * S + kn + row) * D + h * DH + chnk * 8;
                uint32_t so = row * AT_LDB + chnk * 16;
                cp_async16(buf + so, g_k16 + g);
                cp_async16(buf + AT_TILE + so, g_v16 + g);
            }
            CP_COMMIT();
        }
        cur = (cur + 1 >= 3) ? 0 : cur + 1;
    }

    // ---- epilogue: final rescale + PV(iq), then normalize and store ----
    {
        const int curv = iq % 3;
        const uint32_t Vl = sb + (2 * curv + 1) * AT_TILE;
        #pragma unroll
        for (int nf = 0; nf < 16; nf++) {
            o[nf][0] *= scp0; o[nf][1] *= scp0;
            o[nf][2] *= scp1; o[nf][3] *= scp1;
        }
        #pragma unroll
        for (int g = 0; g < 4; g++) {
            #pragma unroll
            for (int vb = 0; vb < 8; vb++) {
                uint32_t vh4[4];
                ldsm_x4_t(vh4, Vl + (g * 16 + vrow) * AT_LDB + (vb * 16 + vcol) * 2);
                #pragma unroll
                for (int half = 0; half < 2; half++) {
                    int nf = vb * 2 + half;
                    mma16816h(o[nf], pahp[g], &vh4[half * 2]);
                }
            }
        }
    }

    const float inv0 = 1.f / l0, inv1 = 1.f / l1;
    const int colb = h * DH + (lane & 3) * 2;
    #pragma unroll
    for (int nf = 0; nf < 16; nf++) {
        int col = colb + nf * 8;
        size_t g0 = (size_t)(b * S + r0g) * D + col;
        size_t g1 = (size_t)(b * S + r1g) * D + col;
        *(uint32_t*)(g_c16 + g0) =
            pack_f16(__float2half_rn(o[nf][0] * inv0), __float2half_rn(o[nf][1] * inv0));
        *(uint32_t*)(g_c16 + g1) =
            pack_f16(__float2half_rn(o[nf][2] * inv1), __float2half_rn(o[nf][3] * inv1));
    }
}

// ---------------------------------------------------------------------------
extern "C" void kernel_launch(void* const* d_in, const int* in_sizes, int n_in,
                              void* d_out, int out_size)
{
    const float* X  = (const float*)d_in[0];
    const float* Wq = (const float*)d_in[1];
    const float* bq = (const float*)d_in[2];
    const float* Wk = (const float*)d_in[3];
    const float* bk = (const float*)d_in[4];
    const float* Wv = (const float*)d_in[5];
    const float* bv = (const float*)d_in[6];
    const float* Wo = (const float*)d_in[7];
    const float* bo = (const float*)d_in[8];
    float* out = (float*)d_out;

    cudaFuncSetAttribute(attn_tc_kernel, cudaFuncAttributeMaxDynamicSharedMemorySize, ATTN_SMEM);
    cudaFuncSetAttribute(qkv_tc_gemm, cudaFuncAttributeMaxDynamicSharedMemorySize, GEMM_SMEM2);
    cudaFuncSetAttribute(out_tc_gemm, cudaFuncAttributeMaxDynamicSharedMemorySize, GEMM_SMEM2);

    conv_x_kernel<<<(M * D / 4) / 256, 256>>>((const float4*)X);
    wsplit_kernel<<<dim3(D / 32, D / 32, 4), 256>>>(Wq, Wk, Wv, Wo);
    qkv_tc_gemm<<<dim3(D / 128, M / 128, 3), 128, GEMM_SMEM2>>>(bq, bk, bv);
    attn_tc_kernel<<<dim3(S / 64, B * H), 128, ATTN_SMEM>>>();
    out_tc_gemm<<<dim3(D / 128, M / 128), 128, GEMM_SMEM2>>>(bo, out);
}

// round 14
// speedup vs baseline: 10.1895x; 1.0283x over previous
#include <cuda_runtime.h>
#include <cuda_bf16.h>
#include <cuda_fp16.h>
#include <math.h>
#include <cstdint>

// Problem constants
constexpr int B  = 4;
constexpr int S  = 2048;
constexpr int D  = 2048;
constexpr int H  = 16;
constexpr int DH = 128;
constexpr int M  = B * S;          // 8192 rows

// ---------------------------------------------------------------------------
// Scratch (allocation-free rule: device globals). fp16 everywhere.
// ---------------------------------------------------------------------------
__device__ __half g_x16[(size_t)M * D];
__device__ __half g_q16[(size_t)M * D];
__device__ __half g_k16[(size_t)M * D];
__device__ __half g_v16[(size_t)M * D];
__device__ __half g_c16[(size_t)M * D];
__device__ __half g_wT16[(size_t)4 * D * D];   // [w][N][K] single fp16

// ---------------------------------------------------------------------------
// PTX helpers (sm_103 baseline: mma.sync + ldmatrix + cp.async only)
// ---------------------------------------------------------------------------
__device__ __forceinline__ uint32_t smem_u32(const void* p) {
    uint32_t a;
    asm("{ .reg .u64 t; cvta.to.shared.u64 t, %1; cvt.u32.u64 %0, t; }" : "=r"(a) : "l"(p));
    return a;
}

__device__ __forceinline__ void cp_async16(uint32_t dst, const void* src) {
    asm volatile("cp.async.cg.shared.global [%0], [%1], 16;" :: "r"(dst), "l"(src));
}
#define CP_COMMIT() asm volatile("cp.async.commit_group;" ::: "memory")
#define CP_WAIT0()  asm volatile("cp.async.wait_group 0;" ::: "memory")
#define CP_WAIT1()  asm volatile("cp.async.wait_group 1;" ::: "memory")

__device__ __forceinline__ void ldsm_x4(uint32_t* r, uint32_t addr) {
    asm volatile("ldmatrix.sync.aligned.m8n8.x4.shared.b16 {%0,%1,%2,%3}, [%4];"
        : "=r"(r[0]), "=r"(r[1]), "=r"(r[2]), "=r"(r[3]) : "r"(addr));
}
__device__ __forceinline__ void ldsm_x4_t(uint32_t* r, uint32_t addr) {
    asm volatile("ldmatrix.sync.aligned.m8n8.x4.trans.shared.b16 {%0,%1,%2,%3}, [%4];"
        : "=r"(r[0]), "=r"(r[1]), "=r"(r[2]), "=r"(r[3]) : "r"(addr));
}

__device__ __forceinline__ void mma16816h(float* c, const uint32_t* a, const uint32_t* b) {
    asm volatile("mma.sync.aligned.m16n8k16.row.col.f32.f16.f16.f32 "
        "{%0,%1,%2,%3}, {%4,%5,%6,%7}, {%8,%9}, {%0,%1,%2,%3};"
        : "+f"(c[0]), "+f"(c[1]), "+f"(c[2]), "+f"(c[3])
        : "r"(a[0]), "r"(a[1]), "r"(a[2]), "r"(a[3]), "r"(b[0]), "r"(b[1]));
}

__device__ __forceinline__ uint32_t pack_f16(__half lo, __half hi) {
    __half2 h2 = __halves2half2(lo, hi);
    return *(uint32_t*)&h2;
}

// 2^z on the MUFU pipe (1 instruction; flushes large-negative to 0).
__device__ __forceinline__ float exp2_mufu(float z) {
    float r;
    asm("ex2.approx.f32 %0, %1;" : "=f"(r) : "f"(z));
    return r;
}

// ---------------------------------------------------------------------------
// Conversion kernels
// ---------------------------------------------------------------------------
__global__ __launch_bounds__(256) void conv_x_kernel(const float4* __restrict__ in) {
    size_t i = (size_t)blockIdx.x * blockDim.x + threadIdx.x;
    float4 v = in[i];
    __half h[4] = {__float2half_rn(v.x), __float2half_rn(v.y),
                   __float2half_rn(v.z), __float2half_rn(v.w)};
    *(uint2*)(g_x16 + i * 4) = *(const uint2*)h;
}

// Weights: W [K][N] fp32 -> transposed single fp16 [N][K]
__global__ __launch_bounds__(256) void wsplit_kernel(const float* __restrict__ Wq,
                                                     const float* __restrict__ Wk,
                                                     const float* __restrict__ Wv,
                                                     const float* __restrict__ Wo) {
    __shared__ float tile[32][33];
    int z = blockIdx.z;
    const float* W = (z == 0) ? Wq : (z == 1) ? Wk : (z == 2) ? Wv : Wo;
    __half* oh = g_wT16 + (size_t)z * D * D;
    int n0 = blockIdx.x * 32, k0 = blockIdx.y * 32;
    int tx = threadIdx.x & 31, ty = threadIdx.x >> 5;
    #pragma unroll
    for (int i = 0; i < 4; i++) {
        int k = ty + i * 8;
        tile[k][tx] = W[(size_t)(k0 + k) * D + n0 + tx];
    }
    __syncthreads();
    #pragma unroll
    for (int i = 0; i < 4; i++) {
        int n = ty + i * 8;
        oh[(size_t)(n0 + n) * D + k0 + tx] = __float2half_rn(tile[tx][n]);
    }
}

// ---------------------------------------------------------------------------
// mma.sync fp16 1-pass GEMM: C[128x128] = A @ B^T + bias
// 4 warps (2x2), warp tile 64x64, BK=32, 3-stage cp.async, ONE sync/iter.
// MODE: 0 = fp32 out, 2 = fp16 out
// ---------------------------------------------------------------------------
constexpr int BKG      = 32;
constexpr int LDT      = 40;                 // f16 stride per tile row (80 B)
constexpr int TILE_BY  = 128 * LDT * 2;      // 10240 B per tile
constexpr int NITER    = D / BKG;            // 64
constexpr int GEMM_SMEM2 = 3 * 2 * TILE_BY;  // 61440 B

__device__ __forceinline__ void load_stage(uint32_t sbase,
                                           const __half* A,
                                           const __half* Bm,
                                           int k0, int t) {
    const __half* bases[2] = {A, Bm};
    #pragma unroll
    for (int i = 0; i < 8; i++) {
        const int tile = i >> 2;              // 4 slots per tile per thread
        int idx  = t + 128 * (i & 3);         // 0..511
        int row  = idx >> 2;                  // 0..127
        int chnk = idx & 3;                   // 16B chunk
        const __half* src = bases[tile] + (size_t)row * D + k0 + chnk * 8;
        uint32_t dst = sbase + tile * TILE_BY + row * (LDT * 2) + chnk * 16;
        cp_async16(dst, src);
    }
    CP_COMMIT();
}

template <int MODE>
__device__ __forceinline__ void tc_gemm_body(const __half* __restrict__ Ap,
                                             const __half* __restrict__ Bp,
                                             const float* __restrict__ bias,
                                             float* __restrict__ C,
                                             __half* __restrict__ F) {
    constexpr int STAGE = 2 * TILE_BY;
    extern __shared__ char smem[];
    const uint32_t sb = smem_u32(smem);
    const int t    = threadIdx.x;
    const int lane = t & 31;
    const int w    = t >> 5;
    const int wm   = (w & 1) * 64;
    const int wn   = (w >> 1) * 64;
    const int m0   = blockIdx.y * 128;
    const int n0   = blockIdx.x * 128;

    const __half* Arow = Ap + (size_t)m0 * D;
    const __half* Brow = Bp + (size_t)n0 * D;

    float acc[4][8][4];
    #pragma unroll
    for (int i = 0; i < 4; i++)
        #pragma unroll
        for (int j = 0; j < 8; j++)
            #pragma unroll
            for (int r = 0; r < 4; r++) acc[i][j][r] = 0.f;

    const int arow  = lane & 15;
    const int akoff = (lane >> 4) * 16;
    const int bn    = (lane & 7) + ((lane >> 4) << 3);
    const int bkoff = ((lane >> 3) & 1) * 16;

    load_stage(sb + 0 * STAGE, Arow, Brow, 0, t);
    load_stage(sb + 1 * STAGE, Arow, Brow, BKG, t);

    int bufc = 0;
    for (int c = 0; c < NITER; c++) {
        if (c + 1 < NITER) { CP_WAIT1(); } else { CP_WAIT0(); }
        __syncthreads();                       // stage c visible; buf (c+2)%3 free

        const uint32_t sbase = sb + bufc * STAGE;
        #pragma unroll
        for (int kk = 0; kk < 2; kk++) {
            const uint32_t kbyte = kk * 32;
            uint32_t ah[4][4];
            #pragma unroll
            for (int mf = 0; mf < 4; mf++) {
                uint32_t ad = sbase + (wm + mf * 16 + arow) * (LDT * 2) + kbyte + akoff;
                ldsm_x4(ah[mf], ad);
            }
            #pragma unroll
            for (int nb = 0; nb < 4; nb++) {
                uint32_t bh4[4];
                uint32_t bd = sbase + TILE_BY + (wn + nb * 16 + bn) * (LDT * 2) + kbyte + bkoff;
                ldsm_x4(bh4, bd);
                #pragma unroll
                for (int mf = 0; mf < 4; mf++)
                    #pragma unroll
                    for (int half = 0; half < 2; half++) {
                        int nf = nb * 2 + half;
                        mma16816h(acc[mf][nf], ah[mf], &bh4[half * 2]);
                    }
            }
        }
        // Issue next-next stage AFTER compute; its buffer was last read at
        // iter c-1 and all warps passed this iter's barrier -> no hazard.
        if (c + 2 < NITER) {
            int bufn = bufc + 2; if (bufn >= 3) bufn -= 3;
            load_stage(sb + bufn * STAGE, Arow, Brow, (c + 2) * BKG, t);
        }
        if (++bufc == 3) bufc = 0;
    }

    // Epilogue
    const int rbase = m0 + wm + (lane >> 2);
    const int cbase = n0 + wn + (lane & 3) * 2;
    #pragma unroll
    for (int mf = 0; mf < 4; mf++) {
        #pragma unroll
        for (int nf = 0; nf < 8; nf++) {
            int col = cbase + nf * 8;
            float2 bv = *(const float2*)(bias + col);
            int r0 = rbase + mf * 16;
            float v0 = acc[mf][nf][0] + bv.x, v1 = acc[mf][nf][1] + bv.y;
            float v2 = acc[mf][nf][2] + bv.x, v3 = acc[mf][nf][3] + bv.y;
            if (MODE == 0) {
                float2 o0 = {v0, v1}, o1 = {v2, v3};
                *(float2*)(C + (size_t)r0 * D + col)       = o0;
                *(float2*)(C + (size_t)(r0 + 8) * D + col) = o1;
            } else {
                *(uint32_t*)(F + (size_t)r0 * D + col) =
                    pack_f16(__float2half_rn(v0), __float2half_rn(v1));
                *(uint32_t*)(F + (size_t)(r0 + 8) * D + col) =
                    pack_f16(__float2half_rn(v2), __float2half_rn(v3));
            }
        }
    }
}

// Q/K/V projections: 1-pass fp16
__global__ __launch_bounds__(128, 2) void qkv_tc_gemm(const float* __restrict__ bq,
                                                      const float* __restrict__ bk,
                                                      const float* __restrict__ bv) {
    const int z = blockIdx.z;
    const __half* W = g_wT16 + (size_t)z * D * D;
    const float* bias = (z == 0) ? bq : (z == 1) ? bk : bv;
    __half* Out = (z == 0) ? g_q16 : (z == 1) ? g_k16 : g_v16;
    tc_gemm_body<2>(g_x16, W, bias, nullptr, Out);
}

// Output projection: 1-pass, fp32 out
__global__ __launch_bounds__(128, 2) void out_tc_gemm(const float* __restrict__ bo,
                                                      float* __restrict__ out) {
    tc_gemm_body<0>(g_c16, g_wT16 + (size_t)3 * D * D, bo, out, nullptr);
}

// ---------------------------------------------------------------------------
// Tensor-core flash attention (fp16, causal). Br=Bc=64, 128 threads.
// Software-pipelined: PV(jb-1) fused/interleaved with softmax(jb); exp2 on
// the MUFU pipe (idle otherwise) to free FMA issue slots. 3 K/V smem buffers.
// ---------------------------------------------------------------------------
constexpr int AT_LDB   = 272;                    // bytes per tile row (128 f16 + pad)
constexpr int AT_TILE  = 64 * AT_LDB;            // 17408 B
constexpr int ATTN_SMEM = 6 * AT_TILE;           // 3 KV buffers (Q reuses tile 0)
constexpr float SCALE_LOG2E = 0.12751650f;       // (1/sqrt(128)) * log2(e)

__global__ __launch_bounds__(128, 2) void attn_tc_kernel() {
    extern __shared__ char sm8[];
    const uint32_t sb = smem_u32(sm8);

    const int t    = threadIdx.x;
    const int lane = t & 31;
    const int w    = t >> 5;
    const int iq   = (gridDim.x - 1) - blockIdx.x;      // big blocks first
    const int bh   = blockIdx.y;
    const int b    = bh >> 4;
    const int h    = bh & 15;
    const int q0   = iq * 64;
    const int wq   = w * 16;

    // ldmatrix lane offsets
    const int arow  = lane & 15;
    const int akoff = (lane >> 4) * 16;
    const int bn    = (lane & 7) + ((lane >> 4) << 3);
    const int bkoff = ((lane >> 3) & 1) * 16;
    const int vrow  = lane & 15;
    const int vcol  = (lane >> 4) << 3;

    // ---- Load Q into tile 0, hoist to registers ----
    {
        #pragma unroll
        for (int i = 0; i < 8; i++) {
            int idx  = t + 128 * i;
            int row  = idx >> 4;
            int chnk = idx & 15;
            size_t g = (size_t)(b * S + q0 + row) * D + h * DH + chnk * 8;
            cp_async16(sb + row * AT_LDB + chnk * 16, g_q16 + g);
        }
        CP_COMMIT();
        CP_WAIT0();
        __syncthreads();
    }
    uint32_t qhr[8][4];
    #pragma unroll
    for (int kt = 0; kt < 8; kt++) {
        ldsm_x4(qhr[kt], sb + (wq + arow) * AT_LDB + kt * 32 + akoff);
    }
    // Zero V tile of buffer 2 (tile 5): first-iteration dummy PV reads it.
    for (uint32_t i = (uint32_t)t * 16; i < (uint32_t)AT_TILE; i += 128 * 16) {
        *(uint4*)(sm8 + 5 * AT_TILE + i) = make_uint4(0, 0, 0, 0);
    }
    __syncthreads();   // Q reads + zeroing done before KV(0) overwrites tile 0

    // ---- Issue KV(0) -> buf0, KV(1) -> buf1 ----
    #pragma unroll
    for (int i = 0; i < 8; i++) {
        int idx  = t + 128 * i;
        int row  = idx >> 4;
        int chnk = idx & 15;
        size_t g = (size_t)(b * S + row) * D + h * DH + chnk * 8;
        uint32_t so = row * AT_LDB + chnk * 16;
        cp_async16(sb + so, g_k16 + g);
        cp_async16(sb + AT_TILE + so, g_v16 + g);
    }
    CP_COMMIT();
    if (iq >= 1) {
        #pragma unroll
        for (int i = 0; i < 8; i++) {
            int idx  = t + 128 * i;
            int row  = idx >> 4;
            int chnk = idx & 15;
            size_t g = (size_t)(b * S + 64 + row) * D + h * DH + chnk * 8;
            uint32_t so = row * AT_LDB + chnk * 16;
            cp_async16(sb + 2 * AT_TILE + so, g_k16 + g);
            cp_async16(sb + 3 * AT_TILE + so, g_v16 + g);
        }
        CP_COMMIT();
    }

    float o[16][4];
    #pragma unroll
    for (int i = 0; i < 16; i++)
        #pragma unroll
        for (int r = 0; r < 4; r++) o[i][r] = 0.f;
    float m0 = -1e30f, m1 = -1e30f, l0 = 0.f, l1 = 0.f;
    uint32_t pahp[4][4];
    #pragma unroll
    for (int g = 0; g < 4; g++)
        #pragma unroll
        for (int q = 0; q < 4; q++) pahp[g][q] = 0u;   // P(-1) = 0
    float scp0 = 1.f, scp1 = 1.f;

    const int r0g = q0 + wq + (lane >> 2);
    const int r1g = r0g + 8;

    int cur = 0;
    for (int jb = 0; jb <= iq; jb++) {
        const int prv = (cur + 2 >= 3) ? cur - 1 : cur + 2;   // (jb-1)%3 == (jb+2)%3
        if (jb < iq) { CP_WAIT1(); } else { CP_WAIT0(); }
        __syncthreads();                     // KV(jb) visible to all warps

        const uint32_t Kb = sb + (2 * cur) * AT_TILE;
        const uint32_t Vp = sb + (2 * prv + 1) * AT_TILE;     // V(jb-1)
        const int k0 = jb * 64;

        // ---- S = Q K^T (single pass, fp16) ----
        float c[8][4];
        #pragma unroll
        for (int j = 0; j < 8; j++)
            #pragma unroll
            for (int r = 0; r < 4; r++) c[j][r] = 0.f;

        #pragma unroll
        for (int kt = 0; kt < 8; kt++) {
            #pragma unroll
            for (int nb = 0; nb < 4; nb++) {
                uint32_t kh4[4];
                ldsm_x4(kh4, Kb + (nb * 16 + bn) * AT_LDB + kt * 32 + bkoff);
                #pragma unroll
                for (int half = 0; half < 2; half++) {
                    int nf = nb * 2 + half;
                    mma16816h(c[nf], qhr[kt], &kh4[half * 2]);
                }
            }
        }

        // ---- scale (+ causal mask only on the diagonal block) ----
        if (jb == iq) {
            #pragma unroll
            for (int j = 0; j < 8; j++) {
                int cc = k0 + j * 8 + (lane & 3) * 2;
                #pragma unroll
                for (int r = 0; r < 4; r++) {
                    float v = c[j][r] * SCALE_LOG2E;
                    int col = cc + (r & 1);
                    int row = (r < 2) ? r0g : r1g;
                    if (col > row) v = -1e30f;
                    c[j][r] = v;
                }
            }
        } else {
            #pragma unroll
            for (int j = 0; j < 8; j++)
                #pragma unroll
                for (int r = 0; r < 4; r++)
                    c[j][r] *= SCALE_LOG2E;
        }

        // ---- row max + running max ----
        float mx0 = -1e30f, mx1 = -1e30f;
        #pragma unroll
        for (int j = 0; j < 8; j++) {
            mx0 = fmaxf(mx0, fmaxf(c[j][0], c[j][1]));
            mx1 = fmaxf(mx1, fmaxf(c[j][2], c[j][3]));
        }
        mx0 = fmaxf(mx0, __shfl_xor_sync(0xffffffffu, mx0, 1));
        mx0 = fmaxf(mx0, __shfl_xor_sync(0xffffffffu, mx0, 2));
        mx1 = fmaxf(mx1, __shfl_xor_sync(0xffffffffu, mx1, 1));
        mx1 = fmaxf(mx1, __shfl_xor_sync(0xffffffffu, mx1, 2));
        float mn0 = fmaxf(m0, mx0), mn1 = fmaxf(m1, mx1);
        float sc0 = exp2_mufu(m0 - mn0), sc1 = exp2_mufu(m1 - mn1);
        m0 = mn0; m1 = mn1;

        // ---- rescale O by PREVIOUS sc (before adding PV(jb-1)) ----
        #pragma unroll
        for (int nf = 0; nf < 16; nf++) {
            o[nf][0] *= scp0; o[nf][1] *= scp0;
            o[nf][2] *= scp1; o[nf][3] *= scp1;
        }

        // ---- FUSED: PV(jb-1) [tensor] interleaved with exp2 [MUFU] ----
        float ls0 = 0.f, ls1 = 0.f;
        uint32_t pah[4][4];
        #pragma unroll
        for (int g = 0; g < 4; g++) {
            // tensor: PV(jb-1) row-group g
            #pragma unroll
            for (int vb = 0; vb < 8; vb++) {
                uint32_t vh4[4];
                ldsm_x4_t(vh4, Vp + (g * 16 + vrow) * AT_LDB + (vb * 16 + vcol) * 2);
                #pragma unroll
                for (int half = 0; half < 2; half++) {
                    int nf = vb * 2 + half;
                    mma16816h(o[nf], pahp[g], &vh4[half * 2]);
                }
            }
            // scalar/MUFU: exp2 + partial sums + pack for j = 2g, 2g+1
            #pragma unroll
            for (int jj = 0; jj < 2; jj++) {
                int j = 2 * g + jj;
                c[j][0] = exp2_mufu(c[j][0] - mn0);
                c[j][1] = exp2_mufu(c[j][1] - mn0);
                c[j][2] = exp2_mufu(c[j][2] - mn1);
                c[j][3] = exp2_mufu(c[j][3] - mn1);
                ls0 += c[j][0] + c[j][1];
                ls1 += c[j][2] + c[j][3];
            }
            #pragma unroll
            for (int q = 0; q < 4; q++) {
                int j = 2 * g + (q >> 1);
                int e = (q & 1) * 2;
                pah[g][q] = pack_f16(__float2half_rn(c[j][e]),
                                     __float2half_rn(c[j][e + 1]));
            }
        }

        // ---- finish softmax stats ----
        ls0 += __shfl_xor_sync(0xffffffffu, ls0, 1);
        ls0 += __shfl_xor_sync(0xffffffffu, ls0, 2);
        ls1 += __shfl_xor_sync(0xffffffffu, ls1, 1);
        ls1 += __shfl_xor_sync(0xffffffffu, ls1, 2);
        l0 = l0 * sc0 + ls0;
        l1 = l1 * sc1 + ls1;

        // carry P and sc to next iteration
        #pragma unroll
        for (int g = 0; g < 4; g++)
            #pragma unroll
            for (int q = 0; q < 4; q++) pahp[g][q] = pah[g][q];
        scp0 = sc0; scp1 = sc1;

        __syncthreads();                     // everyone done with V(jb-1) buffer
        if (jb + 2 <= iq) {                  // load KV(jb+2) into buffer prv
            const int kn = (jb + 2) * 64;
            const uint32_t buf = sb + (2 * prv) * AT_TILE;
            #pragma unroll
            for (int i = 0; i < 8; i++) {
                int idx  = t + 128 * i;
                int row  = idx >> 4;
                int chnk = idx & 15;
                size_t g = (size_t)(b * S + kn + row) * D + h * DH + chnk * 8;
                uint32_t so = row * AT_LDB + chnk * 16;
                cp_async16(buf + so, g_k16 + g);
                cp_async16(buf + AT_TILE + so, g_v16 + g);
            }
            CP_COMMIT();
        }
        cur = (cur + 1 >= 3) ? 0 : cur + 1;
    }

    // ---- epilogue: final rescale + PV(iq), then normalize and store ----
    {
        const int curv = iq % 3;
        const uint32_t Vl = sb + (2 * curv + 1) * AT_TILE;
        #pragma unroll
        for (int nf = 0; nf < 16; nf++) {
            o[nf][0] *= scp0; o[nf][1] *= scp0;
            o[nf][2] *= scp1; o[nf][3] *= scp1;
        }
        #pragma unroll
        for (int g = 0; g < 4; g++) {
            #pragma unroll
            for (int vb = 0; vb < 8; vb++) {
                uint32_t vh4[4];
                ldsm_x4_t(vh4, Vl + (g * 16 + vrow) * AT_LDB + (vb * 16 + vcol) * 2);
                #pragma unroll
                for (int half = 0; half < 2; half++) {
                    int nf = vb * 2 + half;
                    mma16816h(o[nf], pahp[g], &vh4[half * 2]);
                }
            }
        }
    }

    const float inv0 = 1.f / l0, inv1 = 1.f / l1;
    const int colb = h * DH + (lane & 3) * 2;
    #pragma unroll
    for (int nf = 0; nf < 16; nf++) {
        int col = colb + nf * 8;
        size_t g0 = (size_t)(b * S + r0g) * D + col;
        size_t g1 = (size_t)(b * S + r1g) * D + col;
        *(uint32_t*)(g_c16 + g0) =
            pack_f16(__float2half_rn(o[nf][0] * inv0), __float2half_rn(o[nf][1] * inv0));
        *(uint32_t*)(g_c16 + g1) =
            pack_f16(__float2half_rn(o[nf][2] * inv1), __float2half_rn(o[nf][3] * inv1));
    }
}

// ---------------------------------------------------------------------------
extern "C" void kernel_launch(void* const* d_in, const int* in_sizes, int n_in,
                              void* d_out, int out_size)
{
    const float* X  = (const float*)d_in[0];
    const float* Wq = (const float*)d_in[1];
    const float* bq = (const float*)d_in[2];
    const float* Wk = (const float*)d_in[3];
    const float* bk = (const float*)d_in[4];
    const float* Wv = (const float*)d_in[5];
    const float* bv = (const float*)d_in[6];
    const float* Wo = (const float*)d_in[7];
    const float* bo = (const float*)d_in[8];
    float* out = (float*)d_out;

    cudaFuncSetAttribute(attn_tc_kernel, cudaFuncAttributeMaxDynamicSharedMemorySize, ATTN_SMEM);
    cudaFuncSetAttribute(qkv_tc_gemm, cudaFuncAttributeMaxDynamicSharedMemorySize, GEMM_SMEM2);
    cudaFuncSetAttribute(out_tc_gemm, cudaFuncAttributeMaxDynamicSharedMemorySize, GEMM_SMEM2);

    conv_x_kernel<<<(M * D / 4) / 256, 256>>>((const float4*)X);
    wsplit_kernel<<<dim3(D / 32, D / 32, 4), 256>>>(Wq, Wk, Wv, Wo);
    qkv_tc_gemm<<<dim3(D / 128, M / 128, 3), 128, GEMM_SMEM2>>>(bq, bk, bv);
    attn_tc_kernel<<<dim3(S / 64, B * H), 128, ATTN_SMEM>>>();
    out_tc_gemm<<<dim3(D / 128, M / 128), 128, GEMM_SMEM2>>>(bo, out);
}